// round 1
// baseline (speedup 1.0000x reference)
#include <cuda_runtime.h>
#include <cuda_bf16.h>
#include <math.h>

// Problem constants
#define Bsz 4
#define Ssz 2048
#define Hsz 1024
#define Nh  16
#define Dh  64
#define Msz (Bsz*Ssz)      // 8192
#define EPSF 1e-6f

// ---------------- scratch (static device globals; no allocs allowed) -------
__device__ float g_q[Msz*Hsz];        // 32 MB
__device__ float g_k[Msz*Hsz];
__device__ float g_v[Msz*Hsz];
__device__ float g_comb[Msz*Hsz];
__device__ float g_kv_part[8*64*64*64];   // [chunk][b*n][k][v]
__device__ float g_kv[64*64*64];          // [b*n][k][v]
__device__ float g_ksum_part[8*64*64];
__device__ float g_ksum[64*64];
__device__ float g_gate[Msz];

// ---------------- SGEMM: C[M,N] = A[M,K] @ W[K,N] + bias ------------------
// 128x128 block tile, BK=16, 256 threads, 8x8 per-thread microtile,
// double-buffered smem with register-staged global prefetch.
__global__ __launch_bounds__(256, 2)
void sgemm128(const float* __restrict__ A, const float* __restrict__ W,
              const float* __restrict__ bias, float* __restrict__ C,
              int M, int N, int K)
{
    __shared__ float As[2][16][132];   // padded to kill STS bank conflicts
    __shared__ float Bs[2][16][128];

    const int tid = threadIdx.x;
    const int bx = blockIdx.x, by = blockIdx.y;

    const int ar = tid >> 2;           // 0..63  (A row within tile, +64 twin)
    const int ac = (tid & 3) << 2;     // 0,4,8,12 (A col group)
    const int br = tid >> 5;           // 0..7   (B row, +8 twin)
    const int bc = (tid & 31) << 2;    // 0..124 (B col group)
    const int tr = tid >> 4;           // 0..15
    const int tc = tid & 15;           // 0..15

    const float* Ap = A + (long)(by * 128 + ar) * K + ac;
    const float* Wp = W + (long)br * N + bx * 128 + bc;

    float acc[8][8];
#pragma unroll
    for (int i = 0; i < 8; i++)
#pragma unroll
        for (int j = 0; j < 8; j++) acc[i][j] = 0.f;

    // preload tile 0
    {
        float4 a0 = *(const float4*)Ap;
        float4 a1 = *(const float4*)(Ap + (long)64 * K);
        float4 b0 = *(const float4*)Wp;
        float4 b1 = *(const float4*)(Wp + (long)8 * N);
        As[0][ac+0][ar]    = a0.x; As[0][ac+1][ar]    = a0.y;
        As[0][ac+2][ar]    = a0.z; As[0][ac+3][ar]    = a0.w;
        As[0][ac+0][ar+64] = a1.x; As[0][ac+1][ar+64] = a1.y;
        As[0][ac+2][ar+64] = a1.z; As[0][ac+3][ar+64] = a1.w;
        *(float4*)&Bs[0][br][bc]     = b0;
        *(float4*)&Bs[0][br + 8][bc] = b1;
    }
    __syncthreads();

    const int nt = K >> 4;
    for (int t = 0; t < nt; ++t) {
        const int cur = t & 1;
        float4 a0, a1, b0, b1;
        const bool pf = (t + 1 < nt);
        if (pf) {
            const float* Ap2 = Ap + (t + 1) * 16;
            const float* Wp2 = Wp + (long)(t + 1) * 16 * N;
            a0 = *(const float4*)Ap2;
            a1 = *(const float4*)(Ap2 + (long)64 * K);
            b0 = *(const float4*)Wp2;
            b1 = *(const float4*)(Wp2 + (long)8 * N);
        }
#pragma unroll
        for (int kk = 0; kk < 16; ++kk) {
            float4 av0 = *(const float4*)&As[cur][kk][tr * 4];
            float4 av1 = *(const float4*)&As[cur][kk][tr * 4 + 64];
            float4 bv0 = *(const float4*)&Bs[cur][kk][tc * 4];
            float4 bv1 = *(const float4*)&Bs[cur][kk][tc * 4 + 64];
            float a[8] = {av0.x, av0.y, av0.z, av0.w, av1.x, av1.y, av1.z, av1.w};
            float b[8] = {bv0.x, bv0.y, bv0.z, bv0.w, bv1.x, bv1.y, bv1.z, bv1.w};
#pragma unroll
            for (int i = 0; i < 8; i++)
#pragma unroll
                for (int j = 0; j < 8; j++)
                    acc[i][j] += a[i] * b[j];
        }
        if (pf) {
            const int nxt = cur ^ 1;
            As[nxt][ac+0][ar]    = a0.x; As[nxt][ac+1][ar]    = a0.y;
            As[nxt][ac+2][ar]    = a0.z; As[nxt][ac+3][ar]    = a0.w;
            As[nxt][ac+0][ar+64] = a1.x; As[nxt][ac+1][ar+64] = a1.y;
            As[nxt][ac+2][ar+64] = a1.z; As[nxt][ac+3][ar+64] = a1.w;
            *(float4*)&Bs[nxt][br][bc]     = b0;
            *(float4*)&Bs[nxt][br + 8][bc] = b1;
        }
        __syncthreads();
    }

    // epilogue with bias
    const float* bp = bias + bx * 128;
    float4 bias0 = *(const float4*)&bp[tc * 4];
    float4 bias1 = *(const float4*)&bp[tc * 4 + 64];
    float bb[8] = {bias0.x, bias0.y, bias0.z, bias0.w,
                   bias1.x, bias1.y, bias1.z, bias1.w};
#pragma unroll
    for (int i = 0; i < 8; i++) {
        int r = by * 128 + tr * 4 + (i & 3) + ((i >> 2) << 6);
        float* cp = C + (long)r * N + bx * 128 + tc * 4;
        float4 v0 = make_float4(acc[i][0] + bb[0], acc[i][1] + bb[1],
                                acc[i][2] + bb[2], acc[i][3] + bb[3]);
        float4 v1 = make_float4(acc[i][4] + bb[4], acc[i][5] + bb[5],
                                acc[i][6] + bb[6], acc[i][7] + bb[7]);
        *(float4*)cp        = v0;
        *(float4*)(cp + 64) = v1;
    }
}

// ---------------- gate: g[row] = sigmoid(x[row,:] . Wg + bg) ---------------
__global__ void gate_kernel(const float* __restrict__ X,
                            const float* __restrict__ Wg,
                            const float* __restrict__ bg,
                            float* __restrict__ gout)
{
    const int row = blockIdx.x;
    const float* xr = X + (long)row * Hsz;
    float s = 0.f;
    for (int h = threadIdx.x; h < Hsz; h += 256) s += xr[h] * Wg[h];
#pragma unroll
    for (int o = 16; o; o >>= 1) s += __shfl_down_sync(0xffffffffu, s, o);
    __shared__ float ws[8];
    if ((threadIdx.x & 31) == 0) ws[threadIdx.x >> 5] = s;
    __syncthreads();
    if (threadIdx.x == 0) {
        float t = 0.f;
#pragma unroll
        for (int i = 0; i < 8; i++) t += ws[i];
        t += bg[0];
        gout[row] = 1.f / (1.f + expf(-t));
    }
}

// ---------------- RoPE + feature map (in place on q,k) + mask (k,v) --------
__device__ __forceinline__ float phi_fn(float x) {
    float t = (x > 0.f) ? x : expm1f(x);
    return (t + 1.0f) + EPSF;           // match jax association order
}

__global__ void rope_map_kernel(const float* __restrict__ mask,
                                float* __restrict__ q,
                                float* __restrict__ k,
                                float* __restrict__ v)
{
    __shared__ float invf_s[32];
    const int tid = threadIdx.x;
    if (tid < 32) {
        double p = pow(10000.0, (double)(2 * tid) / 64.0);
        invf_s[tid] = 1.0f / (float)p;
    }
    __syncthreads();

    long idx = (long)blockIdx.x * 256 + tid;   // B*S*N*32 = 4194304 total
    const int i = (int)(idx & 31);
    long t = idx >> 5;
    const int n = (int)(t & 15); t >>= 4;
    const int s = (int)(t & 2047);
    const int b = (int)(t >> 11);

    const float m = mask[b * Ssz + s];
    const float freq = (float)s * invf_s[i];
    const float c = cosf(freq), sn = sinf(freq);

    const long base = (((long)(b * Ssz + s) * Nh) + n) * Dh + i;

    float q1 = q[base], q2 = q[base + 32];
    float rq1 = q1 * c - q2 * sn;
    float rq2 = q2 * c + q1 * sn;
    q[base]      = phi_fn(rq1) * 0.125f;       // scaling = D^-0.5
    q[base + 32] = phi_fn(rq2) * 0.125f;

    float k1 = k[base], k2 = k[base + 32];
    float rk1 = k1 * c - k2 * sn;
    float rk2 = k2 * c + k1 * sn;
    k[base]      = phi_fn(rk1) * m;
    k[base + 32] = phi_fn(rk2) * m;

    v[base]      *= m;
    v[base + 32] *= m;
}

// ---------------- kv partial: per (b,n,chunk) 64x64 outer-product sum ------
__global__ void kv_partial_kernel(const float* __restrict__ k,
                                  const float* __restrict__ v,
                                  float* __restrict__ kv_part,
                                  float* __restrict__ ksum_part)
{
    const int bn = blockIdx.x;       // 0..63
    const int c  = blockIdx.y;       // 0..7
    const int b = bn >> 4, n = bn & 15;
    __shared__ float ks[32][64];
    __shared__ float vs[32][64];
    const int tid = threadIdx.x;
    const int ti = tid >> 4, tj = tid & 15;

    float acc[4][4];
#pragma unroll
    for (int a = 0; a < 4; a++)
#pragma unroll
        for (int d = 0; d < 4; d++) acc[a][d] = 0.f;
    float ksum = 0.f;

    const int s0 = c * 256;
    for (int so = 0; so < 256; so += 32) {
#pragma unroll
        for (int e = tid; e < 512; e += 256) {
            int sl = e >> 4, dd = (e & 15) * 4;
            long gb = (((long)(b * Ssz + s0 + so + sl) * Nh) + n) * Dh + dd;
            *(float4*)&ks[sl][dd] = *(const float4*)&k[gb];
            *(float4*)&vs[sl][dd] = *(const float4*)&v[gb];
        }
        __syncthreads();
#pragma unroll 4
        for (int sl = 0; sl < 32; ++sl) {
            float4 kk4 = *(const float4*)&ks[sl][ti * 4];
            float4 vv4 = *(const float4*)&vs[sl][tj * 4];
            float ka[4] = {kk4.x, kk4.y, kk4.z, kk4.w};
            float va[4] = {vv4.x, vv4.y, vv4.z, vv4.w};
#pragma unroll
            for (int a = 0; a < 4; a++)
#pragma unroll
                for (int d = 0; d < 4; d++) acc[a][d] += ka[a] * va[d];
        }
        if (tid < 64) {
#pragma unroll 4
            for (int sl = 0; sl < 32; ++sl) ksum += ks[sl][tid];
        }
        __syncthreads();
    }

    const long pbase = ((long)c * 64 + bn) * 4096;
#pragma unroll
    for (int a = 0; a < 4; a++) {
        float4 o = make_float4(acc[a][0], acc[a][1], acc[a][2], acc[a][3]);
        *(float4*)&kv_part[pbase + (ti * 4 + a) * 64 + tj * 4] = o;
    }
    if (tid < 64) ksum_part[(c * 64 + bn) * 64 + tid] = ksum;
}

__global__ void kv_reduce_kernel(const float* __restrict__ kv_part,
                                 const float* __restrict__ ksum_part,
                                 float* __restrict__ kv,
                                 float* __restrict__ ksum)
{
    const int bn = blockIdx.x;
    const int tid = threadIdx.x;
    for (int e = tid; e < 4096; e += 256) {
        float s = 0.f;
#pragma unroll
        for (int c = 0; c < 8; ++c) s += kv_part[((long)c * 64 + bn) * 4096 + e];
        kv[(long)bn * 4096 + e] = s;
    }
    if (tid < 64) {
        float s = 0.f;
#pragma unroll
        for (int c = 0; c < 8; ++c) s += ksum_part[(c * 64 + bn) * 64 + tid];
        ksum[bn * 64 + tid] = s;
    }
}

// ---------------- combine: num = q@kv ; den = q.ksum+eps ; gate mix --------
__global__ void combine_kernel(const float* __restrict__ q,
                               const float* __restrict__ kv,
                               const float* __restrict__ ksum,
                               const float* __restrict__ gate,
                               const float* __restrict__ df,
                               const float* __restrict__ gw,
                               float* __restrict__ comb)
{
    const int bn = blockIdx.x;       // 0..63
    const int st = blockIdx.y;       // 0..31 (tiles of 64 rows)
    const int b = bn >> 4, n = bn & 15;

    __shared__ float qs[64][68];
    __shared__ float kvs[64][64];
    __shared__ float ksums[64];

    const int tid = threadIdx.x;

    // coef = sum_m softmax(gw)_m * (1 - sigmoid(df_m))  (redundant per thread)
    float w0 = gw[0], w1 = gw[1], w2 = gw[2];
    float d0 = df[0], d1 = df[1], d2 = df[2];
    float mx = fmaxf(w0, fmaxf(w1, w2));
    float e0 = expf(w0 - mx), e1 = expf(w1 - mx), e2 = expf(w2 - mx);
    float s0f = 1.f / (1.f + expf(-d0));
    float s1f = 1.f / (1.f + expf(-d1));
    float s2f = 1.f / (1.f + expf(-d2));
    float coef = (e0 * (1.f - s0f) + e1 * (1.f - s1f) + e2 * (1.f - s2f)) / (e0 + e1 + e2);

    // load kv tile + ksum
    const long kvbase = (long)bn * 4096;
    for (int e = tid; e < 1024; e += 256)
        ((float4*)kvs)[e] = ((const float4*)(kv + kvbase))[e];
    if (tid < 64) ksums[tid] = ksum[bn * 64 + tid];

    // load q tile (64 rows)
    const int srow0 = st * 64;
    for (int e = tid; e < 1024; e += 256) {
        int r = e >> 4, dd = (e & 15) * 4;
        long gq = (((long)(b * Ssz + srow0 + r) * Nh) + n) * Dh + dd;
        *(float4*)&qs[r][dd] = *(const float4*)&q[gq];
    }
    __syncthreads();

    const int sl = tid >> 2;        // 0..63
    const int jg = tid & 3;         // 0..3 -> 16 cols each
    float acc[16];
#pragma unroll
    for (int j = 0; j < 16; j++) acc[j] = 0.f;
    float den = 0.f;

#pragma unroll 4
    for (int kk = 0; kk < 64; ++kk) {
        float qv = qs[sl][kk];
        den += qv * ksums[kk];
        const float4* kr = (const float4*)&kvs[kk][jg * 16];
        float4 c0 = kr[0], c1 = kr[1], c2 = kr[2], c3 = kr[3];
        acc[0]  += qv * c0.x; acc[1]  += qv * c0.y; acc[2]  += qv * c0.z; acc[3]  += qv * c0.w;
        acc[4]  += qv * c1.x; acc[5]  += qv * c1.y; acc[6]  += qv * c1.z; acc[7]  += qv * c1.w;
        acc[8]  += qv * c2.x; acc[9]  += qv * c2.y; acc[10] += qv * c2.z; acc[11] += qv * c2.w;
        acc[12] += qv * c3.x; acc[13] += qv * c3.y; acc[14] += qv * c3.z; acc[15] += qv * c3.w;
    }
    den += EPSF;

    const int srow = srow0 + sl;
    const float g = gate[b * Ssz + srow];
    const float fac = g / den + (1.f - g) * coef;

    const long obase = (((long)(b * Ssz + srow) * Nh) + n) * Dh + jg * 16;
#pragma unroll
    for (int u = 0; u < 4; u++) {
        float4 o = make_float4(acc[u * 4 + 0] * fac, acc[u * 4 + 1] * fac,
                               acc[u * 4 + 2] * fac, acc[u * 4 + 3] * fac);
        *(float4*)&comb[obase + u * 4] = o;
    }
}

// ---------------------------------------------------------------------------
extern "C" void kernel_launch(void* const* d_in, const int* in_sizes, int n_in,
                              void* d_out, int out_size)
{
    const float* x    = (const float*)d_in[0];
    const float* mask = (const float*)d_in[1];
    const float* Wq   = (const float*)d_in[2];
    const float* bq   = (const float*)d_in[3];
    const float* Wk   = (const float*)d_in[4];
    const float* bk   = (const float*)d_in[5];
    const float* Wv   = (const float*)d_in[6];
    const float* bv   = (const float*)d_in[7];
    const float* Wo   = (const float*)d_in[8];
    const float* bo   = (const float*)d_in[9];
    const float* Wg   = (const float*)d_in[10];
    const float* bg   = (const float*)d_in[11];
    const float* df   = (const float*)d_in[12];
    const float* gw   = (const float*)d_in[13];
    float* out = (float*)d_out;

    float *q, *k, *v, *comb, *kvp, *kv, *ksp, *ks, *gate;
    cudaGetSymbolAddress((void**)&q,    g_q);
    cudaGetSymbolAddress((void**)&k,    g_k);
    cudaGetSymbolAddress((void**)&v,    g_v);
    cudaGetSymbolAddress((void**)&comb, g_comb);
    cudaGetSymbolAddress((void**)&kvp,  g_kv_part);
    cudaGetSymbolAddress((void**)&kv,   g_kv);
    cudaGetSymbolAddress((void**)&ksp,  g_ksum_part);
    cudaGetSymbolAddress((void**)&ks,   g_ksum);
    cudaGetSymbolAddress((void**)&gate, g_gate);

    dim3 blk(256);
    dim3 grd(Hsz / 128, Msz / 128);   // (8, 64)

    sgemm128<<<grd, blk>>>(x, Wq, bq, q, Msz, Hsz, Hsz);
    sgemm128<<<grd, blk>>>(x, Wk, bk, k, Msz, Hsz, Hsz);
    sgemm128<<<grd, blk>>>(x, Wv, bv, v, Msz, Hsz, Hsz);

    gate_kernel<<<Msz, 256>>>(x, Wg, bg, gate);

    rope_map_kernel<<<(Bsz * Ssz * Nh * 32) / 256, 256>>>(mask, q, k, v);

    kv_partial_kernel<<<dim3(64, 8), 256>>>(k, v, kvp, ksp);
    kv_reduce_kernel<<<64, 256>>>(kvp, ksp, kv, ks);

    combine_kernel<<<dim3(64, Ssz / 64), 256>>>(q, kv, ks, gate, df, gw, comb);

    sgemm128<<<grd, blk>>>(comb, Wo, bo, out, Msz, Hsz, Hsz);
}

// round 3
// speedup vs baseline: 1.8245x; 1.8245x over previous
#include <cuda_runtime.h>
#include <cuda_bf16.h>
#include <math.h>
#include <stdint.h>

// Problem constants
#define Bsz 4
#define Ssz 2048
#define Hsz 1024
#define Nh  16
#define Dh  64
#define Msz (Bsz*Ssz)      // 8192
#define EPSF 1e-6f

// ---------------- scratch (static device globals; no allocs allowed) -------
__device__ float g_q[Msz*Hsz];
__device__ float g_k[Msz*Hsz];
__device__ float g_v[Msz*Hsz];
__device__ float g_comb[Msz*Hsz];
__device__ float g_kv_part[8*64*64*64];
__device__ float g_kv[64*64*64];
__device__ float g_ksum_part[8*64*64];
__device__ float g_ksum[64*64];
__device__ float g_gate[Msz];
// bf16x3 operands
__device__ __nv_bfloat16 g_ah[Msz*Hsz];   // activation hi
__device__ __nv_bfloat16 g_al[Msz*Hsz];   // activation lo
__device__ __nv_bfloat16 g_bqh[Hsz*Hsz], g_bql[Hsz*Hsz];
__device__ __nv_bfloat16 g_bkh[Hsz*Hsz], g_bkl[Hsz*Hsz];
__device__ __nv_bfloat16 g_bvh[Hsz*Hsz], g_bvl[Hsz*Hsz];
__device__ __nv_bfloat16 g_boh[Hsz*Hsz], g_bol[Hsz*Hsz];

// ================= low-level helpers =======================================
static __device__ __forceinline__ uint32_t s2u(const void* p) {
    uint32_t a;
    asm("{ .reg .u64 t; cvta.to.shared.u64 t, %1; cvt.u32.u64 %0, t; }"
        : "=r"(a) : "l"(p));
    return a;
}

#define CP16(saddr, gptr) \
    asm volatile("cp.async.cg.shared.global [%0], [%1], 16;" \
                 :: "r"(saddr), "l"(gptr))
#define CP_COMMIT() asm volatile("cp.async.commit_group;")
#define CP_WAIT1()  asm volatile("cp.async.wait_group 1;")

static __device__ __forceinline__ void ldsm4(uint32_t* r, uint32_t addr) {
    asm volatile("ldmatrix.sync.aligned.m8n8.x4.shared.b16 {%0,%1,%2,%3}, [%4];"
                 : "=r"(r[0]), "=r"(r[1]), "=r"(r[2]), "=r"(r[3]) : "r"(addr));
}

static __device__ __forceinline__ void mma16816(float* d, const uint32_t* a,
                                                const uint32_t* b) {
    asm volatile(
        "mma.sync.aligned.m16n8k16.row.col.f32.bf16.bf16.f32 "
        "{%0,%1,%2,%3}, {%4,%5,%6,%7}, {%8,%9}, {%0,%1,%2,%3};"
        : "+f"(d[0]), "+f"(d[1]), "+f"(d[2]), "+f"(d[3])
        : "r"(a[0]), "r"(a[1]), "r"(a[2]), "r"(a[3]), "r"(b[0]), "r"(b[1]));
}

// smem tile layout: [128 rows][32 bf16 = 4 x 16B chunks], chunk XOR-swizzled
static __device__ __forceinline__ uint32_t swoff(int row, int c16) {
    return (uint32_t)(row * 64 + ((c16 ^ ((row >> 1) & 3)) << 4));
}

// ================= bf16x3 mma.sync GEMM ====================================
// C[8192,1024] = (Ah+Al)[8192,1024] @ (Bh+Bl)^T + bias
// B stored [N][K] K-major. CTA 128x128, BK=32, 3 K-segments of 1024:
//   seg0: Ah*Bh, seg1: Ah*Bl, seg2: Al*Bh  (all fp32-accumulated)
#define STAGES 3
#define STAGE_BYTES 16384          // A 8KB + B 8KB
#define GEMM_SMEM (STAGES * STAGE_BYTES)
#define NIT 96                     // 3 segments * (1024/32)

static __device__ __forceinline__ void load_stage(
    uint32_t sbase, int slot,
    const __nv_bfloat16* __restrict__ A, const __nv_bfloat16* __restrict__ B,
    int m0, int n0, int kk, int tid)
{
    uint32_t sA = sbase + slot * STAGE_BYTES;
    uint32_t sB = sA + 8192;
#pragma unroll
    for (int i = 0; i < 2; i++) {
        int c = tid + i * 256;            // 0..511
        int row = c >> 2, c16 = c & 3;
        uint32_t so = swoff(row, c16);
        const __nv_bfloat16* ga = A + (long)(m0 + row) * 1024 + kk + c16 * 8;
        const __nv_bfloat16* gb = B + (long)(n0 + row) * 1024 + kk + c16 * 8;
        CP16(sA + so, ga);
        CP16(sB + so, gb);
    }
}

__global__ __launch_bounds__(256, 2)
void gemm_mma_bf16x3(const __nv_bfloat16* __restrict__ Ah,
                     const __nv_bfloat16* __restrict__ Al,
                     const __nv_bfloat16* __restrict__ Bh,
                     const __nv_bfloat16* __restrict__ Bl,
                     const float* __restrict__ bias, float* __restrict__ C)
{
    extern __shared__ char smem[];
    const uint32_t sbase = s2u(smem);
    const int tid = threadIdx.x;
    const int lane = tid & 31, wid = tid >> 5;
    const int wm = wid & 3, wn = wid >> 2;
    const int n0 = blockIdx.x * 128, m0 = blockIdx.y * 128;

    // ldmatrix per-lane coordinates
    const int a_row  = wm * 32 + (lane & 15);       // + mi*16
    const int a_c16h = lane >> 4;                   // 0/1 -> k halves
    const int b_row  = wn * 64 + ((lane >> 4) << 3) + (lane & 7);  // + nb*16
    const int b_c16h = (lane >> 3) & 1;

    float acc[2][8][4];
#pragma unroll
    for (int mi = 0; mi < 2; mi++)
#pragma unroll
        for (int ni = 0; ni < 8; ni++)
#pragma unroll
            for (int u = 0; u < 4; u++) acc[mi][ni][u] = 0.f;

    // preload stages 0..STAGES-2
#pragma unroll
    for (int p = 0; p < STAGES - 1; p++) {
        const int seg = p >> 5, kk = (p & 31) * 32;
        const __nv_bfloat16* A = (seg == 2) ? Al : Ah;
        const __nv_bfloat16* B = (seg == 1) ? Bl : Bh;
        load_stage(sbase, p, A, B, m0, n0, kk, tid);
        CP_COMMIT();
    }
    CP_WAIT1();
    __syncthreads();

    for (int it = 0; it < NIT; it++) {
        const int pf = it + STAGES - 1;
        if (pf < NIT) {
            const int seg = pf >> 5, kk = (pf & 31) * 32;
            const __nv_bfloat16* A = (seg == 2) ? Al : Ah;
            const __nv_bfloat16* B = (seg == 1) ? Bl : Bh;
            load_stage(sbase, pf % STAGES, A, B, m0, n0, kk, tid);
        }
        CP_COMMIT();

        // compute on slot it%STAGES
        const uint32_t sA = sbase + (it % STAGES) * STAGE_BYTES;
        const uint32_t sB = sA + 8192;
#pragma unroll
        for (int ks = 0; ks < 2; ks++) {
            uint32_t af[2][4];
            ldsm4(af[0], sA + swoff(a_row,      ks * 2 + a_c16h));
            ldsm4(af[1], sA + swoff(a_row + 16, ks * 2 + a_c16h));
#pragma unroll
            for (int nb = 0; nb < 4; nb++) {
                uint32_t bf[4];
                ldsm4(bf, sB + swoff(b_row + nb * 16, ks * 2 + b_c16h));
                mma16816(acc[0][nb * 2 + 0], af[0], bf + 0);
                mma16816(acc[0][nb * 2 + 1], af[0], bf + 2);
                mma16816(acc[1][nb * 2 + 0], af[1], bf + 0);
                mma16816(acc[1][nb * 2 + 1], af[1], bf + 2);
            }
        }
        CP_WAIT1();
        __syncthreads();
    }

    // epilogue: direct register -> gmem with bias
    const int mb = m0 + wm * 32 + (lane >> 2);
    const int nb0 = n0 + wn * 64 + 2 * (lane & 3);
#pragma unroll
    for (int mi = 0; mi < 2; mi++) {
#pragma unroll
        for (int ni = 0; ni < 8; ni++) {
            const int r = mb + mi * 16;
            const int c = nb0 + ni * 8;
            float2 bb = *(const float2*)(bias + c);
            float2 v0 = make_float2(acc[mi][ni][0] + bb.x, acc[mi][ni][1] + bb.y);
            float2 v1 = make_float2(acc[mi][ni][2] + bb.x, acc[mi][ni][3] + bb.y);
            *(float2*)(C + (long)r * 1024 + c)       = v0;
            *(float2*)(C + (long)(r + 8) * 1024 + c) = v1;
        }
    }
}

// ================= conversions =============================================
__global__ void cvt_split(const float4* __restrict__ x,
                          uint2* __restrict__ hi, uint2* __restrict__ lo)
{
    long i = (long)blockIdx.x * 256 + threadIdx.x;
    float4 v = x[i];
    float f[4] = {v.x, v.y, v.z, v.w};
    unsigned short hs[4], ls[4];
#pragma unroll
    for (int j = 0; j < 4; j++) {
        __nv_bfloat16 h = __float2bfloat16(f[j]);
        float r = f[j] - __bfloat162float(h);
        __nv_bfloat16 l = __float2bfloat16(r);
        hs[j] = *(unsigned short*)&h;
        ls[j] = *(unsigned short*)&l;
    }
    uint2 H, L;
    H.x = (uint32_t)hs[0] | ((uint32_t)hs[1] << 16);
    H.y = (uint32_t)hs[2] | ((uint32_t)hs[3] << 16);
    L.x = (uint32_t)ls[0] | ((uint32_t)ls[1] << 16);
    L.y = (uint32_t)ls[2] | ((uint32_t)ls[3] << 16);
    hi[i] = H;
    lo[i] = L;
}

// W[K=1024][N=1024] fp32 -> transposed hi/lo bf16 [N][K]
__global__ void cvt_w(const float* __restrict__ W,
                      __nv_bfloat16* __restrict__ bh, __nv_bfloat16* __restrict__ bl)
{
    __shared__ float t[32][33];
    const int nx = blockIdx.x * 32, kx = blockIdx.y * 32;
    const int tx = threadIdx.x, ty = threadIdx.y;   // 32 x 8
#pragma unroll
    for (int r = 0; r < 32; r += 8)
        t[ty + r][tx] = W[(long)(kx + ty + r) * 1024 + nx + tx];
    __syncthreads();
#pragma unroll
    for (int r = 0; r < 32; r += 8) {
        float v = t[tx][ty + r];
        __nv_bfloat16 h = __float2bfloat16(v);
        float rr = v - __bfloat162float(h);
        __nv_bfloat16 l = __float2bfloat16(rr);
        long o = (long)(nx + ty + r) * 1024 + kx + tx;
        bh[o] = h;
        bl[o] = l;
    }
}

// ---------------- gate: g[row] = sigmoid(x[row,:] . Wg + bg) ---------------
__global__ void gate_kernel(const float* __restrict__ X,
                            const float* __restrict__ Wg,
                            const float* __restrict__ bg,
                            float* __restrict__ gout)
{
    const int row = blockIdx.x;
    const float* xr = X + (long)row * Hsz;
    float s = 0.f;
    for (int h = threadIdx.x; h < Hsz; h += 256) s += xr[h] * Wg[h];
#pragma unroll
    for (int o = 16; o; o >>= 1) s += __shfl_down_sync(0xffffffffu, s, o);
    __shared__ float ws[8];
    if ((threadIdx.x & 31) == 0) ws[threadIdx.x >> 5] = s;
    __syncthreads();
    if (threadIdx.x == 0) {
        float t = 0.f;
#pragma unroll
        for (int i = 0; i < 8; i++) t += ws[i];
        t += bg[0];
        gout[row] = 1.f / (1.f + expf(-t));
    }
}

// ---------------- RoPE + feature map (in place on q,k) + mask (k,v) --------
__device__ __forceinline__ float phi_fn(float x) {
    float t = (x > 0.f) ? x : expm1f(x);
    return (t + 1.0f) + EPSF;
}

__global__ void rope_map_kernel(const float* __restrict__ mask,
                                float* __restrict__ q,
                                float* __restrict__ k,
                                float* __restrict__ v)
{
    __shared__ float invf_s[32];
    const int tid = threadIdx.x;
    if (tid < 32) {
        double p = pow(10000.0, (double)(2 * tid) / 64.0);
        invf_s[tid] = 1.0f / (float)p;
    }
    __syncthreads();

    long idx = (long)blockIdx.x * 256 + tid;
    const int i = (int)(idx & 31);
    long t = idx >> 5;
    const int n = (int)(t & 15); t >>= 4;
    const int s = (int)(t & 2047);
    const int b = (int)(t >> 11);

    const float m = mask[b * Ssz + s];
    const float freq = (float)s * invf_s[i];
    const float c = cosf(freq), sn = sinf(freq);

    const long base = (((long)(b * Ssz + s) * Nh) + n) * Dh + i;

    float q1 = q[base], q2 = q[base + 32];
    float rq1 = q1 * c - q2 * sn;
    float rq2 = q2 * c + q1 * sn;
    q[base]      = phi_fn(rq1) * 0.125f;
    q[base + 32] = phi_fn(rq2) * 0.125f;

    float k1 = k[base], k2 = k[base + 32];
    float rk1 = k1 * c - k2 * sn;
    float rk2 = k2 * c + k1 * sn;
    k[base]      = phi_fn(rk1) * m;
    k[base + 32] = phi_fn(rk2) * m;

    v[base]      *= m;
    v[base + 32] *= m;
}

// ---------------- kv partial: per (b,n,chunk) 64x64 outer-product sum ------
__global__ void kv_partial_kernel(const float* __restrict__ k,
                                  const float* __restrict__ v,
                                  float* __restrict__ kv_part,
                                  float* __restrict__ ksum_part)
{
    const int bn = blockIdx.x;
    const int c  = blockIdx.y;
    const int b = bn >> 4, n = bn & 15;
    __shared__ float ks[32][64];
    __shared__ float vs[32][64];
    const int tid = threadIdx.x;
    const int ti = tid >> 4, tj = tid & 15;

    float acc[4][4];
#pragma unroll
    for (int a = 0; a < 4; a++)
#pragma unroll
        for (int d = 0; d < 4; d++) acc[a][d] = 0.f;
    float ksum = 0.f;

    const int s0 = c * 256;
    for (int so = 0; so < 256; so += 32) {
#pragma unroll
        for (int e = tid; e < 512; e += 256) {
            int sl = e >> 4, dd = (e & 15) * 4;
            long gb = (((long)(b * Ssz + s0 + so + sl) * Nh) + n) * Dh + dd;
            *(float4*)&ks[sl][dd] = *(const float4*)&k[gb];
            *(float4*)&vs[sl][dd] = *(const float4*)&v[gb];
        }
        __syncthreads();
#pragma unroll 4
        for (int sl = 0; sl < 32; ++sl) {
            float4 kk4 = *(const float4*)&ks[sl][ti * 4];
            float4 vv4 = *(const float4*)&vs[sl][tj * 4];
            float ka[4] = {kk4.x, kk4.y, kk4.z, kk4.w};
            float va[4] = {vv4.x, vv4.y, vv4.z, vv4.w};
#pragma unroll
            for (int a = 0; a < 4; a++)
#pragma unroll
                for (int d = 0; d < 4; d++) acc[a][d] += ka[a] * va[d];
        }
        if (tid < 64) {
#pragma unroll 4
            for (int sl = 0; sl < 32; ++sl) ksum += ks[sl][tid];
        }
        __syncthreads();
    }

    const long pbase = ((long)c * 64 + bn) * 4096;
#pragma unroll
    for (int a = 0; a < 4; a++) {
        float4 o = make_float4(acc[a][0], acc[a][1], acc[a][2], acc[a][3]);
        *(float4*)&kv_part[pbase + (ti * 4 + a) * 64 + tj * 4] = o;
    }
    if (tid < 64) ksum_part[(c * 64 + bn) * 64 + tid] = ksum;
}

__global__ void kv_reduce_kernel(const float* __restrict__ kv_part,
                                 const float* __restrict__ ksum_part,
                                 float* __restrict__ kv,
                                 float* __restrict__ ksum)
{
    const int bn = blockIdx.x;
    const int tid = threadIdx.x;
    for (int e = tid; e < 4096; e += 256) {
        float s = 0.f;
#pragma unroll
        for (int c = 0; c < 8; ++c) s += kv_part[((long)c * 64 + bn) * 4096 + e];
        kv[(long)bn * 4096 + e] = s;
    }
    if (tid < 64) {
        float s = 0.f;
#pragma unroll
        for (int c = 0; c < 8; ++c) s += ksum_part[(c * 64 + bn) * 64 + tid];
        ksum[bn * 64 + tid] = s;
    }
}

// ---------------- combine: num = q@kv ; den = q.ksum+eps ; gate mix --------
__global__ void combine_kernel(const float* __restrict__ q,
                               const float* __restrict__ kv,
                               const float* __restrict__ ksum,
                               const float* __restrict__ gate,
                               const float* __restrict__ df,
                               const float* __restrict__ gw,
                               float* __restrict__ comb)
{
    const int bn = blockIdx.x;
    const int st = blockIdx.y;
    const int b = bn >> 4, n = bn & 15;

    __shared__ float qs[64][68];
    __shared__ float kvs[64][64];
    __shared__ float ksums[64];

    const int tid = threadIdx.x;

    float w0 = gw[0], w1 = gw[1], w2 = gw[2];
    float d0 = df[0], d1 = df[1], d2 = df[2];
    float mx = fmaxf(w0, fmaxf(w1, w2));
    float e0 = expf(w0 - mx), e1 = expf(w1 - mx), e2 = expf(w2 - mx);
    float s0f = 1.f / (1.f + expf(-d0));
    float s1f = 1.f / (1.f + expf(-d1));
    float s2f = 1.f / (1.f + expf(-d2));
    float coef = (e0 * (1.f - s0f) + e1 * (1.f - s1f) + e2 * (1.f - s2f)) / (e0 + e1 + e2);

    const long kvbase = (long)bn * 4096;
    for (int e = tid; e < 1024; e += 256)
        ((float4*)kvs)[e] = ((const float4*)(kv + kvbase))[e];
    if (tid < 64) ksums[tid] = ksum[bn * 64 + tid];

    const int srow0 = st * 64;
    for (int e = tid; e < 1024; e += 256) {
        int r = e >> 4, dd = (e & 15) * 4;
        long gq = (((long)(b * Ssz + srow0 + r) * Nh) + n) * Dh + dd;
        *(float4*)&qs[r][dd] = *(const float4*)&q[gq];
    }
    __syncthreads();

    const int sl = tid >> 2;
    const int jg = tid & 3;
    float acc[16];
#pragma unroll
    for (int j = 0; j < 16; j++) acc[j] = 0.f;
    float den = 0.f;

#pragma unroll 4
    for (int kk = 0; kk < 64; ++kk) {
        float qv = qs[sl][kk];
        den += qv * ksums[kk];
        const float4* kr = (const float4*)&kvs[kk][jg * 16];
        float4 c0 = kr[0], c1 = kr[1], c2 = kr[2], c3 = kr[3];
        acc[0]  += qv * c0.x; acc[1]  += qv * c0.y; acc[2]  += qv * c0.z; acc[3]  += qv * c0.w;
        acc[4]  += qv * c1.x; acc[5]  += qv * c1.y; acc[6]  += qv * c1.z; acc[7]  += qv * c1.w;
        acc[8]  += qv * c2.x; acc[9]  += qv * c2.y; acc[10] += qv * c2.z; acc[11] += qv * c2.w;
        acc[12] += qv * c3.x; acc[13] += qv * c3.y; acc[14] += qv * c3.z; acc[15] += qv * c3.w;
    }
    den += EPSF;

    const int srow = srow0 + sl;
    const float g = gate[b * Ssz + srow];
    const float fac = g / den + (1.f - g) * coef;

    const long obase = (((long)(b * Ssz + srow) * Nh) + n) * Dh + jg * 16;
#pragma unroll
    for (int u = 0; u < 4; u++) {
        float4 o = make_float4(acc[u * 4 + 0] * fac, acc[u * 4 + 1] * fac,
                               acc[u * 4 + 2] * fac, acc[u * 4 + 3] * fac);
        *(float4*)&comb[obase + u * 4] = o;
    }
}

// ---------------------------------------------------------------------------
extern "C" void kernel_launch(void* const* d_in, const int* in_sizes, int n_in,
                              void* d_out, int out_size)
{
    const float* x    = (const float*)d_in[0];
    const float* mask = (const float*)d_in[1];
    const float* Wq   = (const float*)d_in[2];
    const float* bq   = (const float*)d_in[3];
    const float* Wk   = (const float*)d_in[4];
    const float* bk   = (const float*)d_in[5];
    const float* Wv   = (const float*)d_in[6];
    const float* bv   = (const float*)d_in[7];
    const float* Wo   = (const float*)d_in[8];
    const float* bo   = (const float*)d_in[9];
    const float* Wg   = (const float*)d_in[10];
    const float* bg   = (const float*)d_in[11];
    const float* df   = (const float*)d_in[12];
    const float* gw   = (const float*)d_in[13];
    float* out = (float*)d_out;

    float *q, *k, *v, *comb, *kvp, *kv, *ksp, *ks, *gate;
    __nv_bfloat16 *ah, *al, *bqh, *bql, *bkh, *bkl, *bvh, *bvl, *boh, *bol;
    cudaGetSymbolAddress((void**)&q,    g_q);
    cudaGetSymbolAddress((void**)&k,    g_k);
    cudaGetSymbolAddress((void**)&v,    g_v);
    cudaGetSymbolAddress((void**)&comb, g_comb);
    cudaGetSymbolAddress((void**)&kvp,  g_kv_part);
    cudaGetSymbolAddress((void**)&kv,   g_kv);
    cudaGetSymbolAddress((void**)&ksp,  g_ksum_part);
    cudaGetSymbolAddress((void**)&ks,   g_ksum);
    cudaGetSymbolAddress((void**)&gate, g_gate);
    cudaGetSymbolAddress((void**)&ah,   g_ah);
    cudaGetSymbolAddress((void**)&al,   g_al);
    cudaGetSymbolAddress((void**)&bqh,  g_bqh);
    cudaGetSymbolAddress((void**)&bql,  g_bql);
    cudaGetSymbolAddress((void**)&bkh,  g_bkh);
    cudaGetSymbolAddress((void**)&bkl,  g_bkl);
    cudaGetSymbolAddress((void**)&bvh,  g_bvh);
    cudaGetSymbolAddress((void**)&bvl,  g_bvl);
    cudaGetSymbolAddress((void**)&boh,  g_boh);
    cudaGetSymbolAddress((void**)&bol,  g_bol);

    cudaFuncSetAttribute(gemm_mma_bf16x3,
                         cudaFuncAttributeMaxDynamicSharedMemorySize, GEMM_SMEM);

    dim3 gblk(256);
    dim3 ggrd(Hsz / 128, Msz / 128);   // (8, 64)
    dim3 wblk(32, 8);
    dim3 wgrd(32, 32);

    // split activations + weights to bf16 hi/lo
    cvt_split<<<Msz * Hsz / 1024, 256>>>((const float4*)x, (uint2*)ah, (uint2*)al);
    cvt_w<<<wgrd, wblk>>>(Wq, bqh, bql);
    cvt_w<<<wgrd, wblk>>>(Wk, bkh, bkl);
    cvt_w<<<wgrd, wblk>>>(Wv, bvh, bvl);
    cvt_w<<<wgrd, wblk>>>(Wo, boh, bol);

    gemm_mma_bf16x3<<<ggrd, gblk, GEMM_SMEM>>>(ah, al, bqh, bql, bq, q);
    gemm_mma_bf16x3<<<ggrd, gblk, GEMM_SMEM>>>(ah, al, bkh, bkl, bk, k);
    gemm_mma_bf16x3<<<ggrd, gblk, GEMM_SMEM>>>(ah, al, bvh, bvl, bv, v);

    gate_kernel<<<Msz, 256>>>(x, Wg, bg, gate);

    rope_map_kernel<<<(Bsz * Ssz * Nh * 32) / 256, 256>>>(mask, q, k, v);

    kv_partial_kernel<<<dim3(64, 8), 256>>>(k, v, kvp, ksp);
    kv_reduce_kernel<<<64, 256>>>(kvp, ksp, kv, ks);

    combine_kernel<<<dim3(64, Ssz / 64), 256>>>(q, kv, ks, gate, df, gw, comb);

    cvt_split<<<Msz * Hsz / 1024, 256>>>((const float4*)comb, (uint2*)ah, (uint2*)al);
    gemm_mma_bf16x3<<<ggrd, gblk, GEMM_SMEM>>>(ah, al, boh, bol, bo, out);
}

// round 4
// speedup vs baseline: 2.2173x; 1.2153x over previous
#include <cuda_runtime.h>
#include <cuda.h>
#include <cuda_bf16.h>
#include <math.h>
#include <stdint.h>

// Problem constants
#define Bsz 4
#define Ssz 2048
#define Hsz 1024
#define Nh  16
#define Dh  64
#define Msz (Bsz*Ssz)      // 8192
#define EPSF 1e-6f

// ---------------- scratch (static device globals; no allocs allowed) -------
__device__ float g_q[Msz*Hsz];
__device__ float g_k[Msz*Hsz];
__device__ float g_v[Msz*Hsz];
__device__ float g_kv_part[8*64*64*64];
__device__ float g_kv[64*64*64];
__device__ float g_ksum_part[8*64*64];
__device__ float g_ksum[64*64];
__device__ float g_gate[Msz];
// bf16x3 operands
__device__ __nv_bfloat16 g_ah[Msz*Hsz];   // activation hi
__device__ __nv_bfloat16 g_al[Msz*Hsz];   // activation lo
__device__ __nv_bfloat16 g_bqh[Hsz*Hsz], g_bql[Hsz*Hsz];
__device__ __nv_bfloat16 g_bkh[Hsz*Hsz], g_bkl[Hsz*Hsz];
__device__ __nv_bfloat16 g_bvh[Hsz*Hsz], g_bvl[Hsz*Hsz];
__device__ __nv_bfloat16 g_boh[Hsz*Hsz], g_bol[Hsz*Hsz];

// ================= low-level helpers =======================================
static __device__ __forceinline__ uint32_t s2u(const void* p) {
    uint32_t a;
    asm("{ .reg .u64 t; cvta.to.shared.u64 t, %1; cvt.u32.u64 %0, t; }"
        : "=r"(a) : "l"(p));
    return a;
}

static __device__ __forceinline__ void ldsm4(uint32_t* r, uint32_t addr) {
    asm volatile("ldmatrix.sync.aligned.m8n8.x4.shared.b16 {%0,%1,%2,%3}, [%4];"
                 : "=r"(r[0]), "=r"(r[1]), "=r"(r[2]), "=r"(r[3]) : "r"(addr));
}

static __device__ __forceinline__ void mma16816(float* d, const uint32_t* a,
                                                const uint32_t* b) {
    asm volatile(
        "mma.sync.aligned.m16n8k16.row.col.f32.bf16.bf16.f32 "
        "{%0,%1,%2,%3}, {%4,%5,%6,%7}, {%8,%9}, {%0,%1,%2,%3};"
        : "+f"(d[0]), "+f"(d[1]), "+f"(d[2]), "+f"(d[3])
        : "r"(a[0]), "r"(a[1]), "r"(a[2]), "r"(a[3]), "r"(b[0]), "r"(b[1]));
}

// smem tile: [128 rows][32 bf16 = 64B], SW64 swizzle: chunk16 ^= (row>>1)&3
// (identical byte pattern to TMA CU_TENSOR_MAP_SWIZZLE_64B with 64B rows)
static __device__ __forceinline__ uint32_t swoff(int row, int c16) {
    return (uint32_t)(row * 64 + ((c16 ^ ((row >> 1) & 3)) << 4));
}

#define MBAR_INIT(m, c) \
    asm volatile("mbarrier.init.shared.b64 [%0], %1;" \
                 :: "r"((uint32_t)(m)), "r"((uint32_t)(c)) : "memory")
#define MBAR_EXPECT(m, b) \
    asm volatile("mbarrier.arrive.expect_tx.shared.b64 _, [%0], %1;" \
                 :: "r"((uint32_t)(m)), "r"((uint32_t)(b)) : "memory")

static __device__ __forceinline__ void mbar_wait(uint32_t mbar, uint32_t parity) {
    asm volatile(
        "{\n\t.reg .pred P;\n\t"
        "WL_%=:\n\t"
        "mbarrier.try_wait.parity.acquire.cta.shared::cta.b64 P, [%0], %1, 0x989680;\n\t"
        "@P bra.uni WD_%=;\n\t"
        "bra.uni WL_%=;\n\t"
        "WD_%=:\n\t}"
        :: "r"(mbar), "r"(parity) : "memory");
}

#define TMA2D(sa, mp, cx, cy, mb) \
    asm volatile("cp.async.bulk.tensor.2d.shared::cta.global.tile.mbarrier::complete_tx::bytes " \
                 "[%0], [%1, {%2, %3}], [%4];" \
                 :: "r"((uint32_t)(sa)), "l"(mp), "r"((int)(cx)), "r"((int)(cy)), \
                    "r"((uint32_t)(mb)) : "memory")

// ================= bf16x3 mma.sync + TMA GEMM ==============================
// C[8192,1024] = (Ah+Al) @ (Bh+Bl)^T + bias, B stored [N][K] K-major.
// CTA 128x128, BK=32, 32 K-chunks, 3 products per chunk from shared tiles.
// Stage = 32KB (Ah 8K | Al 8K | Bh 8K | Bl 8K), 3 stages, TMA + mbarrier.
#define NCHUNK 32
#define STAGE_BYTES 32768
#define GEMM_SMEM (3 * STAGE_BYTES + 64)

__global__ __launch_bounds__(256, 2)
void gemm_tma_bf16x3(const __grid_constant__ CUtensorMap mAh,
                     const __grid_constant__ CUtensorMap mAl,
                     const __grid_constant__ CUtensorMap mB0h,
                     const __grid_constant__ CUtensorMap mB0l,
                     const __grid_constant__ CUtensorMap mB1h,
                     const __grid_constant__ CUtensorMap mB1l,
                     const __grid_constant__ CUtensorMap mB2h,
                     const __grid_constant__ CUtensorMap mB2l,
                     const float* __restrict__ b0, const float* __restrict__ b1,
                     const float* __restrict__ b2,
                     float* __restrict__ C0, float* __restrict__ C1,
                     float* __restrict__ C2)
{
    extern __shared__ __align__(1024) char smem[];
    const uint32_t sbase = s2u(smem);
    const uint32_t mbb = sbase + 3 * STAGE_BYTES;
    const int tid = threadIdx.x;
    const int lane = tid & 31, wid = tid >> 5;
    const int wm = wid & 3, wn = wid >> 2;
    const int n0 = blockIdx.x * 128, m0 = blockIdx.y * 128;
    const int z = blockIdx.z;

    const CUtensorMap* pBh = (z == 0) ? &mB0h : (z == 1) ? &mB1h : &mB2h;
    const CUtensorMap* pBl = (z == 0) ? &mB0l : (z == 1) ? &mB1l : &mB2l;
    const float* bias = (z == 0) ? b0 : (z == 1) ? b1 : b2;
    float* C = (z == 0) ? C0 : (z == 1) ? C1 : C2;

    // ldmatrix per-lane coordinates (same as validated R3 layout)
    const int a_row  = wm * 32 + (lane & 15);
    const int a_c16h = lane >> 4;
    const int b_row  = wn * 64 + ((lane >> 4) << 3) + (lane & 7);
    const int b_c16h = (lane >> 3) & 1;

    float acc[2][8][4];
#pragma unroll
    for (int mi = 0; mi < 2; mi++)
#pragma unroll
        for (int ni = 0; ni < 8; ni++)
#pragma unroll
            for (int u = 0; u < 4; u++) acc[mi][ni][u] = 0.f;

    if (tid == 0) {
        MBAR_INIT(mbb + 0, 1);
        MBAR_INIT(mbb + 8, 1);
        MBAR_INIT(mbb + 16, 1);
    }
    __syncthreads();

    if (tid == 0) {
#pragma unroll
        for (int s = 0; s < 3; s++) {
            const uint32_t db = sbase + s * STAGE_BYTES;
            MBAR_EXPECT(mbb + s * 8, STAGE_BYTES);
            TMA2D(db,         &mAh, s * 32, m0, mbb + s * 8);
            TMA2D(db + 8192,  &mAl, s * 32, m0, mbb + s * 8);
            TMA2D(db + 16384, pBh,  s * 32, n0, mbb + s * 8);
            TMA2D(db + 24576, pBl,  s * 32, n0, mbb + s * 8);
        }
    }

    for (int it = 0; it < NCHUNK; it++) {
        const int s = it % 3;
        mbar_wait(mbb + s * 8, (it / 3) & 1);

        const uint32_t base = sbase + s * STAGE_BYTES;
#pragma unroll
        for (int ks = 0; ks < 2; ks++) {
            uint32_t aH[2][4], aL[2][4];
            ldsm4(aH[0], base +        swoff(a_row,      ks * 2 + a_c16h));
            ldsm4(aH[1], base +        swoff(a_row + 16, ks * 2 + a_c16h));
            ldsm4(aL[0], base + 8192 + swoff(a_row,      ks * 2 + a_c16h));
            ldsm4(aL[1], base + 8192 + swoff(a_row + 16, ks * 2 + a_c16h));
#pragma unroll
            for (int nb = 0; nb < 4; nb++) {
                uint32_t bH[4], bL[4];
                ldsm4(bH, base + 16384 + swoff(b_row + nb * 16, ks * 2 + b_c16h));
                ldsm4(bL, base + 24576 + swoff(b_row + nb * 16, ks * 2 + b_c16h));
                mma16816(acc[0][nb * 2 + 0], aH[0], bH + 0);
                mma16816(acc[0][nb * 2 + 1], aH[0], bH + 2);
                mma16816(acc[1][nb * 2 + 0], aH[1], bH + 0);
                mma16816(acc[1][nb * 2 + 1], aH[1], bH + 2);
                mma16816(acc[0][nb * 2 + 0], aH[0], bL + 0);
                mma16816(acc[0][nb * 2 + 1], aH[0], bL + 2);
                mma16816(acc[1][nb * 2 + 0], aH[1], bL + 0);
                mma16816(acc[1][nb * 2 + 1], aH[1], bL + 2);
                mma16816(acc[0][nb * 2 + 0], aL[0], bH + 0);
                mma16816(acc[0][nb * 2 + 1], aL[0], bH + 2);
                mma16816(acc[1][nb * 2 + 0], aL[1], bH + 0);
                mma16816(acc[1][nb * 2 + 1], aL[1], bH + 2);
            }
        }
        __syncthreads();

        const int nc = it + 3;
        if (nc < NCHUNK && tid == 0) {
            const uint32_t db = sbase + s * STAGE_BYTES;
            MBAR_EXPECT(mbb + s * 8, STAGE_BYTES);
            TMA2D(db,         &mAh, nc * 32, m0, mbb + s * 8);
            TMA2D(db + 8192,  &mAl, nc * 32, m0, mbb + s * 8);
            TMA2D(db + 16384, pBh,  nc * 32, n0, mbb + s * 8);
            TMA2D(db + 24576, pBl,  nc * 32, n0, mbb + s * 8);
        }
    }

    // epilogue: direct register -> gmem with bias
    const int mb = m0 + wm * 32 + (lane >> 2);
    const int nb0 = n0 + wn * 64 + 2 * (lane & 3);
#pragma unroll
    for (int mi = 0; mi < 2; mi++) {
#pragma unroll
        for (int ni = 0; ni < 8; ni++) {
            const int r = mb + mi * 16;
            const int c = nb0 + ni * 8;
            float2 bb = *(const float2*)(bias + c);
            float2 v0 = make_float2(acc[mi][ni][0] + bb.x, acc[mi][ni][1] + bb.y);
            float2 v1 = make_float2(acc[mi][ni][2] + bb.x, acc[mi][ni][3] + bb.y);
            *(float2*)(C + (long)r * 1024 + c)       = v0;
            *(float2*)(C + (long)(r + 8) * 1024 + c) = v1;
        }
    }
}

// ================= conversions =============================================
__global__ void cvt_split(const float4* __restrict__ x,
                          uint2* __restrict__ hi, uint2* __restrict__ lo)
{
    long i = (long)blockIdx.x * 256 + threadIdx.x;
    float4 v = x[i];
    float f[4] = {v.x, v.y, v.z, v.w};
    unsigned short hs[4], ls[4];
#pragma unroll
    for (int j = 0; j < 4; j++) {
        __nv_bfloat16 h = __float2bfloat16(f[j]);
        float r = f[j] - __bfloat162float(h);
        __nv_bfloat16 l = __float2bfloat16(r);
        hs[j] = *(unsigned short*)&h;
        ls[j] = *(unsigned short*)&l;
    }
    uint2 H, L;
    H.x = (uint32_t)hs[0] | ((uint32_t)hs[1] << 16);
    H.y = (uint32_t)hs[2] | ((uint32_t)hs[3] << 16);
    L.x = (uint32_t)ls[0] | ((uint32_t)ls[1] << 16);
    L.y = (uint32_t)ls[2] | ((uint32_t)ls[3] << 16);
    hi[i] = H;
    lo[i] = L;
}

// W[K=1024][N=1024] fp32 -> transposed hi/lo bf16 [N][K]
__global__ void cvt_w(const float* __restrict__ W,
                      __nv_bfloat16* __restrict__ bh, __nv_bfloat16* __restrict__ bl)
{
    __shared__ float t[32][33];
    const int nx = blockIdx.x * 32, kx = blockIdx.y * 32;
    const int tx = threadIdx.x, ty = threadIdx.y;   // 32 x 8
#pragma unroll
    for (int r = 0; r < 32; r += 8)
        t[ty + r][tx] = W[(long)(kx + ty + r) * 1024 + nx + tx];
    __syncthreads();
#pragma unroll
    for (int r = 0; r < 32; r += 8) {
        float v = t[tx][ty + r];
        __nv_bfloat16 h = __float2bfloat16(v);
        float rr = v - __bfloat162float(h);
        __nv_bfloat16 l = __float2bfloat16(rr);
        long o = (long)(nx + ty + r) * 1024 + kx + tx;
        bh[o] = h;
        bl[o] = l;
    }
}

// ---------------- gate: g[row] = sigmoid(x[row,:] . Wg + bg) ---------------
__global__ void gate_kernel(const float* __restrict__ X,
                            const float* __restrict__ Wg,
                            const float* __restrict__ bg,
                            float* __restrict__ gout)
{
    const int row = blockIdx.x;
    const float* xr = X + (long)row * Hsz;
    float s = 0.f;
    for (int h = threadIdx.x; h < Hsz; h += 256) s += xr[h] * Wg[h];
#pragma unroll
    for (int o = 16; o; o >>= 1) s += __shfl_down_sync(0xffffffffu, s, o);
    __shared__ float ws[8];
    if ((threadIdx.x & 31) == 0) ws[threadIdx.x >> 5] = s;
    __syncthreads();
    if (threadIdx.x == 0) {
        float t = 0.f;
#pragma unroll
        for (int i = 0; i < 8; i++) t += ws[i];
        t += bg[0];
        gout[row] = 1.f / (1.f + expf(-t));
    }
}

// ---------------- RoPE + feature map (in place on q,k) + mask (k,v) --------
__device__ __forceinline__ float phi_fn(float x) {
    float t = (x > 0.f) ? x : expm1f(x);
    return (t + 1.0f) + EPSF;
}

__global__ void rope_map_kernel(const float* __restrict__ mask,
                                float* __restrict__ q,
                                float* __restrict__ k,
                                float* __restrict__ v)
{
    __shared__ float invf_s[32];
    const int tid = threadIdx.x;
    if (tid < 32) {
        double p = pow(10000.0, (double)(2 * tid) / 64.0);
        invf_s[tid] = 1.0f / (float)p;
    }
    __syncthreads();

    long idx = (long)blockIdx.x * 256 + tid;
    const int i = (int)(idx & 31);
    long t = idx >> 5;
    const int n = (int)(t & 15); t >>= 4;
    const int s = (int)(t & 2047);
    const int b = (int)(t >> 11);

    const float m = mask[b * Ssz + s];
    const float freq = (float)s * invf_s[i];
    const float c = cosf(freq), sn = sinf(freq);

    const long base = (((long)(b * Ssz + s) * Nh) + n) * Dh + i;

    float q1 = q[base], q2 = q[base + 32];
    float rq1 = q1 * c - q2 * sn;
    float rq2 = q2 * c + q1 * sn;
    q[base]      = phi_fn(rq1) * 0.125f;
    q[base + 32] = phi_fn(rq2) * 0.125f;

    float k1 = k[base], k2 = k[base + 32];
    float rk1 = k1 * c - k2 * sn;
    float rk2 = k2 * c + k1 * sn;
    k[base]      = phi_fn(rk1) * m;
    k[base + 32] = phi_fn(rk2) * m;

    v[base]      *= m;
    v[base + 32] *= m;
}

// ---------------- kv partial: per (b,n,chunk) 64x64 outer-product sum ------
__global__ void kv_partial_kernel(const float* __restrict__ k,
                                  const float* __restrict__ v,
                                  float* __restrict__ kv_part,
                                  float* __restrict__ ksum_part)
{
    const int bn = blockIdx.x;
    const int c  = blockIdx.y;
    const int b = bn >> 4, n = bn & 15;
    __shared__ float ks[32][64];
    __shared__ float vs[32][64];
    const int tid = threadIdx.x;
    const int ti = tid >> 4, tj = tid & 15;

    float acc[4][4];
#pragma unroll
    for (int a = 0; a < 4; a++)
#pragma unroll
        for (int d = 0; d < 4; d++) acc[a][d] = 0.f;
    float ksum = 0.f;

    const int s0 = c * 256;
    for (int so = 0; so < 256; so += 32) {
#pragma unroll
        for (int e = tid; e < 512; e += 256) {
            int sl = e >> 4, dd = (e & 15) * 4;
            long gb = (((long)(b * Ssz + s0 + so + sl) * Nh) + n) * Dh + dd;
            *(float4*)&ks[sl][dd] = *(const float4*)&k[gb];
            *(float4*)&vs[sl][dd] = *(const float4*)&v[gb];
        }
        __syncthreads();
#pragma unroll 4
        for (int sl = 0; sl < 32; ++sl) {
            float4 kk4 = *(const float4*)&ks[sl][ti * 4];
            float4 vv4 = *(const float4*)&vs[sl][tj * 4];
            float ka[4] = {kk4.x, kk4.y, kk4.z, kk4.w};
            float va[4] = {vv4.x, vv4.y, vv4.z, vv4.w};
#pragma unroll
            for (int a = 0; a < 4; a++)
#pragma unroll
                for (int d = 0; d < 4; d++) acc[a][d] += ka[a] * va[d];
        }
        if (tid < 64) {
#pragma unroll 4
            for (int sl = 0; sl < 32; ++sl) ksum += ks[sl][tid];
        }
        __syncthreads();
    }

    const long pbase = ((long)c * 64 + bn) * 4096;
#pragma unroll
    for (int a = 0; a < 4; a++) {
        float4 o = make_float4(acc[a][0], acc[a][1], acc[a][2], acc[a][3]);
        *(float4*)&kv_part[pbase + (ti * 4 + a) * 64 + tj * 4] = o;
    }
    if (tid < 64) ksum_part[(c * 64 + bn) * 64 + tid] = ksum;
}

__global__ void kv_reduce_kernel(const float* __restrict__ kv_part,
                                 const float* __restrict__ ksum_part,
                                 float* __restrict__ kv,
                                 float* __restrict__ ksum)
{
    const int bn = blockIdx.x;
    const int tid = threadIdx.x;
    for (int e = tid; e < 4096; e += 256) {
        float s = 0.f;
#pragma unroll
        for (int c = 0; c < 8; ++c) s += kv_part[((long)c * 64 + bn) * 4096 + e];
        kv[(long)bn * 4096 + e] = s;
    }
    if (tid < 64) {
        float s = 0.f;
#pragma unroll
        for (int c = 0; c < 8; ++c) s += ksum_part[(c * 64 + bn) * 64 + tid];
        ksum[bn * 64 + tid] = s;
    }
}

// ---- combine: num=q@kv; den=q.ksum+eps; gate mix; write bf16 hi/lo --------
__global__ void combine_kernel(const float* __restrict__ q,
                               const float* __restrict__ kv,
                               const float* __restrict__ ksum,
                               const float* __restrict__ gate,
                               const float* __restrict__ df,
                               const float* __restrict__ gw,
                               __nv_bfloat16* __restrict__ ch,
                               __nv_bfloat16* __restrict__ cl)
{
    const int bn = blockIdx.x;
    const int st = blockIdx.y;
    const int b = bn >> 4, n = bn & 15;

    __shared__ float qs[64][68];
    __shared__ float kvs[64][64];
    __shared__ float ksums[64];

    const int tid = threadIdx.x;

    float w0 = gw[0], w1 = gw[1], w2 = gw[2];
    float d0 = df[0], d1 = df[1], d2 = df[2];
    float mx = fmaxf(w0, fmaxf(w1, w2));
    float e0 = expf(w0 - mx), e1 = expf(w1 - mx), e2 = expf(w2 - mx);
    float s0f = 1.f / (1.f + expf(-d0));
    float s1f = 1.f / (1.f + expf(-d1));
    float s2f = 1.f / (1.f + expf(-d2));
    float coef = (e0 * (1.f - s0f) + e1 * (1.f - s1f) + e2 * (1.f - s2f)) / (e0 + e1 + e2);

    const long kvbase = (long)bn * 4096;
    for (int e = tid; e < 1024; e += 256)
        ((float4*)kvs)[e] = ((const float4*)(kv + kvbase))[e];
    if (tid < 64) ksums[tid] = ksum[bn * 64 + tid];

    const int srow0 = st * 64;
    for (int e = tid; e < 1024; e += 256) {
        int r = e >> 4, dd = (e & 15) * 4;
        long gq = (((long)(b * Ssz + srow0 + r) * Nh) + n) * Dh + dd;
        *(float4*)&qs[r][dd] = *(const float4*)&q[gq];
    }
    __syncthreads();

    const int sl = tid >> 2;
    const int jg = tid & 3;
    float acc[16];
#pragma unroll
    for (int j = 0; j < 16; j++) acc[j] = 0.f;
    float den = 0.f;

#pragma unroll 4
    for (int kk = 0; kk < 64; ++kk) {
        float qv = qs[sl][kk];
        den += qv * ksums[kk];
        const float4* kr = (const float4*)&kvs[kk][jg * 16];
        float4 c0 = kr[0], c1 = kr[1], c2 = kr[2], c3 = kr[3];
        acc[0]  += qv * c0.x; acc[1]  += qv * c0.y; acc[2]  += qv * c0.z; acc[3]  += qv * c0.w;
        acc[4]  += qv * c1.x; acc[5]  += qv * c1.y; acc[6]  += qv * c1.z; acc[7]  += qv * c1.w;
        acc[8]  += qv * c2.x; acc[9]  += qv * c2.y; acc[10] += qv * c2.z; acc[11] += qv * c2.w;
        acc[12] += qv * c3.x; acc[13] += qv * c3.y; acc[14] += qv * c3.z; acc[15] += qv * c3.w;
    }
    den += EPSF;

    const int srow = srow0 + sl;
    const float g = gate[b * Ssz + srow];
    const float fac = g / den + (1.f - g) * coef;

    const long obase = (((long)(b * Ssz + srow) * Nh) + n) * Dh + jg * 16;
#pragma unroll
    for (int u = 0; u < 4; u++) {
        unsigned short hs[4], ls[4];
#pragma unroll
        for (int e = 0; e < 4; e++) {
            float val = acc[u * 4 + e] * fac;
            __nv_bfloat16 h = __float2bfloat16(val);
            float r = val - __bfloat162float(h);
            __nv_bfloat16 l = __float2bfloat16(r);
            hs[e] = *(unsigned short*)&h;
            ls[e] = *(unsigned short*)&l;
        }
        uint2 H, L;
        H.x = (uint32_t)hs[0] | ((uint32_t)hs[1] << 16);
        H.y = (uint32_t)hs[2] | ((uint32_t)hs[3] << 16);
        L.x = (uint32_t)ls[0] | ((uint32_t)ls[1] << 16);
        L.y = (uint32_t)ls[2] | ((uint32_t)ls[3] << 16);
        *(uint2*)(ch + obase + u * 4) = H;
        *(uint2*)(cl + obase + u * 4) = L;
    }
}

// ================= host: tensormap construction ============================
typedef CUresult (*PFN_encodeTiled)(
    CUtensorMap*, CUtensorMapDataType, cuuint32_t, void*,
    const cuuint64_t*, const cuuint64_t*, const cuuint32_t*, const cuuint32_t*,
    CUtensorMapInterleave, CUtensorMapSwizzle, CUtensorMapL2promotion,
    CUtensorMapFloatOOBfill);

static PFN_encodeTiled get_encoder() {
    static PFN_encodeTiled fn = nullptr;
    if (!fn) {
        void* p = nullptr;
        cudaDriverEntryPointQueryResult st;
        cudaGetDriverEntryPointByVersion("cuTensorMapEncodeTiled", &p, 12000,
                                         cudaEnableDefault, &st);
        fn = (PFN_encodeTiled)p;
    }
    return fn;
}

static void make_map(CUtensorMap* m, void* base, uint64_t rows) {
    cuuint64_t dims[2]    = {1024, rows};
    cuuint64_t strides[1] = {2048};          // row pitch bytes
    cuuint32_t box[2]     = {32, 128};       // 64B x 128 rows
    cuuint32_t es[2]      = {1, 1};
    get_encoder()(m, CU_TENSOR_MAP_DATA_TYPE_BFLOAT16, 2, base, dims, strides,
                  box, es, CU_TENSOR_MAP_INTERLEAVE_NONE,
                  CU_TENSOR_MAP_SWIZZLE_64B, CU_TENSOR_MAP_L2_PROMOTION_L2_128B,
                  CU_TENSOR_MAP_FLOAT_OOB_FILL_NONE);
}

// ---------------------------------------------------------------------------
extern "C" void kernel_launch(void* const* d_in, const int* in_sizes, int n_in,
                              void* d_out, int out_size)
{
    const float* x    = (const float*)d_in[0];
    const float* mask = (const float*)d_in[1];
    const float* Wq   = (const float*)d_in[2];
    const float* bq   = (const float*)d_in[3];
    const float* Wk   = (const float*)d_in[4];
    const float* bk   = (const float*)d_in[5];
    const float* Wv   = (const float*)d_in[6];
    const float* bv   = (const float*)d_in[7];
    const float* Wo   = (const float*)d_in[8];
    const float* bo   = (const float*)d_in[9];
    const float* Wg   = (const float*)d_in[10];
    const float* bg   = (const float*)d_in[11];
    const float* df   = (const float*)d_in[12];
    const float* gw   = (const float*)d_in[13];
    float* out = (float*)d_out;

    float *q, *k, *v, *kvp, *kv, *ksp, *ks, *gate;
    __nv_bfloat16 *ah, *al, *bqh, *bql, *bkh, *bkl, *bvh, *bvl, *boh, *bol;
    cudaGetSymbolAddress((void**)&q,    g_q);
    cudaGetSymbolAddress((void**)&k,    g_k);
    cudaGetSymbolAddress((void**)&v,    g_v);
    cudaGetSymbolAddress((void**)&kvp,  g_kv_part);
    cudaGetSymbolAddress((void**)&kv,   g_kv);
    cudaGetSymbolAddress((void**)&ksp,  g_ksum_part);
    cudaGetSymbolAddress((void**)&ks,   g_ksum);
    cudaGetSymbolAddress((void**)&gate, g_gate);
    cudaGetSymbolAddress((void**)&ah,   g_ah);
    cudaGetSymbolAddress((void**)&al,   g_al);
    cudaGetSymbolAddress((void**)&bqh,  g_bqh);
    cudaGetSymbolAddress((void**)&bql,  g_bql);
    cudaGetSymbolAddress((void**)&bkh,  g_bkh);
    cudaGetSymbolAddress((void**)&bkl,  g_bkl);
    cudaGetSymbolAddress((void**)&bvh,  g_bvh);
    cudaGetSymbolAddress((void**)&bvl,  g_bvl);
    cudaGetSymbolAddress((void**)&boh,  g_boh);
    cudaGetSymbolAddress((void**)&bol,  g_bol);

    // tensormaps (host-side, deterministic; params baked at graph capture)
    CUtensorMap mAh, mAl, mQh, mQl, mKh, mKl, mVh, mVl, mOh, mOl;
    make_map(&mAh, ah, Msz);  make_map(&mAl, al, Msz);
    make_map(&mQh, bqh, Hsz); make_map(&mQl, bql, Hsz);
    make_map(&mKh, bkh, Hsz); make_map(&mKl, bkl, Hsz);
    make_map(&mVh, bvh, Hsz); make_map(&mVl, bvl, Hsz);
    make_map(&mOh, boh, Hsz); make_map(&mOl, bol, Hsz);

    cudaFuncSetAttribute(gemm_tma_bf16x3,
                         cudaFuncAttributeMaxDynamicSharedMemorySize, GEMM_SMEM);

    dim3 wblk(32, 8);
    dim3 wgrd(32, 32);

    // split activations + weights to bf16 hi/lo
    cvt_split<<<Msz * Hsz / 1024, 256>>>((const float4*)x, (uint2*)ah, (uint2*)al);
    cvt_w<<<wgrd, wblk>>>(Wq, bqh, bql);
    cvt_w<<<wgrd, wblk>>>(Wk, bkh, bkl);
    cvt_w<<<wgrd, wblk>>>(Wv, bvh, bvl);
    cvt_w<<<wgrd, wblk>>>(Wo, boh, bol);

    // fused QKV projection (grid.z selects weight/bias/output)
    gemm_tma_bf16x3<<<dim3(8, 64, 3), 256, GEMM_SMEM>>>(
        mAh, mAl, mQh, mQl, mKh, mKl, mVh, mVl, bq, bk, bv, q, k, v);

    gate_kernel<<<Msz, 256>>>(x, Wg, bg, gate);

    rope_map_kernel<<<(Bsz * Ssz * Nh * 32) / 256, 256>>>(mask, q, k, v);

    kv_partial_kernel<<<dim3(64, 8), 256>>>(k, v, kvp, ksp);
    kv_reduce_kernel<<<64, 256>>>(kvp, ksp, kv, ks);

    // combine writes bf16 hi/lo directly into ah/al for the output GEMM
    combine_kernel<<<dim3(64, Ssz / 64), 256>>>(q, kv, ks, gate, df, gw, ah, al);

    gemm_tma_bf16x3<<<dim3(8, 64, 1), 256, GEMM_SMEM>>>(
        mAh, mAl, mOh, mOl, mOh, mOl, mOh, mOl, bo, bo, bo, out, out, out);
}

// round 5
// speedup vs baseline: 2.6367x; 1.1892x over previous
#include <cuda_runtime.h>
#include <cuda.h>
#include <cuda_bf16.h>
#include <math.h>
#include <stdint.h>

// Problem constants
#define Bsz 4
#define Ssz 2048
#define Hsz 1024
#define Nh  16
#define Dh  64
#define Msz (Bsz*Ssz)      // 8192
#define EPSF 1e-6f

// ---------------- scratch (static device globals; no allocs allowed) -------
__device__ float g_q[Msz*Hsz];
__device__ float g_k[Msz*Hsz];
__device__ float g_v[Msz*Hsz];
__device__ float g_kv_part[8*64*64*64];
__device__ float g_kv[64*64*64];
__device__ float g_ksum_part[8*64*64];
__device__ float g_ksum[64*64];
__device__ float g_gate[Msz];
__device__ float2 g_rope[Ssz*32];         // (cos, sin) per (s, i)
// bf16x3 operands
__device__ __nv_bfloat16 g_ah[Msz*Hsz];   // activation hi
__device__ __nv_bfloat16 g_al[Msz*Hsz];   // activation lo
__device__ __nv_bfloat16 g_bqh[Hsz*Hsz], g_bql[Hsz*Hsz];
__device__ __nv_bfloat16 g_bkh[Hsz*Hsz], g_bkl[Hsz*Hsz];
__device__ __nv_bfloat16 g_bvh[Hsz*Hsz], g_bvl[Hsz*Hsz];
__device__ __nv_bfloat16 g_boh[Hsz*Hsz], g_bol[Hsz*Hsz];

// ================= low-level helpers =======================================
static __device__ __forceinline__ uint32_t s2u(const void* p) {
    uint32_t a;
    asm("{ .reg .u64 t; cvta.to.shared.u64 t, %1; cvt.u32.u64 %0, t; }"
        : "=r"(a) : "l"(p));
    return a;
}

static __device__ __forceinline__ void ldsm4(uint32_t* r, uint32_t addr) {
    asm volatile("ldmatrix.sync.aligned.m8n8.x4.shared.b16 {%0,%1,%2,%3}, [%4];"
                 : "=r"(r[0]), "=r"(r[1]), "=r"(r[2]), "=r"(r[3]) : "r"(addr));
}

static __device__ __forceinline__ void mma16816(float* d, const uint32_t* a,
                                                const uint32_t* b) {
    asm volatile(
        "mma.sync.aligned.m16n8k16.row.col.f32.bf16.bf16.f32 "
        "{%0,%1,%2,%3}, {%4,%5,%6,%7}, {%8,%9}, {%0,%1,%2,%3};"
        : "+f"(d[0]), "+f"(d[1]), "+f"(d[2]), "+f"(d[3])
        : "r"(a[0]), "r"(a[1]), "r"(a[2]), "r"(a[3]), "r"(b[0]), "r"(b[1]));
}

// smem tile: [128 rows][32 bf16 = 64B], SW64 swizzle: chunk16 ^= (row>>1)&3
static __device__ __forceinline__ uint32_t swoff(int row, int c16) {
    return (uint32_t)(row * 64 + ((c16 ^ ((row >> 1) & 3)) << 4));
}

#define MBAR_INIT(m, c) \
    asm volatile("mbarrier.init.shared.b64 [%0], %1;" \
                 :: "r"((uint32_t)(m)), "r"((uint32_t)(c)) : "memory")
#define MBAR_EXPECT(m, b) \
    asm volatile("mbarrier.arrive.expect_tx.shared.b64 _, [%0], %1;" \
                 :: "r"((uint32_t)(m)), "r"((uint32_t)(b)) : "memory")

static __device__ __forceinline__ void mbar_wait(uint32_t mbar, uint32_t parity) {
    asm volatile(
        "{\n\t.reg .pred P;\n\t"
        "WL_%=:\n\t"
        "mbarrier.try_wait.parity.acquire.cta.shared::cta.b64 P, [%0], %1, 0x989680;\n\t"
        "@P bra.uni WD_%=;\n\t"
        "bra.uni WL_%=;\n\t"
        "WD_%=:\n\t}"
        :: "r"(mbar), "r"(parity) : "memory");
}

#define TMA2D(sa, mp, cx, cy, mb) \
    asm volatile("cp.async.bulk.tensor.2d.shared::cta.global.tile.mbarrier::complete_tx::bytes " \
                 "[%0], [%1, {%2, %3}], [%4];" \
                 :: "r"((uint32_t)(sa)), "l"(mp), "r"((int)(cx)), "r"((int)(cy)), \
                    "r"((uint32_t)(mb)) : "memory")

__device__ __forceinline__ float phi_fn(float x) {
    float t = (x > 0.f) ? x : expm1f(x);
    return (t + 1.0f) + EPSF;
}

// ================= bf16x3 mma.sync + TMA GEMM ==============================
// CTA 128x128, BK=32, 32 K-chunks, 3 products/chunk (AhBh + AhBl + AlBh).
// Stage = 32KB (Ah 8K | Al 8K | Bh 8K | Bl 8K), 3 stages, TMA + mbarrier.
// epi_mode 0: fused QKV epilogue (z: 0=q rope+phi*0.125, 1=k rope+phi*mask,
//             2=v mask). epi_mode 1: plain bias+store.
#define NCHUNK 32
#define STAGE_BYTES 32768
#define GEMM_SMEM (3 * STAGE_BYTES + 64)

__global__ __launch_bounds__(256, 2)
void gemm_tma_bf16x3(const __grid_constant__ CUtensorMap mAh,
                     const __grid_constant__ CUtensorMap mAl,
                     const __grid_constant__ CUtensorMap mB0h,
                     const __grid_constant__ CUtensorMap mB0l,
                     const __grid_constant__ CUtensorMap mB1h,
                     const __grid_constant__ CUtensorMap mB1l,
                     const __grid_constant__ CUtensorMap mB2h,
                     const __grid_constant__ CUtensorMap mB2l,
                     const float* __restrict__ b0, const float* __restrict__ b1,
                     const float* __restrict__ b2,
                     float* __restrict__ C0, float* __restrict__ C1,
                     float* __restrict__ C2,
                     const float* __restrict__ maskp,
                     const float2* __restrict__ tab,
                     int epi_mode)
{
    extern __shared__ __align__(1024) char smem[];
    const uint32_t sbase = s2u(smem);
    const uint32_t mbb = sbase + 3 * STAGE_BYTES;
    const int tid = threadIdx.x;
    const int lane = tid & 31, wid = tid >> 5;
    const int wm = wid & 3, wn = wid >> 2;
    const int n0 = blockIdx.x * 128, m0 = blockIdx.y * 128;
    const int z = blockIdx.z;

    const CUtensorMap* pBh = (z == 0) ? &mB0h : (z == 1) ? &mB1h : &mB2h;
    const CUtensorMap* pBl = (z == 0) ? &mB0l : (z == 1) ? &mB1l : &mB2l;
    const float* bias = (z == 0) ? b0 : (z == 1) ? b1 : b2;
    float* C = (z == 0) ? C0 : (z == 1) ? C1 : C2;

    const int a_row  = wm * 32 + (lane & 15);
    const int a_c16h = lane >> 4;
    const int b_row  = wn * 64 + ((lane >> 4) << 3) + (lane & 7);
    const int b_c16h = (lane >> 3) & 1;

    float acc[2][8][4];
#pragma unroll
    for (int mi = 0; mi < 2; mi++)
#pragma unroll
        for (int ni = 0; ni < 8; ni++)
#pragma unroll
            for (int u = 0; u < 4; u++) acc[mi][ni][u] = 0.f;

    if (tid == 0) {
        MBAR_INIT(mbb + 0, 1);
        MBAR_INIT(mbb + 8, 1);
        MBAR_INIT(mbb + 16, 1);
    }
    __syncthreads();

    if (tid == 0) {
#pragma unroll
        for (int s = 0; s < 3; s++) {
            const uint32_t db = sbase + s * STAGE_BYTES;
            MBAR_EXPECT(mbb + s * 8, STAGE_BYTES);
            TMA2D(db,         &mAh, s * 32, m0, mbb + s * 8);
            TMA2D(db + 8192,  &mAl, s * 32, m0, mbb + s * 8);
            TMA2D(db + 16384, pBh,  s * 32, n0, mbb + s * 8);
            TMA2D(db + 24576, pBl,  s * 32, n0, mbb + s * 8);
        }
    }

    for (int it = 0; it < NCHUNK; it++) {
        const int s = it % 3;
        mbar_wait(mbb + s * 8, (it / 3) & 1);

        const uint32_t base = sbase + s * STAGE_BYTES;
#pragma unroll
        for (int ks = 0; ks < 2; ks++) {
            uint32_t aH[2][4], aL[2][4];
            ldsm4(aH[0], base +        swoff(a_row,      ks * 2 + a_c16h));
            ldsm4(aH[1], base +        swoff(a_row + 16, ks * 2 + a_c16h));
            ldsm4(aL[0], base + 8192 + swoff(a_row,      ks * 2 + a_c16h));
            ldsm4(aL[1], base + 8192 + swoff(a_row + 16, ks * 2 + a_c16h));
#pragma unroll
            for (int np = 0; np < 2; np++) {
                const int j0 = np * 4;
                uint32_t bH0[4], bH1[4], bL0[4], bL1[4];
                ldsm4(bH0, base + 16384 + swoff(b_row + (2*np)   * 16, ks * 2 + b_c16h));
                ldsm4(bH1, base + 16384 + swoff(b_row + (2*np+1) * 16, ks * 2 + b_c16h));
                // phase HH — 8 distinct accumulators
                mma16816(acc[0][j0+0], aH[0], bH0 + 0);
                mma16816(acc[0][j0+1], aH[0], bH0 + 2);
                mma16816(acc[0][j0+2], aH[0], bH1 + 0);
                mma16816(acc[0][j0+3], aH[0], bH1 + 2);
                mma16816(acc[1][j0+0], aH[1], bH0 + 0);
                mma16816(acc[1][j0+1], aH[1], bH0 + 2);
                mma16816(acc[1][j0+2], aH[1], bH1 + 0);
                mma16816(acc[1][j0+3], aH[1], bH1 + 2);
                // start bL loads (independent), then phase LH reusing bH
                ldsm4(bL0, base + 24576 + swoff(b_row + (2*np)   * 16, ks * 2 + b_c16h));
                ldsm4(bL1, base + 24576 + swoff(b_row + (2*np+1) * 16, ks * 2 + b_c16h));
                mma16816(acc[0][j0+0], aL[0], bH0 + 0);
                mma16816(acc[0][j0+1], aL[0], bH0 + 2);
                mma16816(acc[0][j0+2], aL[0], bH1 + 0);
                mma16816(acc[0][j0+3], aL[0], bH1 + 2);
                mma16816(acc[1][j0+0], aL[1], bH0 + 0);
                mma16816(acc[1][j0+1], aL[1], bH0 + 2);
                mma16816(acc[1][j0+2], aL[1], bH1 + 0);
                mma16816(acc[1][j0+3], aL[1], bH1 + 2);
                // phase HL
                mma16816(acc[0][j0+0], aH[0], bL0 + 0);
                mma16816(acc[0][j0+1], aH[0], bL0 + 2);
                mma16816(acc[0][j0+2], aH[0], bL1 + 0);
                mma16816(acc[0][j0+3], aH[0], bL1 + 2);
                mma16816(acc[1][j0+0], aH[1], bL0 + 0);
                mma16816(acc[1][j0+1], aH[1], bL0 + 2);
                mma16816(acc[1][j0+2], aH[1], bL1 + 0);
                mma16816(acc[1][j0+3], aH[1], bL1 + 2);
            }
        }
        __syncthreads();

        const int nc = it + 3;
        if (nc < NCHUNK && tid == 0) {
            const uint32_t db = sbase + s * STAGE_BYTES;
            MBAR_EXPECT(mbb + s * 8, STAGE_BYTES);
            TMA2D(db,         &mAh, nc * 32, m0, mbb + s * 8);
            TMA2D(db + 8192,  &mAl, nc * 32, m0, mbb + s * 8);
            TMA2D(db + 16384, pBh,  nc * 32, n0, mbb + s * 8);
            TMA2D(db + 24576, pBl,  nc * 32, n0, mbb + s * 8);
        }
    }

    // ---------------- epilogue ----------------
    const int r0 = m0 + wm * 32 + (lane >> 2);
    const int nb0 = n0 + wn * 64 + 2 * (lane & 3);

    if (epi_mode == 1) {
#pragma unroll
        for (int mi = 0; mi < 2; mi++) {
#pragma unroll
            for (int ni = 0; ni < 8; ni++) {
                const int r = r0 + mi * 16;
                const int c = nb0 + ni * 8;
                float2 bb = *(const float2*)(bias + c);
                *(float2*)(C + (long)r * 1024 + c) =
                    make_float2(acc[mi][ni][0] + bb.x, acc[mi][ni][1] + bb.y);
                *(float2*)(C + (long)(r + 8) * 1024 + c) =
                    make_float2(acc[mi][ni][2] + bb.x, acc[mi][ni][3] + bb.y);
            }
        }
        return;
    }

    // fused QKV epilogue
#pragma unroll
    for (int mi = 0; mi < 2; mi++) {
#pragma unroll
        for (int uu = 0; uu < 4; uu += 2) {
            const int r = r0 + mi * 16 + (uu ? 8 : 0);
            const int srow = r & (Ssz - 1);
            const float msk = maskp[r];
            if (z == 2) {
#pragma unroll
                for (int ni = 0; ni < 8; ni++) {
                    const int c = nb0 + ni * 8;
                    float v0 = (acc[mi][ni][uu+0] + bias[c])     * msk;
                    float v1 = (acc[mi][ni][uu+1] + bias[c + 1]) * msk;
                    *(float2*)(C + (long)r * 1024 + c) = make_float2(v0, v1);
                }
            } else {
                const float scale = (z == 0) ? 0.125f : msk;
#pragma unroll
                for (int ni = 0; ni < 4; ni++) {
                    float o1[2], o2[2];
#pragma unroll
                    for (int e = 0; e < 2; e++) {
                        const int i = 2 * (lane & 3) + ni * 8 + e;
                        const int c = nb0 + ni * 8 + e;
                        float x1 = acc[mi][ni][uu + e]     + bias[c];
                        float x2 = acc[mi][ni + 4][uu + e] + bias[c + 32];
                        float2 cs = tab[srow * 32 + i];
                        float r1 = x1 * cs.x - x2 * cs.y;
                        float r2 = x2 * cs.x + x1 * cs.y;
                        o1[e] = phi_fn(r1) * scale;
                        o2[e] = phi_fn(r2) * scale;
                    }
                    const int c = nb0 + ni * 8;
                    *(float2*)(C + (long)r * 1024 + c)      = make_float2(o1[0], o1[1]);
                    *(float2*)(C + (long)r * 1024 + c + 32) = make_float2(o2[0], o2[1]);
                }
            }
        }
    }
}

// ================= rope table ==============================================
__global__ void rope_table_kernel(float2* __restrict__ tab)
{
    const int idx = blockIdx.x * 256 + threadIdx.x;   // 65536
    const int i = idx & 31, s = idx >> 5;
    double p = pow(10000.0, (double)(2 * i) / 64.0);
    float f = (float)s * (1.0f / (float)p);
    tab[idx] = make_float2(cosf(f), sinf(f));
}

// ============ cvt x -> bf16 hi/lo + gate (one block per row) ===============
__global__ void cvt_x_gate(const float4* __restrict__ x,
                           const float4* __restrict__ Wg,
                           const float* __restrict__ bg,
                           uint2* __restrict__ hi, uint2* __restrict__ lo,
                           float* __restrict__ gout)
{
    const int row = blockIdx.x;
    const int tid = threadIdx.x;
    const long i = (long)row * 256 + tid;
    float4 v = x[i];
    float4 w = Wg[tid];
    float dot = v.x * w.x + v.y * w.y + v.z * w.z + v.w * w.w;

    float f[4] = {v.x, v.y, v.z, v.w};
    unsigned short hs[4], ls[4];
#pragma unroll
    for (int j = 0; j < 4; j++) {
        __nv_bfloat16 h = __float2bfloat16(f[j]);
        float r = f[j] - __bfloat162float(h);
        __nv_bfloat16 l = __float2bfloat16(r);
        hs[j] = *(unsigned short*)&h;
        ls[j] = *(unsigned short*)&l;
    }
    uint2 H, L;
    H.x = (uint32_t)hs[0] | ((uint32_t)hs[1] << 16);
    H.y = (uint32_t)hs[2] | ((uint32_t)hs[3] << 16);
    L.x = (uint32_t)ls[0] | ((uint32_t)ls[1] << 16);
    L.y = (uint32_t)ls[2] | ((uint32_t)ls[3] << 16);
    hi[i] = H;
    lo[i] = L;

#pragma unroll
    for (int o = 16; o; o >>= 1) dot += __shfl_down_sync(0xffffffffu, dot, o);
    __shared__ float ws[8];
    if ((tid & 31) == 0) ws[tid >> 5] = dot;
    __syncthreads();
    if (tid == 0) {
        float t = 0.f;
#pragma unroll
        for (int j = 0; j < 8; j++) t += ws[j];
        t += bg[0];
        gout[row] = 1.f / (1.f + expf(-t));
    }
}

// W[K][N] fp32 -> transposed hi/lo bf16 [N][K]; z selects which W
__global__ void cvt_w4(const float* __restrict__ W0, const float* __restrict__ W1,
                       const float* __restrict__ W2, const float* __restrict__ W3,
                       __nv_bfloat16* __restrict__ h0, __nv_bfloat16* __restrict__ l0,
                       __nv_bfloat16* __restrict__ h1, __nv_bfloat16* __restrict__ l1,
                       __nv_bfloat16* __restrict__ h2, __nv_bfloat16* __restrict__ l2,
                       __nv_bfloat16* __restrict__ h3, __nv_bfloat16* __restrict__ l3)
{
    const int z = blockIdx.z;
    const float* W = (z == 0) ? W0 : (z == 1) ? W1 : (z == 2) ? W2 : W3;
    __nv_bfloat16* bh = (z == 0) ? h0 : (z == 1) ? h1 : (z == 2) ? h2 : h3;
    __nv_bfloat16* bl = (z == 0) ? l0 : (z == 1) ? l1 : (z == 2) ? l2 : l3;

    __shared__ float t[32][33];
    const int nx = blockIdx.x * 32, kx = blockIdx.y * 32;
    const int tx = threadIdx.x, ty = threadIdx.y;   // 32 x 8
#pragma unroll
    for (int r = 0; r < 32; r += 8)
        t[ty + r][tx] = W[(long)(kx + ty + r) * 1024 + nx + tx];
    __syncthreads();
#pragma unroll
    for (int r = 0; r < 32; r += 8) {
        float v = t[tx][ty + r];
        __nv_bfloat16 h = __float2bfloat16(v);
        float rr = v - __bfloat162float(h);
        __nv_bfloat16 l = __float2bfloat16(rr);
        long o = (long)(nx + ty + r) * 1024 + kx + tx;
        bh[o] = h;
        bl[o] = l;
    }
}

// ---------------- kv partial: per (b,n,chunk) 64x64 outer-product sum ------
__global__ void kv_partial_kernel(const float* __restrict__ k,
                                  const float* __restrict__ v,
                                  float* __restrict__ kv_part,
                                  float* __restrict__ ksum_part)
{
    const int bn = blockIdx.x;
    const int c  = blockIdx.y;
    const int b = bn >> 4, n = bn & 15;
    __shared__ float ks[32][64];
    __shared__ float vs[32][64];
    const int tid = threadIdx.x;
    const int ti = tid >> 4, tj = tid & 15;

    float acc[4][4];
#pragma unroll
    for (int a = 0; a < 4; a++)
#pragma unroll
        for (int d = 0; d < 4; d++) acc[a][d] = 0.f;
    float ksum = 0.f;

    const int s0 = c * 256;
    for (int so = 0; so < 256; so += 32) {
#pragma unroll
        for (int e = tid; e < 512; e += 256) {
            int sl = e >> 4, dd = (e & 15) * 4;
            long gb = (((long)(b * Ssz + s0 + so + sl) * Nh) + n) * Dh + dd;
            *(float4*)&ks[sl][dd] = *(const float4*)&k[gb];
            *(float4*)&vs[sl][dd] = *(const float4*)&v[gb];
        }
        __syncthreads();
#pragma unroll 4
        for (int sl = 0; sl < 32; ++sl) {
            float4 kk4 = *(const float4*)&ks[sl][ti * 4];
            float4 vv4 = *(const float4*)&vs[sl][tj * 4];
            float ka[4] = {kk4.x, kk4.y, kk4.z, kk4.w};
            float va[4] = {vv4.x, vv4.y, vv4.z, vv4.w};
#pragma unroll
            for (int a = 0; a < 4; a++)
#pragma unroll
                for (int d = 0; d < 4; d++) acc[a][d] += ka[a] * va[d];
        }
        if (tid < 64) {
#pragma unroll 4
            for (int sl = 0; sl < 32; ++sl) ksum += ks[sl][tid];
        }
        __syncthreads();
    }

    const long pbase = ((long)c * 64 + bn) * 4096;
#pragma unroll
    for (int a = 0; a < 4; a++) {
        float4 o = make_float4(acc[a][0], acc[a][1], acc[a][2], acc[a][3]);
        *(float4*)&kv_part[pbase + (ti * 4 + a) * 64 + tj * 4] = o;
    }
    if (tid < 64) ksum_part[(c * 64 + bn) * 64 + tid] = ksum;
}

__global__ void kv_reduce_kernel(const float* __restrict__ kv_part,
                                 const float* __restrict__ ksum_part,
                                 float* __restrict__ kv,
                                 float* __restrict__ ksum)
{
    const int bn = blockIdx.x;
    const int tid = threadIdx.x;
    for (int e = tid; e < 4096; e += 256) {
        float s = 0.f;
#pragma unroll
        for (int c = 0; c < 8; ++c) s += kv_part[((long)c * 64 + bn) * 4096 + e];
        kv[(long)bn * 4096 + e] = s;
    }
    if (tid < 64) {
        float s = 0.f;
#pragma unroll
        for (int c = 0; c < 8; ++c) s += ksum_part[(c * 64 + bn) * 64 + tid];
        ksum[bn * 64 + tid] = s;
    }
}

// ---- combine: num=q@kv; den=q.ksum+eps; gate mix; write bf16 hi/lo --------
__global__ void combine_kernel(const float* __restrict__ q,
                               const float* __restrict__ kv,
                               const float* __restrict__ ksum,
                               const float* __restrict__ gate,
                               const float* __restrict__ df,
                               const float* __restrict__ gw,
                               __nv_bfloat16* __restrict__ ch,
                               __nv_bfloat16* __restrict__ cl)
{
    const int bn = blockIdx.x;
    const int st = blockIdx.y;
    const int b = bn >> 4, n = bn & 15;

    __shared__ float qs[64][68];
    __shared__ float kvs[64][64];
    __shared__ float ksums[64];

    const int tid = threadIdx.x;

    float w0 = gw[0], w1 = gw[1], w2 = gw[2];
    float d0 = df[0], d1 = df[1], d2 = df[2];
    float mx = fmaxf(w0, fmaxf(w1, w2));
    float e0 = expf(w0 - mx), e1 = expf(w1 - mx), e2 = expf(w2 - mx);
    float s0f = 1.f / (1.f + expf(-d0));
    float s1f = 1.f / (1.f + expf(-d1));
    float s2f = 1.f / (1.f + expf(-d2));
    float coef = (e0 * (1.f - s0f) + e1 * (1.f - s1f) + e2 * (1.f - s2f)) / (e0 + e1 + e2);

    const long kvbase = (long)bn * 4096;
    for (int e = tid; e < 1024; e += 256)
        ((float4*)kvs)[e] = ((const float4*)(kv + kvbase))[e];
    if (tid < 64) ksums[tid] = ksum[bn * 64 + tid];

    const int srow0 = st * 64;
    for (int e = tid; e < 1024; e += 256) {
        int r = e >> 4, dd = (e & 15) * 4;
        long gq = (((long)(b * Ssz + srow0 + r) * Nh) + n) * Dh + dd;
        *(float4*)&qs[r][dd] = *(const float4*)&q[gq];
    }
    __syncthreads();

    const int sl = tid >> 2;
    const int jg = tid & 3;
    float acc[16];
#pragma unroll
    for (int j = 0; j < 16; j++) acc[j] = 0.f;
    float den = 0.f;

#pragma unroll 4
    for (int kk = 0; kk < 64; ++kk) {
        float qv = qs[sl][kk];
        den += qv * ksums[kk];
        const float4* kr = (const float4*)&kvs[kk][jg * 16];
        float4 c0 = kr[0], c1 = kr[1], c2 = kr[2], c3 = kr[3];
        acc[0]  += qv * c0.x; acc[1]  += qv * c0.y; acc[2]  += qv * c0.z; acc[3]  += qv * c0.w;
        acc[4]  += qv * c1.x; acc[5]  += qv * c1.y; acc[6]  += qv * c1.z; acc[7]  += qv * c1.w;
        acc[8]  += qv * c2.x; acc[9]  += qv * c2.y; acc[10] += qv * c2.z; acc[11] += qv * c2.w;
        acc[12] += qv * c3.x; acc[13] += qv * c3.y; acc[14] += qv * c3.z; acc[15] += qv * c3.w;
    }
    den += EPSF;

    const int srow = srow0 + sl;
    const float g = gate[b * Ssz + srow];
    const float fac = g / den + (1.f - g) * coef;

    const long obase = (((long)(b * Ssz + srow) * Nh) + n) * Dh + jg * 16;
#pragma unroll
    for (int u = 0; u < 4; u++) {
        unsigned short hs[4], ls[4];
#pragma unroll
        for (int e = 0; e < 4; e++) {
            float val = acc[u * 4 + e] * fac;
            __nv_bfloat16 h = __float2bfloat16(val);
            float r = val - __bfloat162float(h);
            __nv_bfloat16 l = __float2bfloat16(r);
            hs[e] = *(unsigned short*)&h;
            ls[e] = *(unsigned short*)&l;
        }
        uint2 H, L;
        H.x = (uint32_t)hs[0] | ((uint32_t)hs[1] << 16);
        H.y = (uint32_t)hs[2] | ((uint32_t)hs[3] << 16);
        L.x = (uint32_t)ls[0] | ((uint32_t)ls[1] << 16);
        L.y = (uint32_t)ls[2] | ((uint32_t)ls[3] << 16);
        *(uint2*)(ch + obase + u * 4) = H;
        *(uint2*)(cl + obase + u * 4) = L;
    }
}

// ================= host: tensormap construction ============================
typedef CUresult (*PFN_encodeTiled)(
    CUtensorMap*, CUtensorMapDataType, cuuint32_t, void*,
    const cuuint64_t*, const cuuint64_t*, const cuuint32_t*, const cuuint32_t*,
    CUtensorMapInterleave, CUtensorMapSwizzle, CUtensorMapL2promotion,
    CUtensorMapFloatOOBfill);

static PFN_encodeTiled get_encoder() {
    static PFN_encodeTiled fn = nullptr;
    if (!fn) {
        void* p = nullptr;
        cudaDriverEntryPointQueryResult st;
        cudaGetDriverEntryPointByVersion("cuTensorMapEncodeTiled", &p, 12000,
                                         cudaEnableDefault, &st);
        fn = (PFN_encodeTiled)p;
    }
    return fn;
}

static void make_map(CUtensorMap* m, void* base, uint64_t rows) {
    cuuint64_t dims[2]    = {1024, rows};
    cuuint64_t strides[1] = {2048};
    cuuint32_t box[2]     = {32, 128};
    cuuint32_t es[2]      = {1, 1};
    get_encoder()(m, CU_TENSOR_MAP_DATA_TYPE_BFLOAT16, 2, base, dims, strides,
                  box, es, CU_TENSOR_MAP_INTERLEAVE_NONE,
                  CU_TENSOR_MAP_SWIZZLE_64B, CU_TENSOR_MAP_L2_PROMOTION_L2_128B,
                  CU_TENSOR_MAP_FLOAT_OOB_FILL_NONE);
}

// ---------------------------------------------------------------------------
extern "C" void kernel_launch(void* const* d_in, const int* in_sizes, int n_in,
                              void* d_out, int out_size)
{
    const float* x    = (const float*)d_in[0];
    const float* mask = (const float*)d_in[1];
    const float* Wq   = (const float*)d_in[2];
    const float* bq   = (const float*)d_in[3];
    const float* Wk   = (const float*)d_in[4];
    const float* bk   = (const float*)d_in[5];
    const float* Wv   = (const float*)d_in[6];
    const float* bv   = (const float*)d_in[7];
    const float* Wo   = (const float*)d_in[8];
    const float* bo   = (const float*)d_in[9];
    const float* Wg   = (const float*)d_in[10];
    const float* bg   = (const float*)d_in[11];
    const float* df   = (const float*)d_in[12];
    const float* gw   = (const float*)d_in[13];
    float* out = (float*)d_out;

    float *q, *k, *v, *kvp, *kv, *ksp, *ks, *gate;
    float2* tab;
    __nv_bfloat16 *ah, *al, *bqh, *bql, *bkh, *bkl, *bvh, *bvl, *boh, *bol;
    cudaGetSymbolAddress((void**)&q,    g_q);
    cudaGetSymbolAddress((void**)&k,    g_k);
    cudaGetSymbolAddress((void**)&v,    g_v);
    cudaGetSymbolAddress((void**)&kvp,  g_kv_part);
    cudaGetSymbolAddress((void**)&kv,   g_kv);
    cudaGetSymbolAddress((void**)&ksp,  g_ksum_part);
    cudaGetSymbolAddress((void**)&ks,   g_ksum);
    cudaGetSymbolAddress((void**)&gate, g_gate);
    cudaGetSymbolAddress((void**)&tab,  g_rope);
    cudaGetSymbolAddress((void**)&ah,   g_ah);
    cudaGetSymbolAddress((void**)&al,   g_al);
    cudaGetSymbolAddress((void**)&bqh,  g_bqh);
    cudaGetSymbolAddress((void**)&bql,  g_bql);
    cudaGetSymbolAddress((void**)&bkh,  g_bkh);
    cudaGetSymbolAddress((void**)&bkl,  g_bkl);
    cudaGetSymbolAddress((void**)&bvh,  g_bvh);
    cudaGetSymbolAddress((void**)&bvl,  g_bvl);
    cudaGetSymbolAddress((void**)&boh,  g_boh);
    cudaGetSymbolAddress((void**)&bol,  g_bol);

    CUtensorMap mAh, mAl, mQh, mQl, mKh, mKl, mVh, mVl, mOh, mOl;
    make_map(&mAh, ah, Msz);  make_map(&mAl, al, Msz);
    make_map(&mQh, bqh, Hsz); make_map(&mQl, bql, Hsz);
    make_map(&mKh, bkh, Hsz); make_map(&mKl, bkl, Hsz);
    make_map(&mVh, bvh, Hsz); make_map(&mVl, bvl, Hsz);
    make_map(&mOh, boh, Hsz); make_map(&mOl, bol, Hsz);

    cudaFuncSetAttribute(gemm_tma_bf16x3,
                         cudaFuncAttributeMaxDynamicSharedMemorySize, GEMM_SMEM);

    // 1. rope table
    rope_table_kernel<<<Ssz * 32 / 256, 256>>>(tab);
    // 2. activation split + gate
    cvt_x_gate<<<Msz, 256>>>((const float4*)x, (const float4*)Wg, bg,
                             (uint2*)ah, (uint2*)al, gate);
    // 3. all four weight conversions in one launch
    cvt_w4<<<dim3(32, 32, 4), dim3(32, 8)>>>(Wq, Wk, Wv, Wo,
                                             bqh, bql, bkh, bkl,
                                             bvh, bvl, boh, bol);
    // 4. fused QKV projection + rope/phi/mask epilogue   (profiled launch)
    gemm_tma_bf16x3<<<dim3(8, 64, 3), 256, GEMM_SMEM>>>(
        mAh, mAl, mQh, mQl, mKh, mKl, mVh, mVl, bq, bk, bv, q, k, v,
        mask, tab, 0);
    // 5-6. kv aggregation
    kv_partial_kernel<<<dim3(64, 8), 256>>>(k, v, kvp, ksp);
    kv_reduce_kernel<<<64, 256>>>(kvp, ksp, kv, ks);
    // 7. combine writes bf16 hi/lo into ah/al
    combine_kernel<<<dim3(64, Ssz / 64), 256>>>(q, kv, ks, gate, df, gw, ah, al);
    // 8. output projection
    gemm_tma_bf16x3<<<dim3(8, 64, 1), 256, GEMM_SMEM>>>(
        mAh, mAl, mOh, mOl, mOh, mOl, mOh, mOl, bo, bo, bo, out, out, out,
        mask, tab, 1);
}

// round 6
// speedup vs baseline: 3.0729x; 1.1654x over previous
#include <cuda_runtime.h>
#include <cuda.h>
#include <cuda_bf16.h>
#include <cuda_fp16.h>
#include <math.h>
#include <stdint.h>

// Problem constants
#define Bsz 4
#define Ssz 2048
#define Hsz 1024
#define Nh  16
#define Dh  64
#define Msz (Bsz*Ssz)      // 8192
#define EPSF 1e-6f

// ---------------- scratch (static device globals; no allocs allowed) -------
__device__ float g_q[Msz*Hsz];
__device__ float g_k[Msz*Hsz];
__device__ float g_v[Msz*Hsz];
__device__ float g_kv_part[8*64*64*64];
__device__ float g_kv[64*64*64];
__device__ float g_ksum_part[8*64*64];
__device__ float g_ksum[64*64];
__device__ float g_gate[Msz];
__device__ float2 g_rope[Ssz*32];         // (cos, sin) per (s, i)
// 16-bit operand buffers. g_ah/g_al: QKV phase holds fp16 x (ah only);
// after combine they hold bf16 hi/lo of comb for the out-projection.
__device__ __nv_bfloat16 g_ah[Msz*Hsz];
__device__ __nv_bfloat16 g_al[Msz*Hsz];
__device__ __nv_bfloat16 g_bqh[Hsz*Hsz], g_bql[Hsz*Hsz];   // fp16 hi/lo
__device__ __nv_bfloat16 g_bkh[Hsz*Hsz], g_bkl[Hsz*Hsz];   // fp16 hi/lo
__device__ __nv_bfloat16 g_bvh[Hsz*Hsz], g_bvl[Hsz*Hsz];   // fp16 hi/lo
__device__ __nv_bfloat16 g_boh[Hsz*Hsz], g_bol[Hsz*Hsz];   // bf16 hi/lo

// ================= low-level helpers =======================================
static __device__ __forceinline__ uint32_t s2u(const void* p) {
    uint32_t a;
    asm("{ .reg .u64 t; cvta.to.shared.u64 t, %1; cvt.u32.u64 %0, t; }"
        : "=r"(a) : "l"(p));
    return a;
}

static __device__ __forceinline__ void ldsm4(uint32_t* r, uint32_t addr) {
    asm volatile("ldmatrix.sync.aligned.m8n8.x4.shared.b16 {%0,%1,%2,%3}, [%4];"
                 : "=r"(r[0]), "=r"(r[1]), "=r"(r[2]), "=r"(r[3]) : "r"(addr));
}

static __device__ __forceinline__ void mma16816(float* d, const uint32_t* a,
                                                const uint32_t* b) {
    asm volatile(
        "mma.sync.aligned.m16n8k16.row.col.f32.bf16.bf16.f32 "
        "{%0,%1,%2,%3}, {%4,%5,%6,%7}, {%8,%9}, {%0,%1,%2,%3};"
        : "+f"(d[0]), "+f"(d[1]), "+f"(d[2]), "+f"(d[3])
        : "r"(a[0]), "r"(a[1]), "r"(a[2]), "r"(a[3]), "r"(b[0]), "r"(b[1]));
}

static __device__ __forceinline__ void mma16816h(float* d, const uint32_t* a,
                                                 const uint32_t* b) {
    asm volatile(
        "mma.sync.aligned.m16n8k16.row.col.f32.f16.f16.f32 "
        "{%0,%1,%2,%3}, {%4,%5,%6,%7}, {%8,%9}, {%0,%1,%2,%3};"
        : "+f"(d[0]), "+f"(d[1]), "+f"(d[2]), "+f"(d[3])
        : "r"(a[0]), "r"(a[1]), "r"(a[2]), "r"(a[3]), "r"(b[0]), "r"(b[1]));
}

// smem tile: [128 rows][32 elems = 64B], SW64 swizzle: chunk16 ^= (row>>1)&3
static __device__ __forceinline__ uint32_t swoff(int row, int c16) {
    return (uint32_t)(row * 64 + ((c16 ^ ((row >> 1) & 3)) << 4));
}

#define MBAR_INIT(m, c) \
    asm volatile("mbarrier.init.shared.b64 [%0], %1;" \
                 :: "r"((uint32_t)(m)), "r"((uint32_t)(c)) : "memory")
#define MBAR_EXPECT(m, b) \
    asm volatile("mbarrier.arrive.expect_tx.shared.b64 _, [%0], %1;" \
                 :: "r"((uint32_t)(m)), "r"((uint32_t)(b)) : "memory")

static __device__ __forceinline__ void mbar_wait(uint32_t mbar, uint32_t parity) {
    asm volatile(
        "{\n\t.reg .pred P;\n\t"
        "WL_%=:\n\t"
        "mbarrier.try_wait.parity.acquire.cta.shared::cta.b64 P, [%0], %1, 0x989680;\n\t"
        "@P bra.uni WD_%=;\n\t"
        "bra.uni WL_%=;\n\t"
        "WD_%=:\n\t}"
        :: "r"(mbar), "r"(parity) : "memory");
}

#define TMA2D(sa, mp, cx, cy, mb) \
    asm volatile("cp.async.bulk.tensor.2d.shared::cta.global.tile.mbarrier::complete_tx::bytes " \
                 "[%0], [%1, {%2, %3}], [%4];" \
                 :: "r"((uint32_t)(sa)), "l"(mp), "r"((int)(cx)), "r"((int)(cy)), \
                    "r"((uint32_t)(mb)) : "memory")

__device__ __forceinline__ float phi_fn(float x) {
    float t = (x > 0.f) ? x : expm1f(x);
    return (t + 1.0f) + EPSF;
}

#define NCHUNK 32

// ================= fp16x2 QKV GEMM (A single fp16, B split hi/lo) ==========
// q/k/v[8192,1024] = Af @ (Bh+Bl)^T + bias, fused rope/phi/mask epilogue.
// Stage = 24KB (Af 8K | Bh 8K | Bl 8K), 4 stages.
#define STAGE_F16 24576
#define SMEM_F16 (4 * STAGE_F16 + 64)

__global__ __launch_bounds__(256, 2)
void gemm_qkv_f16x2(const __grid_constant__ CUtensorMap mAf,
                    const __grid_constant__ CUtensorMap mB0h,
                    const __grid_constant__ CUtensorMap mB0l,
                    const __grid_constant__ CUtensorMap mB1h,
                    const __grid_constant__ CUtensorMap mB1l,
                    const __grid_constant__ CUtensorMap mB2h,
                    const __grid_constant__ CUtensorMap mB2l,
                    const float* __restrict__ b0, const float* __restrict__ b1,
                    const float* __restrict__ b2,
                    float* __restrict__ C0, float* __restrict__ C1,
                    float* __restrict__ C2,
                    const float* __restrict__ maskp,
                    const float2* __restrict__ tab)
{
    extern __shared__ __align__(1024) char smem[];
    const uint32_t sbase = s2u(smem);
    const uint32_t mbb = sbase + 4 * STAGE_F16;
    const int tid = threadIdx.x;
    const int lane = tid & 31, wid = tid >> 5;
    const int wm = wid & 3, wn = wid >> 2;
    const int n0 = blockIdx.x * 128, m0 = blockIdx.y * 128;
    const int z = blockIdx.z;

    const CUtensorMap* pBh = (z == 0) ? &mB0h : (z == 1) ? &mB1h : &mB2h;
    const CUtensorMap* pBl = (z == 0) ? &mB0l : (z == 1) ? &mB1l : &mB2l;
    const float* bias = (z == 0) ? b0 : (z == 1) ? b1 : b2;
    float* C = (z == 0) ? C0 : (z == 1) ? C1 : C2;

    const int a_row  = wm * 32 + (lane & 15);
    const int a_c16h = lane >> 4;
    const int b_row  = wn * 64 + ((lane >> 4) << 3) + (lane & 7);
    const int b_c16h = (lane >> 3) & 1;

    float acc[2][8][4];
#pragma unroll
    for (int mi = 0; mi < 2; mi++)
#pragma unroll
        for (int ni = 0; ni < 8; ni++)
#pragma unroll
            for (int u = 0; u < 4; u++) acc[mi][ni][u] = 0.f;

    if (tid == 0) {
#pragma unroll
        for (int s = 0; s < 4; s++) MBAR_INIT(mbb + s * 8, 1);
    }
    __syncthreads();

    if (tid == 0) {
#pragma unroll
        for (int s = 0; s < 4; s++) {
            const uint32_t db = sbase + s * STAGE_F16;
            MBAR_EXPECT(mbb + s * 8, STAGE_F16);
            TMA2D(db,         &mAf, s * 32, m0, mbb + s * 8);
            TMA2D(db + 8192,  pBh,  s * 32, n0, mbb + s * 8);
            TMA2D(db + 16384, pBl,  s * 32, n0, mbb + s * 8);
        }
    }

    for (int it = 0; it < NCHUNK; it++) {
        const int s = it & 3;
        mbar_wait(mbb + s * 8, (it >> 2) & 1);

        const uint32_t base = sbase + s * STAGE_F16;
#pragma unroll
        for (int ks = 0; ks < 2; ks++) {
            uint32_t aF[2][4];
            ldsm4(aF[0], base + swoff(a_row,      ks * 2 + a_c16h));
            ldsm4(aF[1], base + swoff(a_row + 16, ks * 2 + a_c16h));
#pragma unroll
            for (int np = 0; np < 2; np++) {
                const int j0 = np * 4;
                uint32_t bH0[4], bH1[4], bL0[4], bL1[4];
                ldsm4(bH0, base + 8192 + swoff(b_row + (2*np)   * 16, ks * 2 + b_c16h));
                ldsm4(bH1, base + 8192 + swoff(b_row + (2*np+1) * 16, ks * 2 + b_c16h));
                mma16816h(acc[0][j0+0], aF[0], bH0 + 0);
                mma16816h(acc[0][j0+1], aF[0], bH0 + 2);
                mma16816h(acc[0][j0+2], aF[0], bH1 + 0);
                mma16816h(acc[0][j0+3], aF[0], bH1 + 2);
                mma16816h(acc[1][j0+0], aF[1], bH0 + 0);
                mma16816h(acc[1][j0+1], aF[1], bH0 + 2);
                mma16816h(acc[1][j0+2], aF[1], bH1 + 0);
                mma16816h(acc[1][j0+3], aF[1], bH1 + 2);
                ldsm4(bL0, base + 16384 + swoff(b_row + (2*np)   * 16, ks * 2 + b_c16h));
                ldsm4(bL1, base + 16384 + swoff(b_row + (2*np+1) * 16, ks * 2 + b_c16h));
                mma16816h(acc[0][j0+0], aF[0], bL0 + 0);
                mma16816h(acc[0][j0+1], aF[0], bL0 + 2);
                mma16816h(acc[0][j0+2], aF[0], bL1 + 0);
                mma16816h(acc[0][j0+3], aF[0], bL1 + 2);
                mma16816h(acc[1][j0+0], aF[1], bL0 + 0);
                mma16816h(acc[1][j0+1], aF[1], bL0 + 2);
                mma16816h(acc[1][j0+2], aF[1], bL1 + 0);
                mma16816h(acc[1][j0+3], aF[1], bL1 + 2);
            }
        }
        __syncthreads();

        const int nc = it + 4;
        if (nc < NCHUNK && tid == 0) {
            const uint32_t db = sbase + s * STAGE_F16;
            MBAR_EXPECT(mbb + s * 8, STAGE_F16);
            TMA2D(db,         &mAf, nc * 32, m0, mbb + s * 8);
            TMA2D(db + 8192,  pBh,  nc * 32, n0, mbb + s * 8);
            TMA2D(db + 16384, pBl,  nc * 32, n0, mbb + s * 8);
        }
    }

    // fused QKV epilogue (validated R5 layout)
    const int r0 = m0 + wm * 32 + (lane >> 2);
    const int nb0 = n0 + wn * 64 + 2 * (lane & 3);
#pragma unroll
    for (int mi = 0; mi < 2; mi++) {
#pragma unroll
        for (int uu = 0; uu < 4; uu += 2) {
            const int r = r0 + mi * 16 + (uu ? 8 : 0);
            const int srow = r & (Ssz - 1);
            const float msk = maskp[r];
            if (z == 2) {
#pragma unroll
                for (int ni = 0; ni < 8; ni++) {
                    const int c = nb0 + ni * 8;
                    float v0 = (acc[mi][ni][uu+0] + bias[c])     * msk;
                    float v1 = (acc[mi][ni][uu+1] + bias[c + 1]) * msk;
                    *(float2*)(C + (long)r * 1024 + c) = make_float2(v0, v1);
                }
            } else {
                const float scale = (z == 0) ? 0.125f : msk;
#pragma unroll
                for (int ni = 0; ni < 4; ni++) {
                    float o1[2], o2[2];
#pragma unroll
                    for (int e = 0; e < 2; e++) {
                        const int i = 2 * (lane & 3) + ni * 8 + e;
                        const int c = nb0 + ni * 8 + e;
                        float x1 = acc[mi][ni][uu + e]     + bias[c];
                        float x2 = acc[mi][ni + 4][uu + e] + bias[c + 32];
                        float2 cs = tab[srow * 32 + i];
                        float r1 = x1 * cs.x - x2 * cs.y;
                        float r2 = x2 * cs.x + x1 * cs.y;
                        o1[e] = phi_fn(r1) * scale;
                        o2[e] = phi_fn(r2) * scale;
                    }
                    const int c = nb0 + ni * 8;
                    *(float2*)(C + (long)r * 1024 + c)      = make_float2(o1[0], o1[1]);
                    *(float2*)(C + (long)r * 1024 + c + 32) = make_float2(o2[0], o2[1]);
                }
            }
        }
    }
}

// ================= bf16x3 out-projection GEMM (validated R5) ===============
#define STAGE_BYTES 32768
#define GEMM_SMEM (3 * STAGE_BYTES + 64)

__global__ __launch_bounds__(256, 2)
void gemm_out_bf16x3(const __grid_constant__ CUtensorMap mAh,
                     const __grid_constant__ CUtensorMap mAl,
                     const __grid_constant__ CUtensorMap mBh,
                     const __grid_constant__ CUtensorMap mBl,
                     const float* __restrict__ bias, float* __restrict__ C)
{
    extern __shared__ __align__(1024) char smem[];
    const uint32_t sbase = s2u(smem);
    const uint32_t mbb = sbase + 3 * STAGE_BYTES;
    const int tid = threadIdx.x;
    const int lane = tid & 31, wid = tid >> 5;
    const int wm = wid & 3, wn = wid >> 2;
    const int n0 = blockIdx.x * 128, m0 = blockIdx.y * 128;

    const int a_row  = wm * 32 + (lane & 15);
    const int a_c16h = lane >> 4;
    const int b_row  = wn * 64 + ((lane >> 4) << 3) + (lane & 7);
    const int b_c16h = (lane >> 3) & 1;

    float acc[2][8][4];
#pragma unroll
    for (int mi = 0; mi < 2; mi++)
#pragma unroll
        for (int ni = 0; ni < 8; ni++)
#pragma unroll
            for (int u = 0; u < 4; u++) acc[mi][ni][u] = 0.f;

    if (tid == 0) {
        MBAR_INIT(mbb + 0, 1);
        MBAR_INIT(mbb + 8, 1);
        MBAR_INIT(mbb + 16, 1);
    }
    __syncthreads();

    if (tid == 0) {
#pragma unroll
        for (int s = 0; s < 3; s++) {
            const uint32_t db = sbase + s * STAGE_BYTES;
            MBAR_EXPECT(mbb + s * 8, STAGE_BYTES);
            TMA2D(db,         &mAh, s * 32, m0, mbb + s * 8);
            TMA2D(db + 8192,  &mAl, s * 32, m0, mbb + s * 8);
            TMA2D(db + 16384, &mBh, s * 32, n0, mbb + s * 8);
            TMA2D(db + 24576, &mBl, s * 32, n0, mbb + s * 8);
        }
    }

    for (int it = 0; it < NCHUNK; it++) {
        const int s = it % 3;
        mbar_wait(mbb + s * 8, (it / 3) & 1);

        const uint32_t base = sbase + s * STAGE_BYTES;
#pragma unroll
        for (int ks = 0; ks < 2; ks++) {
            uint32_t aH[2][4], aL[2][4];
            ldsm4(aH[0], base +        swoff(a_row,      ks * 2 + a_c16h));
            ldsm4(aH[1], base +        swoff(a_row + 16, ks * 2 + a_c16h));
            ldsm4(aL[0], base + 8192 + swoff(a_row,      ks * 2 + a_c16h));
            ldsm4(aL[1], base + 8192 + swoff(a_row + 16, ks * 2 + a_c16h));
#pragma unroll
            for (int np = 0; np < 2; np++) {
                const int j0 = np * 4;
                uint32_t bH0[4], bH1[4], bL0[4], bL1[4];
                ldsm4(bH0, base + 16384 + swoff(b_row + (2*np)   * 16, ks * 2 + b_c16h));
                ldsm4(bH1, base + 16384 + swoff(b_row + (2*np+1) * 16, ks * 2 + b_c16h));
                mma16816(acc[0][j0+0], aH[0], bH0 + 0);
                mma16816(acc[0][j0+1], aH[0], bH0 + 2);
                mma16816(acc[0][j0+2], aH[0], bH1 + 0);
                mma16816(acc[0][j0+3], aH[0], bH1 + 2);
                mma16816(acc[1][j0+0], aH[1], bH0 + 0);
                mma16816(acc[1][j0+1], aH[1], bH0 + 2);
                mma16816(acc[1][j0+2], aH[1], bH1 + 0);
                mma16816(acc[1][j0+3], aH[1], bH1 + 2);
                ldsm4(bL0, base + 24576 + swoff(b_row + (2*np)   * 16, ks * 2 + b_c16h));
                ldsm4(bL1, base + 24576 + swoff(b_row + (2*np+1) * 16, ks * 2 + b_c16h));
                mma16816(acc[0][j0+0], aL[0], bH0 + 0);
                mma16816(acc[0][j0+1], aL[0], bH0 + 2);
                mma16816(acc[0][j0+2], aL[0], bH1 + 0);
                mma16816(acc[0][j0+3], aL[0], bH1 + 2);
                mma16816(acc[1][j0+0], aL[1], bH0 + 0);
                mma16816(acc[1][j0+1], aL[1], bH0 + 2);
                mma16816(acc[1][j0+2], aL[1], bH1 + 0);
                mma16816(acc[1][j0+3], aL[1], bH1 + 2);
                mma16816(acc[0][j0+0], aH[0], bL0 + 0);
                mma16816(acc[0][j0+1], aH[0], bL0 + 2);
                mma16816(acc[0][j0+2], aH[0], bL1 + 0);
                mma16816(acc[0][j0+3], aH[0], bL1 + 2);
                mma16816(acc[1][j0+0], aH[1], bL0 + 0);
                mma16816(acc[1][j0+1], aH[1], bL0 + 2);
                mma16816(acc[1][j0+2], aH[1], bL1 + 0);
                mma16816(acc[1][j0+3], aH[1], bL1 + 2);
            }
        }
        __syncthreads();

        const int nc = it + 3;
        if (nc < NCHUNK && tid == 0) {
            const uint32_t db = sbase + s * STAGE_BYTES;
            MBAR_EXPECT(mbb + s * 8, STAGE_BYTES);
            TMA2D(db,         &mAh, nc * 32, m0, mbb + s * 8);
            TMA2D(db + 8192,  &mAl, nc * 32, m0, mbb + s * 8);
            TMA2D(db + 16384, &mBh, nc * 32, n0, mbb + s * 8);
            TMA2D(db + 24576, &mBl, nc * 32, n0, mbb + s * 8);
        }
    }

    const int r0 = m0 + wm * 32 + (lane >> 2);
    const int nb0 = n0 + wn * 64 + 2 * (lane & 3);
#pragma unroll
    for (int mi = 0; mi < 2; mi++) {
#pragma unroll
        for (int ni = 0; ni < 8; ni++) {
            const int r = r0 + mi * 16;
            const int c = nb0 + ni * 8;
            float2 bb = *(const float2*)(bias + c);
            *(float2*)(C + (long)r * 1024 + c) =
                make_float2(acc[mi][ni][0] + bb.x, acc[mi][ni][1] + bb.y);
            *(float2*)(C + (long)(r + 8) * 1024 + c) =
                make_float2(acc[mi][ni][2] + bb.x, acc[mi][ni][3] + bb.y);
        }
    }
}

// ================= rope table ==============================================
__global__ void rope_table_kernel(float2* __restrict__ tab)
{
    const int idx = blockIdx.x * 256 + threadIdx.x;   // 65536
    const int i = idx & 31, s = idx >> 5;
    double p = pow(10000.0, (double)(2 * i) / 64.0);
    float f = (float)s * (1.0f / (float)p);
    tab[idx] = make_float2(cosf(f), sinf(f));
}

// ============ cvt x -> single fp16 + gate (one block per row) ==============
__global__ void cvt_x_gate(const float4* __restrict__ x,
                           const float4* __restrict__ Wg,
                           const float* __restrict__ bg,
                           uint2* __restrict__ xf,
                           float* __restrict__ gout)
{
    const int row = blockIdx.x;
    const int tid = threadIdx.x;
    const long i = (long)row * 256 + tid;
    float4 v = x[i];
    float4 w = Wg[tid];
    float dot = v.x * w.x + v.y * w.y + v.z * w.z + v.w * w.w;

    float f[4] = {v.x, v.y, v.z, v.w};
    unsigned short hs[4];
#pragma unroll
    for (int j = 0; j < 4; j++) {
        __half h = __float2half(f[j]);
        hs[j] = *(unsigned short*)&h;
    }
    uint2 H;
    H.x = (uint32_t)hs[0] | ((uint32_t)hs[1] << 16);
    H.y = (uint32_t)hs[2] | ((uint32_t)hs[3] << 16);
    xf[i] = H;

#pragma unroll
    for (int o = 16; o; o >>= 1) dot += __shfl_down_sync(0xffffffffu, dot, o);
    __shared__ float ws[8];
    if ((tid & 31) == 0) ws[tid >> 5] = dot;
    __syncthreads();
    if (tid == 0) {
        float t = 0.f;
#pragma unroll
        for (int j = 0; j < 8; j++) t += ws[j];
        t += bg[0];
        gout[row] = 1.f / (1.f + expf(-t));
    }
}

// W[K][N] fp32 -> transposed hi/lo [N][K]; z<3: fp16 split, z==3: bf16 split
__global__ void cvt_w4(const float* __restrict__ W0, const float* __restrict__ W1,
                       const float* __restrict__ W2, const float* __restrict__ W3,
                       __nv_bfloat16* __restrict__ h0, __nv_bfloat16* __restrict__ l0,
                       __nv_bfloat16* __restrict__ h1, __nv_bfloat16* __restrict__ l1,
                       __nv_bfloat16* __restrict__ h2, __nv_bfloat16* __restrict__ l2,
                       __nv_bfloat16* __restrict__ h3, __nv_bfloat16* __restrict__ l3)
{
    const int z = blockIdx.z;
    const float* W = (z == 0) ? W0 : (z == 1) ? W1 : (z == 2) ? W2 : W3;
    unsigned short* bh = (unsigned short*)((z == 0) ? h0 : (z == 1) ? h1 : (z == 2) ? h2 : h3);
    unsigned short* bl = (unsigned short*)((z == 0) ? l0 : (z == 1) ? l1 : (z == 2) ? l2 : l3);

    __shared__ float t[32][33];
    const int nx = blockIdx.x * 32, kx = blockIdx.y * 32;
    const int tx = threadIdx.x, ty = threadIdx.y;   // 32 x 8
#pragma unroll
    for (int r = 0; r < 32; r += 8)
        t[ty + r][tx] = W[(long)(kx + ty + r) * 1024 + nx + tx];
    __syncthreads();
#pragma unroll
    for (int r = 0; r < 32; r += 8) {
        float v = t[tx][ty + r];
        long o = (long)(nx + ty + r) * 1024 + kx + tx;
        if (z < 3) {
            __half h = __float2half(v);
            float rr = v - __half2float(h);
            __half l = __float2half(rr);
            bh[o] = *(unsigned short*)&h;
            bl[o] = *(unsigned short*)&l;
        } else {
            __nv_bfloat16 h = __float2bfloat16(v);
            float rr = v - __bfloat162float(h);
            __nv_bfloat16 l = __float2bfloat16(rr);
            bh[o] = *(unsigned short*)&h;
            bl[o] = *(unsigned short*)&l;
        }
    }
}

// ---------------- kv partial: per (b,n,chunk) 64x64 outer-product sum ------
__global__ void kv_partial_kernel(const float* __restrict__ k,
                                  const float* __restrict__ v,
                                  float* __restrict__ kv_part,
                                  float* __restrict__ ksum_part)
{
    const int bn = blockIdx.x;
    const int c  = blockIdx.y;
    const int b = bn >> 4, n = bn & 15;
    __shared__ float ks[32][64];
    __shared__ float vs[32][64];
    const int tid = threadIdx.x;
    const int ti = tid >> 4, tj = tid & 15;

    float acc[4][4];
#pragma unroll
    for (int a = 0; a < 4; a++)
#pragma unroll
        for (int d = 0; d < 4; d++) acc[a][d] = 0.f;
    float ksum = 0.f;

    const int s0 = c * 256;
    for (int so = 0; so < 256; so += 32) {
#pragma unroll
        for (int e = tid; e < 512; e += 256) {
            int sl = e >> 4, dd = (e & 15) * 4;
            long gb = (((long)(b * Ssz + s0 + so + sl) * Nh) + n) * Dh + dd;
            *(float4*)&ks[sl][dd] = *(const float4*)&k[gb];
            *(float4*)&vs[sl][dd] = *(const float4*)&v[gb];
        }
        __syncthreads();
#pragma unroll 4
        for (int sl = 0; sl < 32; ++sl) {
            float4 kk4 = *(const float4*)&ks[sl][ti * 4];
            float4 vv4 = *(const float4*)&vs[sl][tj * 4];
            float ka[4] = {kk4.x, kk4.y, kk4.z, kk4.w};
            float va[4] = {vv4.x, vv4.y, vv4.z, vv4.w};
#pragma unroll
            for (int a = 0; a < 4; a++)
#pragma unroll
                for (int d = 0; d < 4; d++) acc[a][d] += ka[a] * va[d];
        }
        if (tid < 64) {
#pragma unroll 4
            for (int sl = 0; sl < 32; ++sl) ksum += ks[sl][tid];
        }
        __syncthreads();
    }

    const long pbase = ((long)c * 64 + bn) * 4096;
#pragma unroll
    for (int a = 0; a < 4; a++) {
        float4 o = make_float4(acc[a][0], acc[a][1], acc[a][2], acc[a][3]);
        *(float4*)&kv_part[pbase + (ti * 4 + a) * 64 + tj * 4] = o;
    }
    if (tid < 64) ksum_part[(c * 64 + bn) * 64 + tid] = ksum;
}

__global__ void kv_reduce_kernel(const float* __restrict__ kv_part,
                                 const float* __restrict__ ksum_part,
                                 float* __restrict__ kv,
                                 float* __restrict__ ksum)
{
    const int bn = blockIdx.x;
    const int tid = threadIdx.x;
    for (int e = tid; e < 4096; e += 256) {
        float s = 0.f;
#pragma unroll
        for (int c = 0; c < 8; ++c) s += kv_part[((long)c * 64 + bn) * 4096 + e];
        kv[(long)bn * 4096 + e] = s;
    }
    if (tid < 64) {
        float s = 0.f;
#pragma unroll
        for (int c = 0; c < 8; ++c) s += ksum_part[(c * 64 + bn) * 64 + tid];
        ksum[bn * 64 + tid] = s;
    }
}

// ---- combine: num=q@kv; den=q.ksum+eps; gate mix; write bf16 hi/lo --------
__global__ void combine_kernel(const float* __restrict__ q,
                               const float* __restrict__ kv,
                               const float* __restrict__ ksum,
                               const float* __restrict__ gate,
                               const float* __restrict__ df,
                               const float* __restrict__ gw,
                               __nv_bfloat16* __restrict__ ch,
                               __nv_bfloat16* __restrict__ cl)
{
    const int bn = blockIdx.x;
    const int st = blockIdx.y;
    const int b = bn >> 4, n = bn & 15;

    __shared__ float qs[64][68];
    __shared__ float kvs[64][64];
    __shared__ float ksums[64];

    const int tid = threadIdx.x;

    float w0 = gw[0], w1 = gw[1], w2 = gw[2];
    float d0 = df[0], d1 = df[1], d2 = df[2];
    float mx = fmaxf(w0, fmaxf(w1, w2));
    float e0 = expf(w0 - mx), e1 = expf(w1 - mx), e2 = expf(w2 - mx);
    float s0f = 1.f / (1.f + expf(-d0));
    float s1f = 1.f / (1.f + expf(-d1));
    float s2f = 1.f / (1.f + expf(-d2));
    float coef = (e0 * (1.f - s0f) + e1 * (1.f - s1f) + e2 * (1.f - s2f)) / (e0 + e1 + e2);

    const long kvbase = (long)bn * 4096;
    for (int e = tid; e < 1024; e += 256)
        ((float4*)kvs)[e] = ((const float4*)(kv + kvbase))[e];
    if (tid < 64) ksums[tid] = ksum[bn * 64 + tid];

    const int srow0 = st * 64;
    for (int e = tid; e < 1024; e += 256) {
        int r = e >> 4, dd = (e & 15) * 4;
        long gq = (((long)(b * Ssz + srow0 + r) * Nh) + n) * Dh + dd;
        *(float4*)&qs[r][dd] = *(const float4*)&q[gq];
    }
    __syncthreads();

    const int sl = tid >> 2;
    const int jg = tid & 3;
    float acc[16];
#pragma unroll
    for (int j = 0; j < 16; j++) acc[j] = 0.f;
    float den = 0.f;

#pragma unroll 4
    for (int kk = 0; kk < 64; ++kk) {
        float qv = qs[sl][kk];
        den += qv * ksums[kk];
        const float4* kr = (const float4*)&kvs[kk][jg * 16];
        float4 c0 = kr[0], c1 = kr[1], c2 = kr[2], c3 = kr[3];
        acc[0]  += qv * c0.x; acc[1]  += qv * c0.y; acc[2]  += qv * c0.z; acc[3]  += qv * c0.w;
        acc[4]  += qv * c1.x; acc[5]  += qv * c1.y; acc[6]  += qv * c1.z; acc[7]  += qv * c1.w;
        acc[8]  += qv * c2.x; acc[9]  += qv * c2.y; acc[10] += qv * c2.z; acc[11] += qv * c2.w;
        acc[12] += qv * c3.x; acc[13] += qv * c3.y; acc[14] += qv * c3.z; acc[15] += qv * c3.w;
    }
    den += EPSF;

    const int srow = srow0 + sl;
    const float g = gate[b * Ssz + srow];
    const float fac = g / den + (1.f - g) * coef;

    const long obase = (((long)(b * Ssz + srow) * Nh) + n) * Dh + jg * 16;
#pragma unroll
    for (int u = 0; u < 4; u++) {
        unsigned short hs[4], ls[4];
#pragma unroll
        for (int e = 0; e < 4; e++) {
            float val = acc[u * 4 + e] * fac;
            __nv_bfloat16 h = __float2bfloat16(val);
            float r = val - __bfloat162float(h);
            __nv_bfloat16 l = __float2bfloat16(r);
            hs[e] = *(unsigned short*)&h;
            ls[e] = *(unsigned short*)&l;
        }
        uint2 H, L;
        H.x = (uint32_t)hs[0] | ((uint32_t)hs[1] << 16);
        H.y = (uint32_t)hs[2] | ((uint32_t)hs[3] << 16);
        L.x = (uint32_t)ls[0] | ((uint32_t)ls[1] << 16);
        L.y = (uint32_t)ls[2] | ((uint32_t)ls[3] << 16);
        *(uint2*)(ch + obase + u * 4) = H;
        *(uint2*)(cl + obase + u * 4) = L;
    }
}

// ================= host: tensormap construction ============================
typedef CUresult (*PFN_encodeTiled)(
    CUtensorMap*, CUtensorMapDataType, cuuint32_t, void*,
    const cuuint64_t*, const cuuint64_t*, const cuuint32_t*, const cuuint32_t*,
    CUtensorMapInterleave, CUtensorMapSwizzle, CUtensorMapL2promotion,
    CUtensorMapFloatOOBfill);

static PFN_encodeTiled get_encoder() {
    static PFN_encodeTiled fn = nullptr;
    if (!fn) {
        void* p = nullptr;
        cudaDriverEntryPointQueryResult st;
        cudaGetDriverEntryPointByVersion("cuTensorMapEncodeTiled", &p, 12000,
                                         cudaEnableDefault, &st);
        fn = (PFN_encodeTiled)p;
    }
    return fn;
}

static void make_map(CUtensorMap* m, void* base, uint64_t rows) {
    cuuint64_t dims[2]    = {1024, rows};
    cuuint64_t strides[1] = {2048};
    cuuint32_t box[2]     = {32, 128};
    cuuint32_t es[2]      = {1, 1};
    get_encoder()(m, CU_TENSOR_MAP_DATA_TYPE_BFLOAT16, 2, base, dims, strides,
                  box, es, CU_TENSOR_MAP_INTERLEAVE_NONE,
                  CU_TENSOR_MAP_SWIZZLE_64B, CU_TENSOR_MAP_L2_PROMOTION_L2_128B,
                  CU_TENSOR_MAP_FLOAT_OOB_FILL_NONE);
}

// ---------------------------------------------------------------------------
extern "C" void kernel_launch(void* const* d_in, const int* in_sizes, int n_in,
                              void* d_out, int out_size)
{
    const float* x    = (const float*)d_in[0];
    const float* mask = (const float*)d_in[1];
    const float* Wq   = (const float*)d_in[2];
    const float* bq   = (const float*)d_in[3];
    const float* Wk   = (const float*)d_in[4];
    const float* bk   = (const float*)d_in[5];
    const float* Wv   = (const float*)d_in[6];
    const float* bv   = (const float*)d_in[7];
    const float* Wo   = (const float*)d_in[8];
    const float* bo   = (const float*)d_in[9];
    const float* Wg   = (const float*)d_in[10];
    const float* bg   = (const float*)d_in[11];
    const float* df   = (const float*)d_in[12];
    const float* gw   = (const float*)d_in[13];
    float* out = (float*)d_out;

    float *q, *k, *v, *kvp, *kv, *ksp, *ks, *gate;
    float2* tab;
    __nv_bfloat16 *ah, *al, *bqh, *bql, *bkh, *bkl, *bvh, *bvl, *boh, *bol;
    cudaGetSymbolAddress((void**)&q,    g_q);
    cudaGetSymbolAddress((void**)&k,    g_k);
    cudaGetSymbolAddress((void**)&v,    g_v);
    cudaGetSymbolAddress((void**)&kvp,  g_kv_part);
    cudaGetSymbolAddress((void**)&kv,   g_kv);
    cudaGetSymbolAddress((void**)&ksp,  g_ksum_part);
    cudaGetSymbolAddress((void**)&ks,   g_ksum);
    cudaGetSymbolAddress((void**)&gate, g_gate);
    cudaGetSymbolAddress((void**)&tab,  g_rope);
    cudaGetSymbolAddress((void**)&ah,   g_ah);
    cudaGetSymbolAddress((void**)&al,   g_al);
    cudaGetSymbolAddress((void**)&bqh,  g_bqh);
    cudaGetSymbolAddress((void**)&bql,  g_bql);
    cudaGetSymbolAddress((void**)&bkh,  g_bkh);
    cudaGetSymbolAddress((void**)&bkl,  g_bkl);
    cudaGetSymbolAddress((void**)&bvh,  g_bvh);
    cudaGetSymbolAddress((void**)&bvl,  g_bvl);
    cudaGetSymbolAddress((void**)&boh,  g_boh);
    cudaGetSymbolAddress((void**)&bol,  g_bol);

    CUtensorMap mAh, mAl, mQh, mQl, mKh, mKl, mVh, mVl, mOh, mOl;
    make_map(&mAh, ah, Msz);  make_map(&mAl, al, Msz);
    make_map(&mQh, bqh, Hsz); make_map(&mQl, bql, Hsz);
    make_map(&mKh, bkh, Hsz); make_map(&mKl, bkl, Hsz);
    make_map(&mVh, bvh, Hsz); make_map(&mVl, bvl, Hsz);
    make_map(&mOh, boh, Hsz); make_map(&mOl, bol, Hsz);

    cudaFuncSetAttribute(gemm_qkv_f16x2,
                         cudaFuncAttributeMaxDynamicSharedMemorySize, SMEM_F16);
    cudaFuncSetAttribute(gemm_out_bf16x3,
                         cudaFuncAttributeMaxDynamicSharedMemorySize, GEMM_SMEM);

    // 1. rope table
    rope_table_kernel<<<Ssz * 32 / 256, 256>>>(tab);
    // 2. activation -> single fp16 (into ah) + gate
    cvt_x_gate<<<Msz, 256>>>((const float4*)x, (const float4*)Wg, bg,
                             (uint2*)ah, gate);
    // 3. weight conversions: Wq/Wk/Wv fp16 hi/lo, Wo bf16 hi/lo
    cvt_w4<<<dim3(32, 32, 4), dim3(32, 8)>>>(Wq, Wk, Wv, Wo,
                                             bqh, bql, bkh, bkl,
                                             bvh, bvl, boh, bol);
    // 4. fused QKV projection (fp16x2) + rope/phi/mask epilogue  (profiled)
    gemm_qkv_f16x2<<<dim3(8, 64, 3), 256, SMEM_F16>>>(
        mAh, mQh, mQl, mKh, mKl, mVh, mVl, bq, bk, bv, q, k, v, mask, tab);
    // 5-6. kv aggregation
    kv_partial_kernel<<<dim3(64, 8), 256>>>(k, v, kvp, ksp);
    kv_reduce_kernel<<<64, 256>>>(kvp, ksp, kv, ks);
    // 7. combine writes bf16 hi/lo into ah/al
    combine_kernel<<<dim3(64, Ssz / 64), 256>>>(q, kv, ks, gate, df, gw, ah, al);
    // 8. output projection (bf16x3)
    gemm_out_bf16x3<<<dim3(8, 64), 256, GEMM_SMEM>>>(mAh, mAl, mOh, mOl, bo, out);
}

// round 7
// speedup vs baseline: 3.4485x; 1.1222x over previous
#include <cuda_runtime.h>
#include <cuda.h>
#include <cuda_bf16.h>
#include <cuda_fp16.h>
#include <math.h>
#include <stdint.h>

// Problem constants
#define Bsz 4
#define Ssz 2048
#define Hsz 1024
#define Nh  16
#define Dh  64
#define Msz (Bsz*Ssz)      // 8192
#define EPSF 1e-6f

// ---------------- scratch (static device globals; no allocs allowed) -------
__device__ float g_q[Msz*Hsz];
__device__ float g_k[Msz*Hsz];
__device__ float g_v[Msz*Hsz];
__device__ float g_kv_part[8*64*64*64];
__device__ float g_kv[64*64*64];
__device__ float g_ksum_part[8*64*64];
__device__ float g_ksum[64*64];
__device__ float g_gate[Msz];
__device__ float2 g_rope[Ssz*32];         // (cos, sin) per (s, i)
// fp16 operand buffers. g_af: x fp16 for QKV phase; comb fp16 after combine.
__device__ __half g_af[Msz*Hsz];
__device__ __half g_bqh[Hsz*Hsz], g_bql[Hsz*Hsz];
__device__ __half g_bkh[Hsz*Hsz], g_bkl[Hsz*Hsz];
__device__ __half g_bvh[Hsz*Hsz], g_bvl[Hsz*Hsz];
__device__ __half g_boh[Hsz*Hsz], g_bol[Hsz*Hsz];

// ================= low-level helpers =======================================
static __device__ __forceinline__ uint32_t s2u(const void* p) {
    uint32_t a;
    asm("{ .reg .u64 t; cvta.to.shared.u64 t, %1; cvt.u32.u64 %0, t; }"
        : "=r"(a) : "l"(p));
    return a;
}

static __device__ __forceinline__ void ldsm4(uint32_t* r, uint32_t addr) {
    asm volatile("ldmatrix.sync.aligned.m8n8.x4.shared.b16 {%0,%1,%2,%3}, [%4];"
                 : "=r"(r[0]), "=r"(r[1]), "=r"(r[2]), "=r"(r[3]) : "r"(addr));
}

static __device__ __forceinline__ void mma16816h(float* d, const uint32_t* a,
                                                 const uint32_t* b) {
    asm volatile(
        "mma.sync.aligned.m16n8k16.row.col.f32.f16.f16.f32 "
        "{%0,%1,%2,%3}, {%4,%5,%6,%7}, {%8,%9}, {%0,%1,%2,%3};"
        : "+f"(d[0]), "+f"(d[1]), "+f"(d[2]), "+f"(d[3])
        : "r"(a[0]), "r"(a[1]), "r"(a[2]), "r"(a[3]), "r"(b[0]), "r"(b[1]));
}

// smem tile: [128 rows][32 elems = 64B], SW64 swizzle: chunk16 ^= (row>>1)&3
static __device__ __forceinline__ uint32_t swoff(int row, int c16) {
    return (uint32_t)(row * 64 + ((c16 ^ ((row >> 1) & 3)) << 4));
}

#define MBAR_INIT(m, c) \
    asm volatile("mbarrier.init.shared.b64 [%0], %1;" \
                 :: "r"((uint32_t)(m)), "r"((uint32_t)(c)) : "memory")
#define MBAR_EXPECT(m, b) \
    asm volatile("mbarrier.arrive.expect_tx.shared.b64 _, [%0], %1;" \
                 :: "r"((uint32_t)(m)), "r"((uint32_t)(b)) : "memory")
#define MBAR_ARRIVE(m) \
    asm volatile("mbarrier.arrive.release.cta.shared.b64 _, [%0];" \
                 :: "r"((uint32_t)(m)) : "memory")

static __device__ __forceinline__ void mbar_wait(uint32_t mbar, uint32_t parity) {
    asm volatile(
        "{\n\t.reg .pred P;\n\t"
        "WL_%=:\n\t"
        "mbarrier.try_wait.parity.acquire.cta.shared::cta.b64 P, [%0], %1, 0x989680;\n\t"
        "@P bra.uni WD_%=;\n\t"
        "bra.uni WL_%=;\n\t"
        "WD_%=:\n\t}"
        :: "r"(mbar), "r"(parity) : "memory");
}

#define TMA2D(sa, mp, cx, cy, mb) \
    asm volatile("cp.async.bulk.tensor.2d.shared::cta.global.tile.mbarrier::complete_tx::bytes " \
                 "[%0], [%1, {%2, %3}], [%4];" \
                 :: "r"((uint32_t)(sa)), "l"(mp), "r"((int)(cx)), "r"((int)(cy)), \
                    "r"((uint32_t)(mb)) : "memory")

__device__ __forceinline__ float phi_fn(float x) {
    float t = (x > 0.f) ? x : expm1f(x);
    return (t + 1.0f) + EPSF;
}

#define NCHUNK 32

// ================= fp16x2 GEMM (A single fp16, B split hi/lo) ==============
// C[8192,1024] = Af @ (Bh+Bl)^T + bias.
// Stage = 24KB (Af 8K | Bh 8K | Bl 8K), 4 stages.
// Sync: "full" mbar per stage (TMA tx) + "consumed" mbar per stage
// (256 arrivals) — tid0 waits consumed before TMA reissue; no __syncthreads
// in the mainloop.
// epi_mode 0: fused QKV epilogue (z: 0=q rope+phi*0.125, 1=k rope+phi*mask,
//             2=v mask). epi_mode 1: plain bias+store.
#define STAGE_F16 24576
#define SMEM_F16 (4 * STAGE_F16 + 128)

__global__ __launch_bounds__(256, 2)
void gemm_f16x2(const __grid_constant__ CUtensorMap mAf,
                const __grid_constant__ CUtensorMap mB0h,
                const __grid_constant__ CUtensorMap mB0l,
                const __grid_constant__ CUtensorMap mB1h,
                const __grid_constant__ CUtensorMap mB1l,
                const __grid_constant__ CUtensorMap mB2h,
                const __grid_constant__ CUtensorMap mB2l,
                const float* __restrict__ b0, const float* __restrict__ b1,
                const float* __restrict__ b2,
                float* __restrict__ C0, float* __restrict__ C1,
                float* __restrict__ C2,
                const float* __restrict__ maskp,
                const float2* __restrict__ tab,
                int epi_mode)
{
    extern __shared__ __align__(1024) char smem[];
    const uint32_t sbase = s2u(smem);
    const uint32_t mbb  = sbase + 4 * STAGE_F16;      // full[4]
    const uint32_t mbc  = mbb + 32;                   // consumed[4]
    const int tid = threadIdx.x;
    const int lane = tid & 31, wid = tid >> 5;
    const int wm = wid & 3, wn = wid >> 2;
    const int n0 = blockIdx.x * 128, m0 = blockIdx.y * 128;
    const int z = blockIdx.z;

    const CUtensorMap* pBh = (z == 0) ? &mB0h : (z == 1) ? &mB1h : &mB2h;
    const CUtensorMap* pBl = (z == 0) ? &mB0l : (z == 1) ? &mB1l : &mB2l;
    const float* bias = (z == 0) ? b0 : (z == 1) ? b1 : b2;
    float* C = (z == 0) ? C0 : (z == 1) ? C1 : C2;

    const int a_row  = wm * 32 + (lane & 15);
    const int a_c16h = lane >> 4;
    const int b_row  = wn * 64 + ((lane >> 4) << 3) + (lane & 7);
    const int b_c16h = (lane >> 3) & 1;

    float acc[2][8][4];
#pragma unroll
    for (int mi = 0; mi < 2; mi++)
#pragma unroll
        for (int ni = 0; ni < 8; ni++)
#pragma unroll
            for (int u = 0; u < 4; u++) acc[mi][ni][u] = 0.f;

    if (tid == 0) {
#pragma unroll
        for (int s = 0; s < 4; s++) {
            MBAR_INIT(mbb + s * 8, 1);
            MBAR_INIT(mbc + s * 8, 256);
        }
    }
    __syncthreads();

    if (tid == 0) {
#pragma unroll
        for (int s = 0; s < 4; s++) {
            const uint32_t db = sbase + s * STAGE_F16;
            MBAR_EXPECT(mbb + s * 8, STAGE_F16);
            TMA2D(db,         &mAf, s * 32, m0, mbb + s * 8);
            TMA2D(db + 8192,  pBh,  s * 32, n0, mbb + s * 8);
            TMA2D(db + 16384, pBl,  s * 32, n0, mbb + s * 8);
        }
    }

    for (int it = 0; it < NCHUNK; it++) {
        const int s = it & 3;
        mbar_wait(mbb + s * 8, (it >> 2) & 1);

        const uint32_t base = sbase + s * STAGE_F16;
#pragma unroll
        for (int ks = 0; ks < 2; ks++) {
            uint32_t aF[2][4];
            ldsm4(aF[0], base + swoff(a_row,      ks * 2 + a_c16h));
            ldsm4(aF[1], base + swoff(a_row + 16, ks * 2 + a_c16h));
#pragma unroll
            for (int np = 0; np < 2; np++) {
                const int j0 = np * 4;
                uint32_t bH0[4], bH1[4], bL0[4], bL1[4];
                ldsm4(bH0, base + 8192 + swoff(b_row + (2*np)   * 16, ks * 2 + b_c16h));
                ldsm4(bH1, base + 8192 + swoff(b_row + (2*np+1) * 16, ks * 2 + b_c16h));
                mma16816h(acc[0][j0+0], aF[0], bH0 + 0);
                mma16816h(acc[0][j0+1], aF[0], bH0 + 2);
                mma16816h(acc[0][j0+2], aF[0], bH1 + 0);
                mma16816h(acc[0][j0+3], aF[0], bH1 + 2);
                mma16816h(acc[1][j0+0], aF[1], bH0 + 0);
                mma16816h(acc[1][j0+1], aF[1], bH0 + 2);
                mma16816h(acc[1][j0+2], aF[1], bH1 + 0);
                mma16816h(acc[1][j0+3], aF[1], bH1 + 2);
                ldsm4(bL0, base + 16384 + swoff(b_row + (2*np)   * 16, ks * 2 + b_c16h));
                ldsm4(bL1, base + 16384 + swoff(b_row + (2*np+1) * 16, ks * 2 + b_c16h));
                mma16816h(acc[0][j0+0], aF[0], bL0 + 0);
                mma16816h(acc[0][j0+1], aF[0], bL0 + 2);
                mma16816h(acc[0][j0+2], aF[0], bL1 + 0);
                mma16816h(acc[0][j0+3], aF[0], bL1 + 2);
                mma16816h(acc[1][j0+0], aF[1], bL0 + 0);
                mma16816h(acc[1][j0+1], aF[1], bL0 + 2);
                mma16816h(acc[1][j0+2], aF[1], bL1 + 0);
                mma16816h(acc[1][j0+3], aF[1], bL1 + 2);
            }
        }
        // signal this thread is done reading stage s
        MBAR_ARRIVE(mbc + s * 8);

        const int nc = it + 4;
        if (nc < NCHUNK && tid == 0) {
            // wait until ALL threads consumed stage s, then refill it
            mbar_wait(mbc + s * 8, (it >> 2) & 1);
            const uint32_t db = sbase + s * STAGE_F16;
            MBAR_EXPECT(mbb + s * 8, STAGE_F16);
            TMA2D(db,         &mAf, nc * 32, m0, mbb + s * 8);
            TMA2D(db + 8192,  pBh,  nc * 32, n0, mbb + s * 8);
            TMA2D(db + 16384, pBl,  nc * 32, n0, mbb + s * 8);
        }
    }

    // ---------------- epilogue ----------------
    const int r0 = m0 + wm * 32 + (lane >> 2);
    const int nb0 = n0 + wn * 64 + 2 * (lane & 3);

    if (epi_mode == 1) {
#pragma unroll
        for (int mi = 0; mi < 2; mi++) {
#pragma unroll
            for (int ni = 0; ni < 8; ni++) {
                const int r = r0 + mi * 16;
                const int c = nb0 + ni * 8;
                float2 bb = *(const float2*)(bias + c);
                *(float2*)(C + (long)r * 1024 + c) =
                    make_float2(acc[mi][ni][0] + bb.x, acc[mi][ni][1] + bb.y);
                *(float2*)(C + (long)(r + 8) * 1024 + c) =
                    make_float2(acc[mi][ni][2] + bb.x, acc[mi][ni][3] + bb.y);
            }
        }
        return;
    }

    // fused QKV epilogue (validated layout)
#pragma unroll
    for (int mi = 0; mi < 2; mi++) {
#pragma unroll
        for (int uu = 0; uu < 4; uu += 2) {
            const int r = r0 + mi * 16 + (uu ? 8 : 0);
            const int srow = r & (Ssz - 1);
            const float msk = maskp[r];
            if (z == 2) {
#pragma unroll
                for (int ni = 0; ni < 8; ni++) {
                    const int c = nb0 + ni * 8;
                    float v0 = (acc[mi][ni][uu+0] + bias[c])     * msk;
                    float v1 = (acc[mi][ni][uu+1] + bias[c + 1]) * msk;
                    *(float2*)(C + (long)r * 1024 + c) = make_float2(v0, v1);
                }
            } else {
                const float scale = (z == 0) ? 0.125f : msk;
#pragma unroll
                for (int ni = 0; ni < 4; ni++) {
                    float o1[2], o2[2];
#pragma unroll
                    for (int e = 0; e < 2; e++) {
                        const int i = 2 * (lane & 3) + ni * 8 + e;
                        const int c = nb0 + ni * 8 + e;
                        float x1 = acc[mi][ni][uu + e]     + bias[c];
                        float x2 = acc[mi][ni + 4][uu + e] + bias[c + 32];
                        float2 cs = tab[srow * 32 + i];
                        float r1 = x1 * cs.x - x2 * cs.y;
                        float r2 = x2 * cs.x + x1 * cs.y;
                        o1[e] = phi_fn(r1) * scale;
                        o2[e] = phi_fn(r2) * scale;
                    }
                    const int c = nb0 + ni * 8;
                    *(float2*)(C + (long)r * 1024 + c)      = make_float2(o1[0], o1[1]);
                    *(float2*)(C + (long)r * 1024 + c + 32) = make_float2(o2[0], o2[1]);
                }
            }
        }
    }
}

// ================= rope table ==============================================
__global__ void rope_table_kernel(float2* __restrict__ tab)
{
    const int idx = blockIdx.x * 256 + threadIdx.x;   // 65536
    const int i = idx & 31, s = idx >> 5;
    double p = pow(10000.0, (double)(2 * i) / 64.0);
    float f = (float)s * (1.0f / (float)p);
    tab[idx] = make_float2(cosf(f), sinf(f));
}

// ============ cvt x -> single fp16 + gate (one block per row) ==============
__global__ void cvt_x_gate(const float4* __restrict__ x,
                           const float4* __restrict__ Wg,
                           const float* __restrict__ bg,
                           uint2* __restrict__ xf,
                           float* __restrict__ gout)
{
    const int row = blockIdx.x;
    const int tid = threadIdx.x;
    const long i = (long)row * 256 + tid;
    float4 v = x[i];
    float4 w = Wg[tid];
    float dot = v.x * w.x + v.y * w.y + v.z * w.z + v.w * w.w;

    float f[4] = {v.x, v.y, v.z, v.w};
    unsigned short hs[4];
#pragma unroll
    for (int j = 0; j < 4; j++) {
        __half h = __float2half(f[j]);
        hs[j] = *(unsigned short*)&h;
    }
    uint2 H;
    H.x = (uint32_t)hs[0] | ((uint32_t)hs[1] << 16);
    H.y = (uint32_t)hs[2] | ((uint32_t)hs[3] << 16);
    xf[i] = H;

#pragma unroll
    for (int o = 16; o; o >>= 1) dot += __shfl_down_sync(0xffffffffu, dot, o);
    __shared__ float ws[8];
    if ((tid & 31) == 0) ws[tid >> 5] = dot;
    __syncthreads();
    if (tid == 0) {
        float t = 0.f;
#pragma unroll
        for (int j = 0; j < 8; j++) t += ws[j];
        t += bg[0];
        gout[row] = 1.f / (1.f + expf(-t));
    }
}

// W[K][N] fp32 -> transposed fp16 hi/lo [N][K]; z selects which W
__global__ void cvt_w4(const float* __restrict__ W0, const float* __restrict__ W1,
                       const float* __restrict__ W2, const float* __restrict__ W3,
                       __half* __restrict__ h0, __half* __restrict__ l0,
                       __half* __restrict__ h1, __half* __restrict__ l1,
                       __half* __restrict__ h2, __half* __restrict__ l2,
                       __half* __restrict__ h3, __half* __restrict__ l3)
{
    const int z = blockIdx.z;
    const float* W = (z == 0) ? W0 : (z == 1) ? W1 : (z == 2) ? W2 : W3;
    __half* bh = (z == 0) ? h0 : (z == 1) ? h1 : (z == 2) ? h2 : h3;
    __half* bl = (z == 0) ? l0 : (z == 1) ? l1 : (z == 2) ? l2 : l3;

    __shared__ float t[32][33];
    const int nx = blockIdx.x * 32, kx = blockIdx.y * 32;
    const int tx = threadIdx.x, ty = threadIdx.y;   // 32 x 8
#pragma unroll
    for (int r = 0; r < 32; r += 8)
        t[ty + r][tx] = W[(long)(kx + ty + r) * 1024 + nx + tx];
    __syncthreads();
#pragma unroll
    for (int r = 0; r < 32; r += 8) {
        float v = t[tx][ty + r];
        long o = (long)(nx + ty + r) * 1024 + kx + tx;
        __half h = __float2half(v);
        float rr = v - __half2float(h);
        bh[o] = h;
        bl[o] = __float2half(rr);
    }
}

// ---------------- kv partial: per (b,n,chunk) 64x64 outer-product sum ------
__global__ void kv_partial_kernel(const float* __restrict__ k,
                                  const float* __restrict__ v,
                                  float* __restrict__ kv_part,
                                  float* __restrict__ ksum_part)
{
    const int bn = blockIdx.x;
    const int c  = blockIdx.y;
    const int b = bn >> 4, n = bn & 15;
    __shared__ float ks[32][64];
    __shared__ float vs[32][64];
    const int tid = threadIdx.x;
    const int ti = tid >> 4, tj = tid & 15;

    float acc[4][4];
#pragma unroll
    for (int a = 0; a < 4; a++)
#pragma unroll
        for (int d = 0; d < 4; d++) acc[a][d] = 0.f;
    float ksum = 0.f;

    const int s0 = c * 256;
    for (int so = 0; so < 256; so += 32) {
#pragma unroll
        for (int e = tid; e < 512; e += 256) {
            int sl = e >> 4, dd = (e & 15) * 4;
            long gb = (((long)(b * Ssz + s0 + so + sl) * Nh) + n) * Dh + dd;
            *(float4*)&ks[sl][dd] = *(const float4*)&k[gb];
            *(float4*)&vs[sl][dd] = *(const float4*)&v[gb];
        }
        __syncthreads();
#pragma unroll 4
        for (int sl = 0; sl < 32; ++sl) {
            float4 kk4 = *(const float4*)&ks[sl][ti * 4];
            float4 vv4 = *(const float4*)&vs[sl][tj * 4];
            float ka[4] = {kk4.x, kk4.y, kk4.z, kk4.w};
            float va[4] = {vv4.x, vv4.y, vv4.z, vv4.w};
#pragma unroll
            for (int a = 0; a < 4; a++)
#pragma unroll
                for (int d = 0; d < 4; d++) acc[a][d] += ka[a] * va[d];
        }
        if (tid < 64) {
#pragma unroll 4
            for (int sl = 0; sl < 32; ++sl) ksum += ks[sl][tid];
        }
        __syncthreads();
    }

    const long pbase = ((long)c * 64 + bn) * 4096;
#pragma unroll
    for (int a = 0; a < 4; a++) {
        float4 o = make_float4(acc[a][0], acc[a][1], acc[a][2], acc[a][3]);
        *(float4*)&kv_part[pbase + (ti * 4 + a) * 64 + tj * 4] = o;
    }
    if (tid < 64) ksum_part[(c * 64 + bn) * 64 + tid] = ksum;
}

__global__ void kv_reduce_kernel(const float* __restrict__ kv_part,
                                 const float* __restrict__ ksum_part,
                                 float* __restrict__ kv,
                                 float* __restrict__ ksum)
{
    const int bn = blockIdx.x;
    const int tid = threadIdx.x;
    for (int e = tid; e < 4096; e += 256) {
        float s = 0.f;
#pragma unroll
        for (int c = 0; c < 8; ++c) s += kv_part[((long)c * 64 + bn) * 4096 + e];
        kv[(long)bn * 4096 + e] = s;
    }
    if (tid < 64) {
        float s = 0.f;
#pragma unroll
        for (int c = 0; c < 8; ++c) s += ksum_part[(c * 64 + bn) * 64 + tid];
        ksum[bn * 64 + tid] = s;
    }
}

// ---- combine: num=q@kv; den=q.ksum+eps; gate mix; write single fp16 -------
__global__ void combine_kernel(const float* __restrict__ q,
                               const float* __restrict__ kv,
                               const float* __restrict__ ksum,
                               const float* __restrict__ gate,
                               const float* __restrict__ df,
                               const float* __restrict__ gw,
                               __half* __restrict__ cf)
{
    const int bn = blockIdx.x;
    const int st = blockIdx.y;
    const int b = bn >> 4, n = bn & 15;

    __shared__ float qs[64][68];
    __shared__ float kvs[64][64];
    __shared__ float ksums[64];

    const int tid = threadIdx.x;

    float w0 = gw[0], w1 = gw[1], w2 = gw[2];
    float d0 = df[0], d1 = df[1], d2 = df[2];
    float mx = fmaxf(w0, fmaxf(w1, w2));
    float e0 = expf(w0 - mx), e1 = expf(w1 - mx), e2 = expf(w2 - mx);
    float s0f = 1.f / (1.f + expf(-d0));
    float s1f = 1.f / (1.f + expf(-d1));
    float s2f = 1.f / (1.f + expf(-d2));
    float coef = (e0 * (1.f - s0f) + e1 * (1.f - s1f) + e2 * (1.f - s2f)) / (e0 + e1 + e2);

    const long kvbase = (long)bn * 4096;
    for (int e = tid; e < 1024; e += 256)
        ((float4*)kvs)[e] = ((const float4*)(kv + kvbase))[e];
    if (tid < 64) ksums[tid] = ksum[bn * 64 + tid];

    const int srow0 = st * 64;
    for (int e = tid; e < 1024; e += 256) {
        int r = e >> 4, dd = (e & 15) * 4;
        long gq = (((long)(b * Ssz + srow0 + r) * Nh) + n) * Dh + dd;
        *(float4*)&qs[r][dd] = *(const float4*)&q[gq];
    }
    __syncthreads();

    const int sl = tid >> 2;
    const int jg = tid & 3;
    float acc[16];
#pragma unroll
    for (int j = 0; j < 16; j++) acc[j] = 0.f;
    float den = 0.f;

#pragma unroll 4
    for (int kk = 0; kk < 64; ++kk) {
        float qv = qs[sl][kk];
        den += qv * ksums[kk];
        const float4* kr = (const float4*)&kvs[kk][jg * 16];
        float4 c0 = kr[0], c1 = kr[1], c2 = kr[2], c3 = kr[3];
        acc[0]  += qv * c0.x; acc[1]  += qv * c0.y; acc[2]  += qv * c0.z; acc[3]  += qv * c0.w;
        acc[4]  += qv * c1.x; acc[5]  += qv * c1.y; acc[6]  += qv * c1.z; acc[7]  += qv * c1.w;
        acc[8]  += qv * c2.x; acc[9]  += qv * c2.y; acc[10] += qv * c2.z; acc[11] += qv * c2.w;
        acc[12] += qv * c3.x; acc[13] += qv * c3.y; acc[14] += qv * c3.z; acc[15] += qv * c3.w;
    }
    den += EPSF;

    const int srow = srow0 + sl;
    const float g = gate[b * Ssz + srow];
    const float fac = g / den + (1.f - g) * coef;

    const long obase = (((long)(b * Ssz + srow) * Nh) + n) * Dh + jg * 16;
#pragma unroll
    for (int u = 0; u < 4; u++) {
        unsigned short hs[4];
#pragma unroll
        for (int e = 0; e < 4; e++) {
            __half h = __float2half(acc[u * 4 + e] * fac);
            hs[e] = *(unsigned short*)&h;
        }
        uint2 H;
        H.x = (uint32_t)hs[0] | ((uint32_t)hs[1] << 16);
        H.y = (uint32_t)hs[2] | ((uint32_t)hs[3] << 16);
        *(uint2*)(cf + obase + u * 4) = H;
    }
}

// ================= host: tensormap construction ============================
typedef CUresult (*PFN_encodeTiled)(
    CUtensorMap*, CUtensorMapDataType, cuuint32_t, void*,
    const cuuint64_t*, const cuuint64_t*, const cuuint32_t*, const cuuint32_t*,
    CUtensorMapInterleave, CUtensorMapSwizzle, CUtensorMapL2promotion,
    CUtensorMapFloatOOBfill);

static PFN_encodeTiled get_encoder() {
    static PFN_encodeTiled fn = nullptr;
    if (!fn) {
        void* p = nullptr;
        cudaDriverEntryPointQueryResult st;
        cudaGetDriverEntryPointByVersion("cuTensorMapEncodeTiled", &p, 12000,
                                         cudaEnableDefault, &st);
        fn = (PFN_encodeTiled)p;
    }
    return fn;
}

static void make_map(CUtensorMap* m, void* base, uint64_t rows) {
    cuuint64_t dims[2]    = {1024, rows};
    cuuint64_t strides[1] = {2048};
    cuuint32_t box[2]     = {32, 128};
    cuuint32_t es[2]      = {1, 1};
    get_encoder()(m, CU_TENSOR_MAP_DATA_TYPE_FLOAT16, 2, base, dims, strides,
                  box, es, CU_TENSOR_MAP_INTERLEAVE_NONE,
                  CU_TENSOR_MAP_SWIZZLE_64B, CU_TENSOR_MAP_L2_PROMOTION_L2_128B,
                  CU_TENSOR_MAP_FLOAT_OOB_FILL_NONE);
}

// ---------------------------------------------------------------------------
extern "C" void kernel_launch(void* const* d_in, const int* in_sizes, int n_in,
                              void* d_out, int out_size)
{
    const float* x    = (const float*)d_in[0];
    const float* mask = (const float*)d_in[1];
    const float* Wq   = (const float*)d_in[2];
    const float* bq   = (const float*)d_in[3];
    const float* Wk   = (const float*)d_in[4];
    const float* bk   = (const float*)d_in[5];
    const float* Wv   = (const float*)d_in[6];
    const float* bv   = (const float*)d_in[7];
    const float* Wo   = (const float*)d_in[8];
    const float* bo   = (const float*)d_in[9];
    const float* Wg   = (const float*)d_in[10];
    const float* bg   = (const float*)d_in[11];
    const float* df   = (const float*)d_in[12];
    const float* gw   = (const float*)d_in[13];
    float* out = (float*)d_out;

    float *q, *k, *v, *kvp, *kv, *ksp, *ks, *gate;
    float2* tab;
    __half *af, *bqh, *bql, *bkh, *bkl, *bvh, *bvl, *boh, *bol;
    cudaGetSymbolAddress((void**)&q,    g_q);
    cudaGetSymbolAddress((void**)&k,    g_k);
    cudaGetSymbolAddress((void**)&v,    g_v);
    cudaGetSymbolAddress((void**)&kvp,  g_kv_part);
    cudaGetSymbolAddress((void**)&kv,   g_kv);
    cudaGetSymbolAddress((void**)&ksp,  g_ksum_part);
    cudaGetSymbolAddress((void**)&ks,   g_ksum);
    cudaGetSymbolAddress((void**)&gate, g_gate);
    cudaGetSymbolAddress((void**)&tab,  g_rope);
    cudaGetSymbolAddress((void**)&af,   g_af);
    cudaGetSymbolAddress((void**)&bqh,  g_bqh);
    cudaGetSymbolAddress((void**)&bql,  g_bql);
    cudaGetSymbolAddress((void**)&bkh,  g_bkh);
    cudaGetSymbolAddress((void**)&bkl,  g_bkl);
    cudaGetSymbolAddress((void**)&bvh,  g_bvh);
    cudaGetSymbolAddress((void**)&bvl,  g_bvl);
    cudaGetSymbolAddress((void**)&boh,  g_boh);
    cudaGetSymbolAddress((void**)&bol,  g_bol);

    CUtensorMap mAf, mQh, mQl, mKh, mKl, mVh, mVl, mOh, mOl;
    make_map(&mAf, af, Msz);
    make_map(&mQh, bqh, Hsz); make_map(&mQl, bql, Hsz);
    make_map(&mKh, bkh, Hsz); make_map(&mKl, bkl, Hsz);
    make_map(&mVh, bvh, Hsz); make_map(&mVl, bvl, Hsz);
    make_map(&mOh, boh, Hsz); make_map(&mOl, bol, Hsz);

    cudaFuncSetAttribute(gemm_f16x2,
                         cudaFuncAttributeMaxDynamicSharedMemorySize, SMEM_F16);

    // 1. rope table
    rope_table_kernel<<<Ssz * 32 / 256, 256>>>(tab);
    // 2. activation -> single fp16 + gate
    cvt_x_gate<<<Msz, 256>>>((const float4*)x, (const float4*)Wg, bg,
                             (uint2*)af, gate);
    // 3. weight conversions: all fp16 hi/lo
    cvt_w4<<<dim3(32, 32, 4), dim3(32, 8)>>>(Wq, Wk, Wv, Wo,
                                             bqh, bql, bkh, bkl,
                                             bvh, bvl, boh, bol);
    // 4. fused QKV projection + rope/phi/mask epilogue  (profiled launch)
    gemm_f16x2<<<dim3(8, 64, 3), 256, SMEM_F16>>>(
        mAf, mQh, mQl, mKh, mKl, mVh, mVl, bq, bk, bv, q, k, v, mask, tab, 0);
    // 5-6. kv aggregation
    kv_partial_kernel<<<dim3(64, 8), 256>>>(k, v, kvp, ksp);
    kv_reduce_kernel<<<64, 256>>>(kvp, ksp, kv, ks);
    // 7. combine writes single fp16 into af
    combine_kernel<<<dim3(64, Ssz / 64), 256>>>(q, kv, ks, gate, df, gw, af);
    // 8. output projection (fp16x2)
    gemm_f16x2<<<dim3(8, 64, 1), 256, SMEM_F16>>>(
        mAf, mOh, mOl, mOh, mOl, mOh, mOl, bo, bo, bo, out, out, out,
        mask, tab, 1);
}

// round 9
// speedup vs baseline: 3.9167x; 1.1358x over previous
#include <cuda_runtime.h>
#include <cuda.h>
#include <cuda_bf16.h>
#include <cuda_fp16.h>
#include <math.h>
#include <stdint.h>

// Problem constants
#define Bsz 4
#define Ssz 2048
#define Hsz 1024
#define Nh  16
#define Dh  64
#define Msz (Bsz*Ssz)      // 8192
#define EPSF 1e-6f

// ---------------- scratch (static device globals; no allocs allowed) -------
__device__ float g_q[Msz*Hsz];
__device__ float g_k[Msz*Hsz];
__device__ float g_v[Msz*Hsz];
__device__ float g_kv_part[8*64*64*64];
__device__ float g_kv[64*64*64];
__device__ float g_ksum_part[8*64*64];
__device__ float g_ksum[64*64];
__device__ float g_gate[Msz];
__device__ float2 g_rope[Ssz*32];         // (cos, sin) per (s, i)
// fp16 operand buffers
__device__ __half g_af[Msz*Hsz];          // x fp16 (QKV phase), comb fp16 after
__device__ __half g_bq16[Hsz*Hsz];        // Wq single fp16 [N][K]
__device__ __half g_bk16[Hsz*Hsz];        // Wk single fp16
__device__ __half g_bv16[Hsz*Hsz];        // Wv single fp16
__device__ __half g_boh[Hsz*Hsz];         // Wo fp16 hi
__device__ __half g_bol[Hsz*Hsz];         // Wo fp16 lo

// ================= low-level helpers =======================================
static __device__ __forceinline__ uint32_t s2u(const void* p) {
    uint32_t a;
    asm("{ .reg .u64 t; cvta.to.shared.u64 t, %1; cvt.u32.u64 %0, t; }"
        : "=r"(a) : "l"(p));
    return a;
}

static __device__ __forceinline__ void ldsm4(uint32_t* r, uint32_t addr) {
    asm volatile("ldmatrix.sync.aligned.m8n8.x4.shared.b16 {%0,%1,%2,%3}, [%4];"
                 : "=r"(r[0]), "=r"(r[1]), "=r"(r[2]), "=r"(r[3]) : "r"(addr));
}

static __device__ __forceinline__ void mma16816h(float* d, const uint32_t* a,
                                                 const uint32_t* b) {
    asm volatile(
        "mma.sync.aligned.m16n8k16.row.col.f32.f16.f16.f32 "
        "{%0,%1,%2,%3}, {%4,%5,%6,%7}, {%8,%9}, {%0,%1,%2,%3};"
        : "+f"(d[0]), "+f"(d[1]), "+f"(d[2]), "+f"(d[3])
        : "r"(a[0]), "r"(a[1]), "r"(a[2]), "r"(a[3]), "r"(b[0]), "r"(b[1]));
}

// smem tile: [128 rows][32 elems = 64B], SW64 swizzle: chunk16 ^= (row>>1)&3
static __device__ __forceinline__ uint32_t swoff(int row, int c16) {
    return (uint32_t)(row * 64 + ((c16 ^ ((row >> 1) & 3)) << 4));
}

#define MBAR_INIT(m, c) \
    asm volatile("mbarrier.init.shared.b64 [%0], %1;" \
                 :: "r"((uint32_t)(m)), "r"((uint32_t)(c)) : "memory")
#define MBAR_EXPECT(m, b) \
    asm volatile("mbarrier.arrive.expect_tx.shared.b64 _, [%0], %1;" \
                 :: "r"((uint32_t)(m)), "r"((uint32_t)(b)) : "memory")

static __device__ __forceinline__ void mbar_wait(uint32_t mbar, uint32_t parity) {
    asm volatile(
        "{\n\t.reg .pred P;\n\t"
        "WL_%=:\n\t"
        "mbarrier.try_wait.parity.acquire.cta.shared::cta.b64 P, [%0], %1, 0x989680;\n\t"
        "@P bra.uni WD_%=;\n\t"
        "bra.uni WL_%=;\n\t"
        "WD_%=:\n\t}"
        :: "r"(mbar), "r"(parity) : "memory");
}

#define TMA2D(sa, mp, cx, cy, mb) \
    asm volatile("cp.async.bulk.tensor.2d.shared::cta.global.tile.mbarrier::complete_tx::bytes " \
                 "[%0], [%1, {%2, %3}], [%4];" \
                 :: "r"((uint32_t)(sa)), "l"(mp), "r"((int)(cx)), "r"((int)(cy)), \
                    "r"((uint32_t)(mb)) : "memory")

__device__ __forceinline__ float phi_fn(float x) {
    float t = (x > 0.f) ? x : expm1f(x);
    return (t + 1.0f) + EPSF;
}

#define NCHUNK 32

// ========== QKV GEMM: single-product fp16, 6-stage, __syncthreads ==========
// q/k/v[8192,1024] = Af @ B^T + bias, fused rope/phi/mask epilogue.
// Stage = 16KB (Af 8K | B 8K). Refill gated by __syncthreads (deterministic,
// validated R4-R6 pattern).
#define QSTAGES 6
#define QSTAGE_B 16384
#define SMEM_QKV (QSTAGES * QSTAGE_B + 64)

__global__ __launch_bounds__(256, 2)
void gemm_qkv(const __grid_constant__ CUtensorMap mAf,
              const __grid_constant__ CUtensorMap mB0,
              const __grid_constant__ CUtensorMap mB1,
              const __grid_constant__ CUtensorMap mB2,
              const float* __restrict__ b0, const float* __restrict__ b1,
              const float* __restrict__ b2,
              float* __restrict__ C0, float* __restrict__ C1,
              float* __restrict__ C2,
              const float* __restrict__ maskp,
              const float2* __restrict__ tab)
{
    extern __shared__ __align__(1024) char smem[];
    const uint32_t sbase = s2u(smem);
    const uint32_t mbb  = sbase + QSTAGES * QSTAGE_B;
    const int tid = threadIdx.x;
    const int lane = tid & 31, wid = tid >> 5;
    const int wm = wid & 3, wn = wid >> 2;
    const int n0 = blockIdx.x * 128, m0 = blockIdx.y * 128;
    const int z = blockIdx.z;

    const CUtensorMap* pB = (z == 0) ? &mB0 : (z == 1) ? &mB1 : &mB2;
    const float* bias = (z == 0) ? b0 : (z == 1) ? b1 : b2;
    float* C = (z == 0) ? C0 : (z == 1) ? C1 : C2;

    const int a_row  = wm * 32 + (lane & 15);
    const int a_c16h = lane >> 4;
    const int b_row  = wn * 64 + ((lane >> 4) << 3) + (lane & 7);
    const int b_c16h = (lane >> 3) & 1;

    float acc[2][8][4];
#pragma unroll
    for (int mi = 0; mi < 2; mi++)
#pragma unroll
        for (int ni = 0; ni < 8; ni++)
#pragma unroll
            for (int u = 0; u < 4; u++) acc[mi][ni][u] = 0.f;

    if (tid == 0) {
#pragma unroll
        for (int s = 0; s < QSTAGES; s++) MBAR_INIT(mbb + s * 8, 1);
    }
    __syncthreads();

    if (tid == 0) {
#pragma unroll
        for (int s = 0; s < QSTAGES; s++) {
            const uint32_t db = sbase + s * QSTAGE_B;
            MBAR_EXPECT(mbb + s * 8, QSTAGE_B);
            TMA2D(db,        &mAf, s * 32, m0, mbb + s * 8);
            TMA2D(db + 8192, pB,   s * 32, n0, mbb + s * 8);
        }
    }

    int s = 0, ph = 0;
    for (int it = 0; it < NCHUNK; it++) {
        mbar_wait(mbb + s * 8, ph);

        const uint32_t base = sbase + s * QSTAGE_B;
#pragma unroll
        for (int ks = 0; ks < 2; ks++) {
            uint32_t aF[2][4];
            ldsm4(aF[0], base + swoff(a_row,      ks * 2 + a_c16h));
            ldsm4(aF[1], base + swoff(a_row + 16, ks * 2 + a_c16h));
#pragma unroll
            for (int np = 0; np < 2; np++) {
                const int j0 = np * 4;
                uint32_t b0r[4], b1r[4];
                ldsm4(b0r, base + 8192 + swoff(b_row + (2*np)   * 16, ks * 2 + b_c16h));
                ldsm4(b1r, base + 8192 + swoff(b_row + (2*np+1) * 16, ks * 2 + b_c16h));
                mma16816h(acc[0][j0+0], aF[0], b0r + 0);
                mma16816h(acc[0][j0+1], aF[0], b0r + 2);
                mma16816h(acc[0][j0+2], aF[0], b1r + 0);
                mma16816h(acc[0][j0+3], aF[0], b1r + 2);
                mma16816h(acc[1][j0+0], aF[1], b0r + 0);
                mma16816h(acc[1][j0+1], aF[1], b0r + 2);
                mma16816h(acc[1][j0+2], aF[1], b1r + 0);
                mma16816h(acc[1][j0+3], aF[1], b1r + 2);
            }
        }
        __syncthreads();   // all readers done with stage s before refill

        const int nc = it + QSTAGES;
        if (nc < NCHUNK && tid == 0) {
            const uint32_t db = sbase + s * QSTAGE_B;
            MBAR_EXPECT(mbb + s * 8, QSTAGE_B);
            TMA2D(db,        &mAf, nc * 32, m0, mbb + s * 8);
            TMA2D(db + 8192, pB,   nc * 32, n0, mbb + s * 8);
        }
        if (++s == QSTAGES) { s = 0; ph ^= 1; }
    }

    // fused QKV epilogue (validated layout)
    const int r0 = m0 + wm * 32 + (lane >> 2);
    const int nb0 = n0 + wn * 64 + 2 * (lane & 3);
#pragma unroll
    for (int mi = 0; mi < 2; mi++) {
#pragma unroll
        for (int uu = 0; uu < 4; uu += 2) {
            const int r = r0 + mi * 16 + (uu ? 8 : 0);
            const int srow = r & (Ssz - 1);
            const float msk = maskp[r];
            if (z == 2) {
#pragma unroll
                for (int ni = 0; ni < 8; ni++) {
                    const int c = nb0 + ni * 8;
                    float v0 = (acc[mi][ni][uu+0] + bias[c])     * msk;
                    float v1 = (acc[mi][ni][uu+1] + bias[c + 1]) * msk;
                    *(float2*)(C + (long)r * 1024 + c) = make_float2(v0, v1);
                }
            } else {
                const float scale = (z == 0) ? 0.125f : msk;
#pragma unroll
                for (int ni = 0; ni < 4; ni++) {
                    float o1[2], o2[2];
#pragma unroll
                    for (int e = 0; e < 2; e++) {
                        const int i = 2 * (lane & 3) + ni * 8 + e;
                        const int c = nb0 + ni * 8 + e;
                        float x1 = acc[mi][ni][uu + e]     + bias[c];
                        float x2 = acc[mi][ni + 4][uu + e] + bias[c + 32];
                        float2 cs = tab[srow * 32 + i];
                        float r1 = x1 * cs.x - x2 * cs.y;
                        float r2 = x2 * cs.x + x1 * cs.y;
                        o1[e] = phi_fn(r1) * scale;
                        o2[e] = phi_fn(r2) * scale;
                    }
                    const int c = nb0 + ni * 8;
                    *(float2*)(C + (long)r * 1024 + c)      = make_float2(o1[0], o1[1]);
                    *(float2*)(C + (long)r * 1024 + c + 32) = make_float2(o2[0], o2[1]);
                }
            }
        }
    }
}

// ======= OUT GEMM: fp16 two-product (A single, Wo hi/lo), 4-stage ==========
#define OSTAGES 4
#define OSTAGE_B 24576
#define SMEM_OUT (OSTAGES * OSTAGE_B + 64)

__global__ __launch_bounds__(256, 2)
void gemm_out(const __grid_constant__ CUtensorMap mAf,
              const __grid_constant__ CUtensorMap mBh,
              const __grid_constant__ CUtensorMap mBl,
              const float* __restrict__ bias, float* __restrict__ C)
{
    extern __shared__ __align__(1024) char smem[];
    const uint32_t sbase = s2u(smem);
    const uint32_t mbb  = sbase + OSTAGES * OSTAGE_B;
    const int tid = threadIdx.x;
    const int lane = tid & 31, wid = tid >> 5;
    const int wm = wid & 3, wn = wid >> 2;
    const int n0 = blockIdx.x * 128, m0 = blockIdx.y * 128;

    const int a_row  = wm * 32 + (lane & 15);
    const int a_c16h = lane >> 4;
    const int b_row  = wn * 64 + ((lane >> 4) << 3) + (lane & 7);
    const int b_c16h = (lane >> 3) & 1;

    float acc[2][8][4];
#pragma unroll
    for (int mi = 0; mi < 2; mi++)
#pragma unroll
        for (int ni = 0; ni < 8; ni++)
#pragma unroll
            for (int u = 0; u < 4; u++) acc[mi][ni][u] = 0.f;

    if (tid == 0) {
#pragma unroll
        for (int s = 0; s < OSTAGES; s++) MBAR_INIT(mbb + s * 8, 1);
    }
    __syncthreads();

    if (tid == 0) {
#pragma unroll
        for (int s = 0; s < OSTAGES; s++) {
            const uint32_t db = sbase + s * OSTAGE_B;
            MBAR_EXPECT(mbb + s * 8, OSTAGE_B);
            TMA2D(db,         &mAf, s * 32, m0, mbb + s * 8);
            TMA2D(db + 8192,  &mBh, s * 32, n0, mbb + s * 8);
            TMA2D(db + 16384, &mBl, s * 32, n0, mbb + s * 8);
        }
    }

    for (int it = 0; it < NCHUNK; it++) {
        const int s = it & 3;
        mbar_wait(mbb + s * 8, (it >> 2) & 1);

        const uint32_t base = sbase + s * OSTAGE_B;
#pragma unroll
        for (int ks = 0; ks < 2; ks++) {
            uint32_t aF[2][4];
            ldsm4(aF[0], base + swoff(a_row,      ks * 2 + a_c16h));
            ldsm4(aF[1], base + swoff(a_row + 16, ks * 2 + a_c16h));
#pragma unroll
            for (int np = 0; np < 2; np++) {
                const int j0 = np * 4;
                uint32_t bH0[4], bH1[4], bL0[4], bL1[4];
                ldsm4(bH0, base + 8192 + swoff(b_row + (2*np)   * 16, ks * 2 + b_c16h));
                ldsm4(bH1, base + 8192 + swoff(b_row + (2*np+1) * 16, ks * 2 + b_c16h));
                mma16816h(acc[0][j0+0], aF[0], bH0 + 0);
                mma16816h(acc[0][j0+1], aF[0], bH0 + 2);
                mma16816h(acc[0][j0+2], aF[0], bH1 + 0);
                mma16816h(acc[0][j0+3], aF[0], bH1 + 2);
                mma16816h(acc[1][j0+0], aF[1], bH0 + 0);
                mma16816h(acc[1][j0+1], aF[1], bH0 + 2);
                mma16816h(acc[1][j0+2], aF[1], bH1 + 0);
                mma16816h(acc[1][j0+3], aF[1], bH1 + 2);
                ldsm4(bL0, base + 16384 + swoff(b_row + (2*np)   * 16, ks * 2 + b_c16h));
                ldsm4(bL1, base + 16384 + swoff(b_row + (2*np+1) * 16, ks * 2 + b_c16h));
                mma16816h(acc[0][j0+0], aF[0], bL0 + 0);
                mma16816h(acc[0][j0+1], aF[0], bL0 + 2);
                mma16816h(acc[0][j0+2], aF[0], bL1 + 0);
                mma16816h(acc[0][j0+3], aF[0], bL1 + 2);
                mma16816h(acc[1][j0+0], aF[1], bL0 + 0);
                mma16816h(acc[1][j0+1], aF[1], bL0 + 2);
                mma16816h(acc[1][j0+2], aF[1], bL1 + 0);
                mma16816h(acc[1][j0+3], aF[1], bL1 + 2);
            }
        }
        __syncthreads();   // all readers done with stage s before refill

        const int nc = it + OSTAGES;
        if (nc < NCHUNK && tid == 0) {
            const uint32_t db = sbase + s * OSTAGE_B;
            MBAR_EXPECT(mbb + s * 8, OSTAGE_B);
            TMA2D(db,         &mAf, nc * 32, m0, mbb + s * 8);
            TMA2D(db + 8192,  &mBh, nc * 32, n0, mbb + s * 8);
            TMA2D(db + 16384, &mBl, nc * 32, n0, mbb + s * 8);
        }
    }

    const int r0 = m0 + wm * 32 + (lane >> 2);
    const int nb0 = n0 + wn * 64 + 2 * (lane & 3);
#pragma unroll
    for (int mi = 0; mi < 2; mi++) {
#pragma unroll
        for (int ni = 0; ni < 8; ni++) {
            const int r = r0 + mi * 16;
            const int c = nb0 + ni * 8;
            float2 bb = *(const float2*)(bias + c);
            *(float2*)(C + (long)r * 1024 + c) =
                make_float2(acc[mi][ni][0] + bb.x, acc[mi][ni][1] + bb.y);
            *(float2*)(C + (long)(r + 8) * 1024 + c) =
                make_float2(acc[mi][ni][2] + bb.x, acc[mi][ni][3] + bb.y);
        }
    }
}

// ================= rope table ==============================================
__global__ void rope_table_kernel(float2* __restrict__ tab)
{
    const int idx = blockIdx.x * 256 + threadIdx.x;   // 65536
    const int i = idx & 31, s = idx >> 5;
    double p = pow(10000.0, (double)(2 * i) / 64.0);
    float f = (float)s * (1.0f / (float)p);
    tab[idx] = make_float2(cosf(f), sinf(f));
}

// ============ cvt x -> single fp16 + gate (one block per row) ==============
__global__ void cvt_x_gate(const float4* __restrict__ x,
                           const float4* __restrict__ Wg,
                           const float* __restrict__ bg,
                           uint2* __restrict__ xf,
                           float* __restrict__ gout)
{
    const int row = blockIdx.x;
    const int tid = threadIdx.x;
    const long i = (long)row * 256 + tid;
    float4 v = x[i];
    float4 w = Wg[tid];
    float dot = v.x * w.x + v.y * w.y + v.z * w.z + v.w * w.w;

    float f[4] = {v.x, v.y, v.z, v.w};
    unsigned short hs[4];
#pragma unroll
    for (int j = 0; j < 4; j++) {
        __half h = __float2half(f[j]);
        hs[j] = *(unsigned short*)&h;
    }
    uint2 H;
    H.x = (uint32_t)hs[0] | ((uint32_t)hs[1] << 16);
    H.y = (uint32_t)hs[2] | ((uint32_t)hs[3] << 16);
    xf[i] = H;

#pragma unroll
    for (int o = 16; o; o >>= 1) dot += __shfl_down_sync(0xffffffffu, dot, o);
    __shared__ float ws[8];
    if ((tid & 31) == 0) ws[tid >> 5] = dot;
    __syncthreads();
    if (tid == 0) {
        float t = 0.f;
#pragma unroll
        for (int j = 0; j < 8; j++) t += ws[j];
        t += bg[0];
        gout[row] = 1.f / (1.f + expf(-t));
    }
}

// W[K][N] fp32 -> transposed fp16 [N][K]; z<3 single, z==3 (Wo) hi+lo
__global__ void cvt_w4(const float* __restrict__ W0, const float* __restrict__ W1,
                       const float* __restrict__ W2, const float* __restrict__ W3,
                       __half* __restrict__ h0, __half* __restrict__ h1,
                       __half* __restrict__ h2,
                       __half* __restrict__ h3, __half* __restrict__ l3)
{
    const int z = blockIdx.z;
    const float* W = (z == 0) ? W0 : (z == 1) ? W1 : (z == 2) ? W2 : W3;
    __half* bh = (z == 0) ? h0 : (z == 1) ? h1 : (z == 2) ? h2 : h3;

    __shared__ float t[32][33];
    const int nx = blockIdx.x * 32, kx = blockIdx.y * 32;
    const int tx = threadIdx.x, ty = threadIdx.y;   // 32 x 8
#pragma unroll
    for (int r = 0; r < 32; r += 8)
        t[ty + r][tx] = W[(long)(kx + ty + r) * 1024 + nx + tx];
    __syncthreads();
#pragma unroll
    for (int r = 0; r < 32; r += 8) {
        float v = t[tx][ty + r];
        long o = (long)(nx + ty + r) * 1024 + kx + tx;
        __half h = __float2half(v);
        bh[o] = h;
        if (z == 3) {
            float rr = v - __half2float(h);
            l3[o] = __float2half(rr);
        }
    }
}

// ---------------- kv partial: per (b,n,chunk) 64x64 outer-product sum ------
__global__ void kv_partial_kernel(const float* __restrict__ k,
                                  const float* __restrict__ v,
                                  float* __restrict__ kv_part,
                                  float* __restrict__ ksum_part)
{
    const int bn = blockIdx.x;
    const int c  = blockIdx.y;
    const int b = bn >> 4, n = bn & 15;
    __shared__ float ks[32][64];
    __shared__ float vs[32][64];
    const int tid = threadIdx.x;
    const int ti = tid >> 4, tj = tid & 15;

    float acc[4][4];
#pragma unroll
    for (int a = 0; a < 4; a++)
#pragma unroll
        for (int d = 0; d < 4; d++) acc[a][d] = 0.f;
    float ksum = 0.f;

    const int s0 = c * 256;
    for (int so = 0; so < 256; so += 32) {
#pragma unroll
        for (int e = tid; e < 512; e += 256) {
            int sl = e >> 4, dd = (e & 15) * 4;
            long gb = (((long)(b * Ssz + s0 + so + sl) * Nh) + n) * Dh + dd;
            *(float4*)&ks[sl][dd] = *(const float4*)&k[gb];
            *(float4*)&vs[sl][dd] = *(const float4*)&v[gb];
        }
        __syncthreads();
#pragma unroll 4
        for (int sl = 0; sl < 32; ++sl) {
            float4 kk4 = *(const float4*)&ks[sl][ti * 4];
            float4 vv4 = *(const float4*)&vs[sl][tj * 4];
            float ka[4] = {kk4.x, kk4.y, kk4.z, kk4.w};
            float va[4] = {vv4.x, vv4.y, vv4.z, vv4.w};
#pragma unroll
            for (int a = 0; a < 4; a++)
#pragma unroll
                for (int d = 0; d < 4; d++) acc[a][d] += ka[a] * va[d];
        }
        if (tid < 64) {
#pragma unroll 4
            for (int sl = 0; sl < 32; ++sl) ksum += ks[sl][tid];
        }
        __syncthreads();
    }

    const long pbase = ((long)c * 64 + bn) * 4096;
#pragma unroll
    for (int a = 0; a < 4; a++) {
        float4 o = make_float4(acc[a][0], acc[a][1], acc[a][2], acc[a][3]);
        *(float4*)&kv_part[pbase + (ti * 4 + a) * 64 + tj * 4] = o;
    }
    if (tid < 64) ksum_part[(c * 64 + bn) * 64 + tid] = ksum;
}

__global__ void kv_reduce_kernel(const float* __restrict__ kv_part,
                                 const float* __restrict__ ksum_part,
                                 float* __restrict__ kv,
                                 float* __restrict__ ksum)
{
    const int bn = blockIdx.x;
    const int tid = threadIdx.x;
    for (int e = tid; e < 4096; e += 256) {
        float s = 0.f;
#pragma unroll
        for (int c = 0; c < 8; ++c) s += kv_part[((long)c * 64 + bn) * 4096 + e];
        kv[(long)bn * 4096 + e] = s;
    }
    if (tid < 64) {
        float s = 0.f;
#pragma unroll
        for (int c = 0; c < 8; ++c) s += ksum_part[(c * 64 + bn) * 64 + tid];
        ksum[bn * 64 + tid] = s;
    }
}

// ---- combine: num=q@kv; den=q.ksum+eps; gate mix; write single fp16 -------
__global__ void combine_kernel(const float* __restrict__ q,
                               const float* __restrict__ kv,
                               const float* __restrict__ ksum,
                               const float* __restrict__ gate,
                               const float* __restrict__ df,
                               const float* __restrict__ gw,
                               __half* __restrict__ cf)
{
    const int bn = blockIdx.x;
    const int st = blockIdx.y;
    const int b = bn >> 4, n = bn & 15;

    __shared__ float qs[64][68];
    __shared__ float kvs[64][64];
    __shared__ float ksums[64];

    const int tid = threadIdx.x;

    float w0 = gw[0], w1 = gw[1], w2 = gw[2];
    float d0 = df[0], d1 = df[1], d2 = df[2];
    float mx = fmaxf(w0, fmaxf(w1, w2));
    float e0 = expf(w0 - mx), e1 = expf(w1 - mx), e2 = expf(w2 - mx);
    float s0f = 1.f / (1.f + expf(-d0));
    float s1f = 1.f / (1.f + expf(-d1));
    float s2f = 1.f / (1.f + expf(-d2));
    float coef = (e0 * (1.f - s0f) + e1 * (1.f - s1f) + e2 * (1.f - s2f)) / (e0 + e1 + e2);

    const long kvbase = (long)bn * 4096;
    for (int e = tid; e < 1024; e += 256)
        ((float4*)kvs)[e] = ((const float4*)(kv + kvbase))[e];
    if (tid < 64) ksums[tid] = ksum[bn * 64 + tid];

    const int srow0 = st * 64;
    for (int e = tid; e < 1024; e += 256) {
        int r = e >> 4, dd = (e & 15) * 4;
        long gq = (((long)(b * Ssz + srow0 + r) * Nh) + n) * Dh + dd;
        *(float4*)&qs[r][dd] = *(const float4*)&q[gq];
    }
    __syncthreads();

    const int sl = tid >> 2;
    const int jg = tid & 3;
    float acc[16];
#pragma unroll
    for (int j = 0; j < 16; j++) acc[j] = 0.f;
    float den = 0.f;

#pragma unroll 4
    for (int kk = 0; kk < 64; ++kk) {
        float qv = qs[sl][kk];
        den += qv * ksums[kk];
        const float4* kr = (const float4*)&kvs[kk][jg * 16];
        float4 c0 = kr[0], c1 = kr[1], c2 = kr[2], c3 = kr[3];
        acc[0]  += qv * c0.x; acc[1]  += qv * c0.y; acc[2]  += qv * c0.z; acc[3]  += qv * c0.w;
        acc[4]  += qv * c1.x; acc[5]  += qv * c1.y; acc[6]  += qv * c1.z; acc[7]  += qv * c1.w;
        acc[8]  += qv * c2.x; acc[9]  += qv * c2.y; acc[10] += qv * c2.z; acc[11] += qv * c2.w;
        acc[12] += qv * c3.x; acc[13] += qv * c3.y; acc[14] += qv * c3.z; acc[15] += qv * c3.w;
    }
    den += EPSF;

    const int srow = srow0 + sl;
    const float g = gate[b * Ssz + srow];
    const float fac = g / den + (1.f - g) * coef;

    const long obase = (((long)(b * Ssz + srow) * Nh) + n) * Dh + jg * 16;
#pragma unroll
    for (int u = 0; u < 4; u++) {
        unsigned short hs[4];
#pragma unroll
        for (int e = 0; e < 4; e++) {
            __half h = __float2half(acc[u * 4 + e] * fac);
            hs[e] = *(unsigned short*)&h;
        }
        uint2 H;
        H.x = (uint32_t)hs[0] | ((uint32_t)hs[1] << 16);
        H.y = (uint32_t)hs[2] | ((uint32_t)hs[3] << 16);
        *(uint2*)(cf + obase + u * 4) = H;
    }
}

// ================= host: tensormap construction ============================
typedef CUresult (*PFN_encodeTiled)(
    CUtensorMap*, CUtensorMapDataType, cuuint32_t, void*,
    const cuuint64_t*, const cuuint64_t*, const cuuint32_t*, const cuuint32_t*,
    CUtensorMapInterleave, CUtensorMapSwizzle, CUtensorMapL2promotion,
    CUtensorMapFloatOOBfill);

static PFN_encodeTiled get_encoder() {
    static PFN_encodeTiled fn = nullptr;
    if (!fn) {
        void* p = nullptr;
        cudaDriverEntryPointQueryResult st;
        cudaGetDriverEntryPointByVersion("cuTensorMapEncodeTiled", &p, 12000,
                                         cudaEnableDefault, &st);
        fn = (PFN_encodeTiled)p;
    }
    return fn;
}

static void make_map(CUtensorMap* m, void* base, uint64_t rows) {
    cuuint64_t dims[2]    = {1024, rows};
    cuuint64_t strides[1] = {2048};
    cuuint32_t box[2]     = {32, 128};
    cuuint32_t es[2]      = {1, 1};
    get_encoder()(m, CU_TENSOR_MAP_DATA_TYPE_FLOAT16, 2, base, dims, strides,
                  box, es, CU_TENSOR_MAP_INTERLEAVE_NONE,
                  CU_TENSOR_MAP_SWIZZLE_64B, CU_TENSOR_MAP_L2_PROMOTION_L2_128B,
                  CU_TENSOR_MAP_FLOAT_OOB_FILL_NONE);
}

// ---------------------------------------------------------------------------
extern "C" void kernel_launch(void* const* d_in, const int* in_sizes, int n_in,
                              void* d_out, int out_size)
{
    const float* x    = (const float*)d_in[0];
    const float* mask = (const float*)d_in[1];
    const float* Wq   = (const float*)d_in[2];
    const float* bq   = (const float*)d_in[3];
    const float* Wk   = (const float*)d_in[4];
    const float* bk   = (const float*)d_in[5];
    const float* Wv   = (const float*)d_in[6];
    const float* bv   = (const float*)d_in[7];
    const float* Wo   = (const float*)d_in[8];
    const float* bo   = (const float*)d_in[9];
    const float* Wg   = (const float*)d_in[10];
    const float* bg   = (const float*)d_in[11];
    const float* df   = (const float*)d_in[12];
    const float* gw   = (const float*)d_in[13];
    float* out = (float*)d_out;

    float *q, *k, *v, *kvp, *kv, *ksp, *ks, *gate;
    float2* tab;
    __half *af, *bq16, *bk16, *bv16, *boh, *bol;
    cudaGetSymbolAddress((void**)&q,    g_q);
    cudaGetSymbolAddress((void**)&k,    g_k);
    cudaGetSymbolAddress((void**)&v,    g_v);
    cudaGetSymbolAddress((void**)&kvp,  g_kv_part);
    cudaGetSymbolAddress((void**)&kv,   g_kv);
    cudaGetSymbolAddress((void**)&ksp,  g_ksum_part);
    cudaGetSymbolAddress((void**)&ks,   g_ksum);
    cudaGetSymbolAddress((void**)&gate, g_gate);
    cudaGetSymbolAddress((void**)&tab,  g_rope);
    cudaGetSymbolAddress((void**)&af,   g_af);
    cudaGetSymbolAddress((void**)&bq16, g_bq16);
    cudaGetSymbolAddress((void**)&bk16, g_bk16);
    cudaGetSymbolAddress((void**)&bv16, g_bv16);
    cudaGetSymbolAddress((void**)&boh,  g_boh);
    cudaGetSymbolAddress((void**)&bol,  g_bol);

    CUtensorMap mAf, mQ, mK, mV, mOh, mOl;
    make_map(&mAf, af, Msz);
    make_map(&mQ,  bq16, Hsz);
    make_map(&mK,  bk16, Hsz);
    make_map(&mV,  bv16, Hsz);
    make_map(&mOh, boh, Hsz);
    make_map(&mOl, bol, Hsz);

    cudaFuncSetAttribute(gemm_qkv,
                         cudaFuncAttributeMaxDynamicSharedMemorySize, SMEM_QKV);
    cudaFuncSetAttribute(gemm_out,
                         cudaFuncAttributeMaxDynamicSharedMemorySize, SMEM_OUT);

    // 1. rope table
    rope_table_kernel<<<Ssz * 32 / 256, 256>>>(tab);
    // 2. activation -> single fp16 + gate
    cvt_x_gate<<<Msz, 256>>>((const float4*)x, (const float4*)Wg, bg,
                             (uint2*)af, gate);
    // 3. weight conversions: Wq/Wk/Wv single fp16, Wo hi+lo
    cvt_w4<<<dim3(32, 32, 4), dim3(32, 8)>>>(Wq, Wk, Wv, Wo,
                                             bq16, bk16, bv16, boh, bol);
    // 4. fused QKV projection (single-product) + rope/phi/mask epilogue
    gemm_qkv<<<dim3(8, 64, 3), 256, SMEM_QKV>>>(
        mAf, mQ, mK, mV, bq, bk, bv, q, k, v, mask, tab);
    // 5-6. kv aggregation
    kv_partial_kernel<<<dim3(64, 8), 256>>>(k, v, kvp, ksp);
    kv_reduce_kernel<<<64, 256>>>(kvp, ksp, kv, ks);
    // 7. combine writes single fp16 into af
    combine_kernel<<<dim3(64, Ssz / 64), 256>>>(q, kv, ks, gate, df, gw, af);
    // 8. output projection (two-product: comb fp16 x (Wo_hi + Wo_lo))
    gemm_out<<<dim3(8, 64), 256, SMEM_OUT>>>(mAf, mOh, mOl, bo, out);
}

// round 10
// speedup vs baseline: 4.0504x; 1.0341x over previous
#include <cuda_runtime.h>
#include <cuda.h>
#include <cuda_bf16.h>
#include <cuda_fp16.h>
#include <math.h>
#include <stdint.h>

// Problem constants
#define Bsz 4
#define Ssz 2048
#define Hsz 1024
#define Nh  16
#define Dh  64
#define Msz (Bsz*Ssz)      // 8192
#define EPSF 1e-6f

// ---------------- scratch (static device globals; no allocs allowed) -------
__device__ __half g_q16[Msz*Hsz];         // q (phi'd, scaled) fp16
__device__ __half g_k16[Msz*Hsz];         // k (phi'd, masked) fp16
__device__ __half g_v16[Msz*Hsz];         // v (masked) fp16
__device__ float g_kv_part[8*64*64*64];
__device__ float g_kv[64*64*64];
__device__ float g_ksum_part[8*64*64];
__device__ float g_ksum[64*64];
__device__ float g_gate[Msz];
__device__ float2 g_rope[Ssz*32];         // (cos, sin) per (s, i)
// fp16 operand buffers
__device__ __half g_af[Msz*Hsz];          // x fp16 (QKV phase), comb fp16 after
__device__ __half g_bq16[Hsz*Hsz];        // Wq single fp16 [N][K]
__device__ __half g_bk16[Hsz*Hsz];        // Wk single fp16
__device__ __half g_bv16[Hsz*Hsz];        // Wv single fp16
__device__ __half g_boh[Hsz*Hsz];         // Wo fp16 hi
__device__ __half g_bol[Hsz*Hsz];         // Wo fp16 lo

// ================= low-level helpers =======================================
static __device__ __forceinline__ uint32_t s2u(const void* p) {
    uint32_t a;
    asm("{ .reg .u64 t; cvta.to.shared.u64 t, %1; cvt.u32.u64 %0, t; }"
        : "=r"(a) : "l"(p));
    return a;
}

static __device__ __forceinline__ void ldsm4(uint32_t* r, uint32_t addr) {
    asm volatile("ldmatrix.sync.aligned.m8n8.x4.shared.b16 {%0,%1,%2,%3}, [%4];"
                 : "=r"(r[0]), "=r"(r[1]), "=r"(r[2]), "=r"(r[3]) : "r"(addr));
}

static __device__ __forceinline__ void mma16816h(float* d, const uint32_t* a,
                                                 const uint32_t* b) {
    asm volatile(
        "mma.sync.aligned.m16n8k16.row.col.f32.f16.f16.f32 "
        "{%0,%1,%2,%3}, {%4,%5,%6,%7}, {%8,%9}, {%0,%1,%2,%3};"
        : "+f"(d[0]), "+f"(d[1]), "+f"(d[2]), "+f"(d[3])
        : "r"(a[0]), "r"(a[1]), "r"(a[2]), "r"(a[3]), "r"(b[0]), "r"(b[1]));
}

// smem tile: [128 rows][32 elems = 64B], SW64 swizzle: chunk16 ^= (row>>1)&3
static __device__ __forceinline__ uint32_t swoff(int row, int c16) {
    return (uint32_t)(row * 64 + ((c16 ^ ((row >> 1) & 3)) << 4));
}

#define MBAR_INIT(m, c) \
    asm volatile("mbarrier.init.shared.b64 [%0], %1;" \
                 :: "r"((uint32_t)(m)), "r"((uint32_t)(c)) : "memory")
#define MBAR_EXPECT(m, b) \
    asm volatile("mbarrier.arrive.expect_tx.shared.b64 _, [%0], %1;" \
                 :: "r"((uint32_t)(m)), "r"((uint32_t)(b)) : "memory")

static __device__ __forceinline__ void mbar_wait(uint32_t mbar, uint32_t parity) {
    asm volatile(
        "{\n\t.reg .pred P;\n\t"
        "WL_%=:\n\t"
        "mbarrier.try_wait.parity.acquire.cta.shared::cta.b64 P, [%0], %1, 0x989680;\n\t"
        "@P bra.uni WD_%=;\n\t"
        "bra.uni WL_%=;\n\t"
        "WD_%=:\n\t}"
        :: "r"(mbar), "r"(parity) : "memory");
}

#define TMA2D(sa, mp, cx, cy, mb) \
    asm volatile("cp.async.bulk.tensor.2d.shared::cta.global.tile.mbarrier::complete_tx::bytes " \
                 "[%0], [%1, {%2, %3}], [%4];" \
                 :: "r"((uint32_t)(sa)), "l"(mp), "r"((int)(cx)), "r"((int)(cy)), \
                    "r"((uint32_t)(mb)) : "memory")

__device__ __forceinline__ float phi_fn(float x) {
    float t = (x > 0.f) ? x : expm1f(x);
    return (t + 1.0f) + EPSF;
}

static __device__ __forceinline__ __half2 pack_h2(float a, float b) {
    return __halves2half2(__float2half(a), __float2half(b));
}

#define NCHUNK 32

// ========== QKV GEMM: single-product fp16, 6-stage, sync every 2 ==========
// q/k/v (fp16) = Af @ B^T + bias, fused rope/phi/mask epilogue.
// Stage = 16KB (Af 8K | B 8K). Refill of the two consumed stages gated by one
// __syncthreads every 2 chunks (deterministic; chunk c -> stage c % QSTAGES).
#define QSTAGES 6
#define QSTAGE_B 16384
#define SMEM_QKV (QSTAGES * QSTAGE_B + 64)

__global__ __launch_bounds__(256, 2)
void gemm_qkv(const __grid_constant__ CUtensorMap mAf,
              const __grid_constant__ CUtensorMap mB0,
              const __grid_constant__ CUtensorMap mB1,
              const __grid_constant__ CUtensorMap mB2,
              const float* __restrict__ b0, const float* __restrict__ b1,
              const float* __restrict__ b2,
              __half* __restrict__ C0, __half* __restrict__ C1,
              __half* __restrict__ C2,
              const float* __restrict__ maskp,
              const float2* __restrict__ tab)
{
    extern __shared__ __align__(1024) char smem[];
    const uint32_t sbase = s2u(smem);
    const uint32_t mbb  = sbase + QSTAGES * QSTAGE_B;
    const int tid = threadIdx.x;
    const int lane = tid & 31, wid = tid >> 5;
    const int wm = wid & 3, wn = wid >> 2;
    const int n0 = blockIdx.x * 128, m0 = blockIdx.y * 128;
    const int z = blockIdx.z;

    const CUtensorMap* pB = (z == 0) ? &mB0 : (z == 1) ? &mB1 : &mB2;
    const float* bias = (z == 0) ? b0 : (z == 1) ? b1 : b2;
    __half* C = (z == 0) ? C0 : (z == 1) ? C1 : C2;

    const int a_row  = wm * 32 + (lane & 15);
    const int a_c16h = lane >> 4;
    const int b_row  = wn * 64 + ((lane >> 4) << 3) + (lane & 7);
    const int b_c16h = (lane >> 3) & 1;

    float acc[2][8][4];
#pragma unroll
    for (int mi = 0; mi < 2; mi++)
#pragma unroll
        for (int ni = 0; ni < 8; ni++)
#pragma unroll
            for (int u = 0; u < 4; u++) acc[mi][ni][u] = 0.f;

    if (tid == 0) {
#pragma unroll
        for (int s = 0; s < QSTAGES; s++) MBAR_INIT(mbb + s * 8, 1);
    }
    __syncthreads();

    if (tid == 0) {
#pragma unroll
        for (int s = 0; s < QSTAGES; s++) {
            const uint32_t db = sbase + s * QSTAGE_B;
            MBAR_EXPECT(mbb + s * 8, QSTAGE_B);
            TMA2D(db,        &mAf, s * 32, m0, mbb + s * 8);
            TMA2D(db + 8192, pB,   s * 32, n0, mbb + s * 8);
        }
    }

    int s = 0, ph = 0;
    for (int it = 0; it < NCHUNK; it++) {
        mbar_wait(mbb + s * 8, ph);

        const uint32_t base = sbase + s * QSTAGE_B;
#pragma unroll
        for (int ks = 0; ks < 2; ks++) {
            uint32_t aF[2][4];
            ldsm4(aF[0], base + swoff(a_row,      ks * 2 + a_c16h));
            ldsm4(aF[1], base + swoff(a_row + 16, ks * 2 + a_c16h));
#pragma unroll
            for (int np = 0; np < 2; np++) {
                const int j0 = np * 4;
                uint32_t b0r[4], b1r[4];
                ldsm4(b0r, base + 8192 + swoff(b_row + (2*np)   * 16, ks * 2 + b_c16h));
                ldsm4(b1r, base + 8192 + swoff(b_row + (2*np+1) * 16, ks * 2 + b_c16h));
                mma16816h(acc[0][j0+0], aF[0], b0r + 0);
                mma16816h(acc[0][j0+1], aF[0], b0r + 2);
                mma16816h(acc[0][j0+2], aF[0], b1r + 0);
                mma16816h(acc[0][j0+3], aF[0], b1r + 2);
                mma16816h(acc[1][j0+0], aF[1], b0r + 0);
                mma16816h(acc[1][j0+1], aF[1], b0r + 2);
                mma16816h(acc[1][j0+2], aF[1], b1r + 0);
                mma16816h(acc[1][j0+3], aF[1], b1r + 2);
            }
        }

        if (it & 1) {
            __syncthreads();   // stages for chunks it-1, it fully consumed
            if (tid == 0) {
#pragma unroll
                for (int d = 0; d < 2; d++) {
                    const int nc = it - 1 + d + QSTAGES;
                    if (nc < NCHUNK) {
                        const int ts = nc % QSTAGES;
                        const uint32_t db = sbase + ts * QSTAGE_B;
                        MBAR_EXPECT(mbb + ts * 8, QSTAGE_B);
                        TMA2D(db,        &mAf, nc * 32, m0, mbb + ts * 8);
                        TMA2D(db + 8192, pB,   nc * 32, n0, mbb + ts * 8);
                    }
                }
            }
        }
        if (++s == QSTAGES) { s = 0; ph ^= 1; }
    }

    // fused QKV epilogue (validated layout), fp16 stores
    const int r0 = m0 + wm * 32 + (lane >> 2);
    const int nb0 = n0 + wn * 64 + 2 * (lane & 3);
#pragma unroll
    for (int mi = 0; mi < 2; mi++) {
#pragma unroll
        for (int uu = 0; uu < 4; uu += 2) {
            const int r = r0 + mi * 16 + (uu ? 8 : 0);
            const int srow = r & (Ssz - 1);
            const float msk = maskp[r];
            if (z == 2) {
#pragma unroll
                for (int ni = 0; ni < 8; ni++) {
                    const int c = nb0 + ni * 8;
                    float v0 = (acc[mi][ni][uu+0] + bias[c])     * msk;
                    float v1 = (acc[mi][ni][uu+1] + bias[c + 1]) * msk;
                    *(__half2*)(C + (long)r * 1024 + c) = pack_h2(v0, v1);
                }
            } else {
                const float scale = (z == 0) ? 0.125f : msk;
#pragma unroll
                for (int ni = 0; ni < 4; ni++) {
                    float o1[2], o2[2];
#pragma unroll
                    for (int e = 0; e < 2; e++) {
                        const int i = 2 * (lane & 3) + ni * 8 + e;
                        const int c = nb0 + ni * 8 + e;
                        float x1 = acc[mi][ni][uu + e]     + bias[c];
                        float x2 = acc[mi][ni + 4][uu + e] + bias[c + 32];
                        float2 cs = tab[srow * 32 + i];
                        float r1 = x1 * cs.x - x2 * cs.y;
                        float r2 = x2 * cs.x + x1 * cs.y;
                        o1[e] = phi_fn(r1) * scale;
                        o2[e] = phi_fn(r2) * scale;
                    }
                    const int c = nb0 + ni * 8;
                    *(__half2*)(C + (long)r * 1024 + c)      = pack_h2(o1[0], o1[1]);
                    *(__half2*)(C + (long)r * 1024 + c + 32) = pack_h2(o2[0], o2[1]);
                }
            }
        }
    }
}

// ======= OUT GEMM: fp16 two-product (A single, Wo hi/lo), 4-stage ==========
#define OSTAGES 4
#define OSTAGE_B 24576
#define SMEM_OUT (OSTAGES * OSTAGE_B + 64)

__global__ __launch_bounds__(256, 2)
void gemm_out(const __grid_constant__ CUtensorMap mAf,
              const __grid_constant__ CUtensorMap mBh,
              const __grid_constant__ CUtensorMap mBl,
              const float* __restrict__ bias, float* __restrict__ C)
{
    extern __shared__ __align__(1024) char smem[];
    const uint32_t sbase = s2u(smem);
    const uint32_t mbb  = sbase + OSTAGES * OSTAGE_B;
    const int tid = threadIdx.x;
    const int lane = tid & 31, wid = tid >> 5;
    const int wm = wid & 3, wn = wid >> 2;
    const int n0 = blockIdx.x * 128, m0 = blockIdx.y * 128;

    const int a_row  = wm * 32 + (lane & 15);
    const int a_c16h = lane >> 4;
    const int b_row  = wn * 64 + ((lane >> 4) << 3) + (lane & 7);
    const int b_c16h = (lane >> 3) & 1;

    float acc[2][8][4];
#pragma unroll
    for (int mi = 0; mi < 2; mi++)
#pragma unroll
        for (int ni = 0; ni < 8; ni++)
#pragma unroll
            for (int u = 0; u < 4; u++) acc[mi][ni][u] = 0.f;

    if (tid == 0) {
#pragma unroll
        for (int s = 0; s < OSTAGES; s++) MBAR_INIT(mbb + s * 8, 1);
    }
    __syncthreads();

    if (tid == 0) {
#pragma unroll
        for (int s = 0; s < OSTAGES; s++) {
            const uint32_t db = sbase + s * OSTAGE_B;
            MBAR_EXPECT(mbb + s * 8, OSTAGE_B);
            TMA2D(db,         &mAf, s * 32, m0, mbb + s * 8);
            TMA2D(db + 8192,  &mBh, s * 32, n0, mbb + s * 8);
            TMA2D(db + 16384, &mBl, s * 32, n0, mbb + s * 8);
        }
    }

    for (int it = 0; it < NCHUNK; it++) {
        const int s = it & 3;
        mbar_wait(mbb + s * 8, (it >> 2) & 1);

        const uint32_t base = sbase + s * OSTAGE_B;
#pragma unroll
        for (int ks = 0; ks < 2; ks++) {
            uint32_t aF[2][4];
            ldsm4(aF[0], base + swoff(a_row,      ks * 2 + a_c16h));
            ldsm4(aF[1], base + swoff(a_row + 16, ks * 2 + a_c16h));
#pragma unroll
            for (int np = 0; np < 2; np++) {
                const int j0 = np * 4;
                uint32_t bH0[4], bH1[4], bL0[4], bL1[4];
                ldsm4(bH0, base + 8192 + swoff(b_row + (2*np)   * 16, ks * 2 + b_c16h));
                ldsm4(bH1, base + 8192 + swoff(b_row + (2*np+1) * 16, ks * 2 + b_c16h));
                mma16816h(acc[0][j0+0], aF[0], bH0 + 0);
                mma16816h(acc[0][j0+1], aF[0], bH0 + 2);
                mma16816h(acc[0][j0+2], aF[0], bH1 + 0);
                mma16816h(acc[0][j0+3], aF[0], bH1 + 2);
                mma16816h(acc[1][j0+0], aF[1], bH0 + 0);
                mma16816h(acc[1][j0+1], aF[1], bH0 + 2);
                mma16816h(acc[1][j0+2], aF[1], bH1 + 0);
                mma16816h(acc[1][j0+3], aF[1], bH1 + 2);
                ldsm4(bL0, base + 16384 + swoff(b_row + (2*np)   * 16, ks * 2 + b_c16h));
                ldsm4(bL1, base + 16384 + swoff(b_row + (2*np+1) * 16, ks * 2 + b_c16h));
                mma16816h(acc[0][j0+0], aF[0], bL0 + 0);
                mma16816h(acc[0][j0+1], aF[0], bL0 + 2);
                mma16816h(acc[0][j0+2], aF[0], bL1 + 0);
                mma16816h(acc[0][j0+3], aF[0], bL1 + 2);
                mma16816h(acc[1][j0+0], aF[1], bL0 + 0);
                mma16816h(acc[1][j0+1], aF[1], bL0 + 2);
                mma16816h(acc[1][j0+2], aF[1], bL1 + 0);
                mma16816h(acc[1][j0+3], aF[1], bL1 + 2);
            }
        }

        if (it & 1) {
            __syncthreads();   // stages for chunks it-1, it fully consumed
            if (tid == 0) {
#pragma unroll
                for (int d = 0; d < 2; d++) {
                    const int nc = it - 1 + d + OSTAGES;
                    if (nc < NCHUNK) {
                        const int ts = nc & 3;
                        const uint32_t db = sbase + ts * OSTAGE_B;
                        MBAR_EXPECT(mbb + ts * 8, OSTAGE_B);
                        TMA2D(db,         &mAf, nc * 32, m0, mbb + ts * 8);
                        TMA2D(db + 8192,  &mBh, nc * 32, n0, mbb + ts * 8);
                        TMA2D(db + 16384, &mBl, nc * 32, n0, mbb + ts * 8);
                    }
                }
            }
        }
    }

    const int r0 = m0 + wm * 32 + (lane >> 2);
    const int nb0 = n0 + wn * 64 + 2 * (lane & 3);
#pragma unroll
    for (int mi = 0; mi < 2; mi++) {
#pragma unroll
        for (int ni = 0; ni < 8; ni++) {
            const int r = r0 + mi * 16;
            const int c = nb0 + ni * 8;
            float2 bb = *(const float2*)(bias + c);
            *(float2*)(C + (long)r * 1024 + c) =
                make_float2(acc[mi][ni][0] + bb.x, acc[mi][ni][1] + bb.y);
            *(float2*)(C + (long)(r + 8) * 1024 + c) =
                make_float2(acc[mi][ni][2] + bb.x, acc[mi][ni][3] + bb.y);
        }
    }
}

// ================= rope table ==============================================
__global__ void rope_table_kernel(float2* __restrict__ tab)
{
    const int idx = blockIdx.x * 256 + threadIdx.x;   // 65536
    const int i = idx & 31, s = idx >> 5;
    double p = pow(10000.0, (double)(2 * i) / 64.0);
    float f = (float)s * (1.0f / (float)p);
    tab[idx] = make_float2(cosf(f), sinf(f));
}

// ============ cvt x -> single fp16 + gate (one block per row) ==============
__global__ void cvt_x_gate(const float4* __restrict__ x,
                           const float4* __restrict__ Wg,
                           const float* __restrict__ bg,
                           uint2* __restrict__ xf,
                           float* __restrict__ gout)
{
    const int row = blockIdx.x;
    const int tid = threadIdx.x;
    const long i = (long)row * 256 + tid;
    float4 v = x[i];
    float4 w = Wg[tid];
    float dot = v.x * w.x + v.y * w.y + v.z * w.z + v.w * w.w;

    float f[4] = {v.x, v.y, v.z, v.w};
    unsigned short hs[4];
#pragma unroll
    for (int j = 0; j < 4; j++) {
        __half h = __float2half(f[j]);
        hs[j] = *(unsigned short*)&h;
    }
    uint2 H;
    H.x = (uint32_t)hs[0] | ((uint32_t)hs[1] << 16);
    H.y = (uint32_t)hs[2] | ((uint32_t)hs[3] << 16);
    xf[i] = H;

#pragma unroll
    for (int o = 16; o; o >>= 1) dot += __shfl_down_sync(0xffffffffu, dot, o);
    __shared__ float ws[8];
    if ((tid & 31) == 0) ws[tid >> 5] = dot;
    __syncthreads();
    if (tid == 0) {
        float t = 0.f;
#pragma unroll
        for (int j = 0; j < 8; j++) t += ws[j];
        t += bg[0];
        gout[row] = 1.f / (1.f + expf(-t));
    }
}

// W[K][N] fp32 -> transposed fp16 [N][K]; z<3 single, z==3 (Wo) hi+lo
__global__ void cvt_w4(const float* __restrict__ W0, const float* __restrict__ W1,
                       const float* __restrict__ W2, const float* __restrict__ W3,
                       __half* __restrict__ h0, __half* __restrict__ h1,
                       __half* __restrict__ h2,
                       __half* __restrict__ h3, __half* __restrict__ l3)
{
    const int z = blockIdx.z;
    const float* W = (z == 0) ? W0 : (z == 1) ? W1 : (z == 2) ? W2 : W3;
    __half* bh = (z == 0) ? h0 : (z == 1) ? h1 : (z == 2) ? h2 : h3;

    __shared__ float t[32][33];
    const int nx = blockIdx.x * 32, kx = blockIdx.y * 32;
    const int tx = threadIdx.x, ty = threadIdx.y;   // 32 x 8
#pragma unroll
    for (int r = 0; r < 32; r += 8)
        t[ty + r][tx] = W[(long)(kx + ty + r) * 1024 + nx + tx];
    __syncthreads();
#pragma unroll
    for (int r = 0; r < 32; r += 8) {
        float v = t[tx][ty + r];
        long o = (long)(nx + ty + r) * 1024 + kx + tx;
        __half h = __float2half(v);
        bh[o] = h;
        if (z == 3) {
            float rr = v - __half2float(h);
            l3[o] = __float2half(rr);
        }
    }
}

// ---------------- kv partial: per (b,n,chunk) 64x64 outer-product sum ------
// k, v are fp16 now; convert to fp32 in smem for the accumulation.
__global__ void kv_partial_kernel(const __half* __restrict__ k,
                                  const __half* __restrict__ v,
                                  float* __restrict__ kv_part,
                                  float* __restrict__ ksum_part)
{
    const int bn = blockIdx.x;
    const int c  = blockIdx.y;
    const int b = bn >> 4, n = bn & 15;
    __shared__ float ks[32][64];
    __shared__ float vs[32][64];
    const int tid = threadIdx.x;
    const int ti = tid >> 4, tj = tid & 15;

    float acc[4][4];
#pragma unroll
    for (int a = 0; a < 4; a++)
#pragma unroll
        for (int d = 0; d < 4; d++) acc[a][d] = 0.f;
    float ksum = 0.f;

    const int s0 = c * 256;
    for (int so = 0; so < 256; so += 32) {
#pragma unroll
        for (int e = tid; e < 512; e += 256) {
            int sl = e >> 4, dd = (e & 15) * 4;
            long gb = (((long)(b * Ssz + s0 + so + sl) * Nh) + n) * Dh + dd;
            uint2 kr = *(const uint2*)&k[gb];
            uint2 vr = *(const uint2*)&v[gb];
            float2 k01 = __half22float2(*(__half2*)&kr.x);
            float2 k23 = __half22float2(*(__half2*)&kr.y);
            float2 v01 = __half22float2(*(__half2*)&vr.x);
            float2 v23 = __half22float2(*(__half2*)&vr.y);
            *(float4*)&ks[sl][dd] = make_float4(k01.x, k01.y, k23.x, k23.y);
            *(float4*)&vs[sl][dd] = make_float4(v01.x, v01.y, v23.x, v23.y);
        }
        __syncthreads();
#pragma unroll 4
        for (int sl = 0; sl < 32; ++sl) {
            float4 kk4 = *(const float4*)&ks[sl][ti * 4];
            float4 vv4 = *(const float4*)&vs[sl][tj * 4];
            float ka[4] = {kk4.x, kk4.y, kk4.z, kk4.w};
            float va[4] = {vv4.x, vv4.y, vv4.z, vv4.w};
#pragma unroll
            for (int a = 0; a < 4; a++)
#pragma unroll
                for (int d = 0; d < 4; d++) acc[a][d] += ka[a] * va[d];
        }
        if (tid < 64) {
#pragma unroll 4
            for (int sl = 0; sl < 32; ++sl) ksum += ks[sl][tid];
        }
        __syncthreads();
    }

    const long pbase = ((long)c * 64 + bn) * 4096;
#pragma unroll
    for (int a = 0; a < 4; a++) {
        float4 o = make_float4(acc[a][0], acc[a][1], acc[a][2], acc[a][3]);
        *(float4*)&kv_part[pbase + (ti * 4 + a) * 64 + tj * 4] = o;
    }
    if (tid < 64) ksum_part[(c * 64 + bn) * 64 + tid] = ksum;
}

__global__ void kv_reduce_kernel(const float* __restrict__ kv_part,
                                 const float* __restrict__ ksum_part,
                                 float* __restrict__ kv,
                                 float* __restrict__ ksum)
{
    const int bn = blockIdx.x;
    const int tid = threadIdx.x;
    for (int e = tid; e < 4096; e += 256) {
        float s = 0.f;
#pragma unroll
        for (int c = 0; c < 8; ++c) s += kv_part[((long)c * 64 + bn) * 4096 + e];
        kv[(long)bn * 4096 + e] = s;
    }
    if (tid < 64) {
        float s = 0.f;
#pragma unroll
        for (int c = 0; c < 8; ++c) s += ksum_part[(c * 64 + bn) * 64 + tid];
        ksum[bn * 64 + tid] = s;
    }
}

// ---- combine: num=q@kv; den=q.ksum+eps; gate mix; write single fp16 -------
__global__ void combine_kernel(const __half* __restrict__ q,
                               const float* __restrict__ kv,
                               const float* __restrict__ ksum,
                               const float* __restrict__ gate,
                               const float* __restrict__ df,
                               const float* __restrict__ gw,
                               __half* __restrict__ cf)
{
    const int bn = blockIdx.x;
    const int st = blockIdx.y;
    const int b = bn >> 4, n = bn & 15;

    __shared__ float qs[64][68];
    __shared__ float kvs[64][64];
    __shared__ float ksums[64];

    const int tid = threadIdx.x;

    float w0 = gw[0], w1 = gw[1], w2 = gw[2];
    float d0 = df[0], d1 = df[1], d2 = df[2];
    float mx = fmaxf(w0, fmaxf(w1, w2));
    float e0 = expf(w0 - mx), e1 = expf(w1 - mx), e2 = expf(w2 - mx);
    float s0f = 1.f / (1.f + expf(-d0));
    float s1f = 1.f / (1.f + expf(-d1));
    float s2f = 1.f / (1.f + expf(-d2));
    float coef = (e0 * (1.f - s0f) + e1 * (1.f - s1f) + e2 * (1.f - s2f)) / (e0 + e1 + e2);

    const long kvbase = (long)bn * 4096;
    for (int e = tid; e < 1024; e += 256)
        ((float4*)kvs)[e] = ((const float4*)(kv + kvbase))[e];
    if (tid < 64) ksums[tid] = ksum[bn * 64 + tid];

    const int srow0 = st * 64;
    for (int e = tid; e < 1024; e += 256) {
        int r = e >> 4, dd = (e & 15) * 4;
        long gq = (((long)(b * Ssz + srow0 + r) * Nh) + n) * Dh + dd;
        uint2 qr = *(const uint2*)&q[gq];
        float2 q01 = __half22float2(*(__half2*)&qr.x);
        float2 q23 = __half22float2(*(__half2*)&qr.y);
        *(float4*)&qs[r][dd] = make_float4(q01.x, q01.y, q23.x, q23.y);
    }
    __syncthreads();

    const int sl = tid >> 2;
    const int jg = tid & 3;
    float acc[16];
#pragma unroll
    for (int j = 0; j < 16; j++) acc[j] = 0.f;
    float den = 0.f;

#pragma unroll 4
    for (int kk = 0; kk < 64; ++kk) {
        float qv = qs[sl][kk];
        den += qv * ksums[kk];
        const float4* kr = (const float4*)&kvs[kk][jg * 16];
        float4 c0 = kr[0], c1 = kr[1], c2 = kr[2], c3 = kr[3];
        acc[0]  += qv * c0.x; acc[1]  += qv * c0.y; acc[2]  += qv * c0.z; acc[3]  += qv * c0.w;
        acc[4]  += qv * c1.x; acc[5]  += qv * c1.y; acc[6]  += qv * c1.z; acc[7]  += qv * c1.w;
        acc[8]  += qv * c2.x; acc[9]  += qv * c2.y; acc[10] += qv * c2.z; acc[11] += qv * c2.w;
        acc[12] += qv * c3.x; acc[13] += qv * c3.y; acc[14] += qv * c3.z; acc[15] += qv * c3.w;
    }
    den += EPSF;

    const int srow = srow0 + sl;
    const float g = gate[b * Ssz + srow];
    const float fac = g / den + (1.f - g) * coef;

    const long obase = (((long)(b * Ssz + srow) * Nh) + n) * Dh + jg * 16;
#pragma unroll
    for (int u = 0; u < 4; u++) {
        unsigned short hs[4];
#pragma unroll
        for (int e = 0; e < 4; e++) {
            __half h = __float2half(acc[u * 4 + e] * fac);
            hs[e] = *(unsigned short*)&h;
        }
        uint2 H;
        H.x = (uint32_t)hs[0] | ((uint32_t)hs[1] << 16);
        H.y = (uint32_t)hs[2] | ((uint32_t)hs[3] << 16);
        *(uint2*)(cf + obase + u * 4) = H;
    }
}

// ================= host: tensormap construction ============================
typedef CUresult (*PFN_encodeTiled)(
    CUtensorMap*, CUtensorMapDataType, cuuint32_t, void*,
    const cuuint64_t*, const cuuint64_t*, const cuuint32_t*, const cuuint32_t*,
    CUtensorMapInterleave, CUtensorMapSwizzle, CUtensorMapL2promotion,
    CUtensorMapFloatOOBfill);

static PFN_encodeTiled get_encoder() {
    static PFN_encodeTiled fn = nullptr;
    if (!fn) {
        void* p = nullptr;
        cudaDriverEntryPointQueryResult st;
        cudaGetDriverEntryPointByVersion("cuTensorMapEncodeTiled", &p, 12000,
                                         cudaEnableDefault, &st);
        fn = (PFN_encodeTiled)p;
    }
    return fn;
}

static void make_map(CUtensorMap* m, void* base, uint64_t rows) {
    cuuint64_t dims[2]    = {1024, rows};
    cuuint64_t strides[1] = {2048};
    cuuint32_t box[2]     = {32, 128};
    cuuint32_t es[2]      = {1, 1};
    get_encoder()(m, CU_TENSOR_MAP_DATA_TYPE_FLOAT16, 2, base, dims, strides,
                  box, es, CU_TENSOR_MAP_INTERLEAVE_NONE,
                  CU_TENSOR_MAP_SWIZZLE_64B, CU_TENSOR_MAP_L2_PROMOTION_L2_128B,
                  CU_TENSOR_MAP_FLOAT_OOB_FILL_NONE);
}

// ---------------------------------------------------------------------------
extern "C" void kernel_launch(void* const* d_in, const int* in_sizes, int n_in,
                              void* d_out, int out_size)
{
    const float* x    = (const float*)d_in[0];
    const float* mask = (const float*)d_in[1];
    const float* Wq   = (const float*)d_in[2];
    const float* bq   = (const float*)d_in[3];
    const float* Wk   = (const float*)d_in[4];
    const float* bk   = (const float*)d_in[5];
    const float* Wv   = (const float*)d_in[6];
    const float* bv   = (const float*)d_in[7];
    const float* Wo   = (const float*)d_in[8];
    const float* bo   = (const float*)d_in[9];
    const float* Wg   = (const float*)d_in[10];
    const float* bg   = (const float*)d_in[11];
    const float* df   = (const float*)d_in[12];
    const float* gw   = (const float*)d_in[13];
    float* out = (float*)d_out;

    float *kvp, *kv, *ksp, *ks, *gate;
    float2* tab;
    __half *q16, *k16, *v16, *af, *bq16, *bk16, *bv16, *boh, *bol;
    cudaGetSymbolAddress((void**)&q16,  g_q16);
    cudaGetSymbolAddress((void**)&k16,  g_k16);
    cudaGetSymbolAddress((void**)&v16,  g_v16);
    cudaGetSymbolAddress((void**)&kvp,  g_kv_part);
    cudaGetSymbolAddress((void**)&kv,   g_kv);
    cudaGetSymbolAddress((void**)&ksp,  g_ksum_part);
    cudaGetSymbolAddress((void**)&ks,   g_ksum);
    cudaGetSymbolAddress((void**)&gate, g_gate);
    cudaGetSymbolAddress((void**)&tab,  g_rope);
    cudaGetSymbolAddress((void**)&af,   g_af);
    cudaGetSymbolAddress((void**)&bq16, g_bq16);
    cudaGetSymbolAddress((void**)&bk16, g_bk16);
    cudaGetSymbolAddress((void**)&bv16, g_bv16);
    cudaGetSymbolAddress((void**)&boh,  g_boh);
    cudaGetSymbolAddress((void**)&bol,  g_bol);

    CUtensorMap mAf, mQ, mK, mV, mOh, mOl;
    make_map(&mAf, af, Msz);
    make_map(&mQ,  bq16, Hsz);
    make_map(&mK,  bk16, Hsz);
    make_map(&mV,  bv16, Hsz);
    make_map(&mOh, boh, Hsz);
    make_map(&mOl, bol, Hsz);

    cudaFuncSetAttribute(gemm_qkv,
                         cudaFuncAttributeMaxDynamicSharedMemorySize, SMEM_QKV);
    cudaFuncSetAttribute(gemm_out,
                         cudaFuncAttributeMaxDynamicSharedMemorySize, SMEM_OUT);

    // 1. rope table
    rope_table_kernel<<<Ssz * 32 / 256, 256>>>(tab);
    // 2. activation -> single fp16 + gate
    cvt_x_gate<<<Msz, 256>>>((const float4*)x, (const float4*)Wg, bg,
                             (uint2*)af, gate);
    // 3. weight conversions: Wq/Wk/Wv single fp16, Wo hi+lo
    cvt_w4<<<dim3(32, 32, 4), dim3(32, 8)>>>(Wq, Wk, Wv, Wo,
                                             bq16, bk16, bv16, boh, bol);
    // 4. fused QKV projection (single-product) + rope/phi/mask epilogue
    gemm_qkv<<<dim3(8, 64, 3), 256, SMEM_QKV>>>(
        mAf, mQ, mK, mV, bq, bk, bv, q16, k16, v16, mask, tab);
    // 5-6. kv aggregation (fp16 inputs)
    kv_partial_kernel<<<dim3(64, 8), 256>>>(k16, v16, kvp, ksp);
    kv_reduce_kernel<<<64, 256>>>(kvp, ksp, kv, ks);
    // 7. combine (fp16 q) writes single fp16 into af
    combine_kernel<<<dim3(64, Ssz / 64), 256>>>(q16, kv, ks, gate, df, gw, af);
    // 8. output projection (two-product: comb fp16 x (Wo_hi + Wo_lo))
    gemm_out<<<dim3(8, 64), 256, SMEM_OUT>>>(mAf, mOh, mOl, bo, out);
}

// round 11
// speedup vs baseline: 4.3980x; 1.0858x over previous
#include <cuda_runtime.h>
#include <cuda.h>
#include <cuda_bf16.h>
#include <cuda_fp16.h>
#include <math.h>
#include <stdint.h>

// Problem constants
#define Bsz 4
#define Ssz 2048
#define Hsz 1024
#define Nh  16
#define Dh  64
#define Msz (Bsz*Ssz)      // 8192
#define EPSF 1e-6f

// ---------------- scratch (static device globals; no allocs allowed) -------
__device__ __half g_q16[Msz*Hsz];         // q (phi'd, scaled) fp16
__device__ __half g_k16[Msz*Hsz];         // k (phi'd, masked) fp16
__device__ __half g_v16[Msz*Hsz];         // v (masked) fp16
__device__ float g_kv_part[8*64*64*64];
__device__ float g_kv[64*64*64];
__device__ float g_ksum_part[8*64*64];
__device__ float g_ksum[64*64];
__device__ float g_gate[Msz];
__device__ float2 g_rope[Ssz*32];         // (cos, sin) per (s, i)
// fp16 operand buffers (single precision level, one product per GEMM)
__device__ __half g_af[Msz*Hsz];          // x fp16 (QKV phase), comb fp16 after
__device__ __half g_bq16[Hsz*Hsz];        // Wq single fp16 [N][K]
__device__ __half g_bk16[Hsz*Hsz];        // Wk single fp16
__device__ __half g_bv16[Hsz*Hsz];        // Wv single fp16
__device__ __half g_bo16[Hsz*Hsz];        // Wo single fp16

// ================= low-level helpers =======================================
static __device__ __forceinline__ uint32_t s2u(const void* p) {
    uint32_t a;
    asm("{ .reg .u64 t; cvta.to.shared.u64 t, %1; cvt.u32.u64 %0, t; }"
        : "=r"(a) : "l"(p));
    return a;
}

static __device__ __forceinline__ void ldsm4(uint32_t* r, uint32_t addr) {
    asm volatile("ldmatrix.sync.aligned.m8n8.x4.shared.b16 {%0,%1,%2,%3}, [%4];"
                 : "=r"(r[0]), "=r"(r[1]), "=r"(r[2]), "=r"(r[3]) : "r"(addr));
}

static __device__ __forceinline__ void mma16816h(float* d, const uint32_t* a,
                                                 const uint32_t* b) {
    asm volatile(
        "mma.sync.aligned.m16n8k16.row.col.f32.f16.f16.f32 "
        "{%0,%1,%2,%3}, {%4,%5,%6,%7}, {%8,%9}, {%0,%1,%2,%3};"
        : "+f"(d[0]), "+f"(d[1]), "+f"(d[2]), "+f"(d[3])
        : "r"(a[0]), "r"(a[1]), "r"(a[2]), "r"(a[3]), "r"(b[0]), "r"(b[1]));
}

// smem tile: [128 rows][32 elems = 64B], SW64 swizzle: chunk16 ^= (row>>1)&3
static __device__ __forceinline__ uint32_t swoff(int row, int c16) {
    return (uint32_t)(row * 64 + ((c16 ^ ((row >> 1) & 3)) << 4));
}

#define MBAR_INIT(m, c) \
    asm volatile("mbarrier.init.shared.b64 [%0], %1;" \
                 :: "r"((uint32_t)(m)), "r"((uint32_t)(c)) : "memory")
#define MBAR_EXPECT(m, b) \
    asm volatile("mbarrier.arrive.expect_tx.shared.b64 _, [%0], %1;" \
                 :: "r"((uint32_t)(m)), "r"((uint32_t)(b)) : "memory")

static __device__ __forceinline__ void mbar_wait(uint32_t mbar, uint32_t parity) {
    asm volatile(
        "{\n\t.reg .pred P;\n\t"
        "WL_%=:\n\t"
        "mbarrier.try_wait.parity.acquire.cta.shared::cta.b64 P, [%0], %1, 0x989680;\n\t"
        "@P bra.uni WD_%=;\n\t"
        "bra.uni WL_%=;\n\t"
        "WD_%=:\n\t}"
        :: "r"(mbar), "r"(parity) : "memory");
}

#define TMA2D(sa, mp, cx, cy, mb) \
    asm volatile("cp.async.bulk.tensor.2d.shared::cta.global.tile.mbarrier::complete_tx::bytes " \
                 "[%0], [%1, {%2, %3}], [%4];" \
                 :: "r"((uint32_t)(sa)), "l"(mp), "r"((int)(cx)), "r"((int)(cy)), \
                    "r"((uint32_t)(mb)) : "memory")

__device__ __forceinline__ float phi_fn(float x) {
    float t = (x > 0.f) ? x : expm1f(x);
    return (t + 1.0f) + EPSF;
}

static __device__ __forceinline__ __half2 pack_h2(float a, float b) {
    return __halves2half2(__float2half(a), __float2half(b));
}

#define NCHUNK 32

// ========== QKV GEMM: single-product fp16, 6-stage, sync every 2 ==========
// q/k/v (fp16) = Af @ B^T + bias, fused rope/phi/mask epilogue.
#define QSTAGES 6
#define QSTAGE_B 16384
#define SMEM_QKV (QSTAGES * QSTAGE_B + 64)

__global__ __launch_bounds__(256, 2)
void gemm_qkv(const __grid_constant__ CUtensorMap mAf,
              const __grid_constant__ CUtensorMap mB0,
              const __grid_constant__ CUtensorMap mB1,
              const __grid_constant__ CUtensorMap mB2,
              const float* __restrict__ b0, const float* __restrict__ b1,
              const float* __restrict__ b2,
              __half* __restrict__ C0, __half* __restrict__ C1,
              __half* __restrict__ C2,
              const float* __restrict__ maskp,
              const float2* __restrict__ tab)
{
    extern __shared__ __align__(1024) char smem[];
    const uint32_t sbase = s2u(smem);
    const uint32_t mbb  = sbase + QSTAGES * QSTAGE_B;
    const int tid = threadIdx.x;
    const int lane = tid & 31, wid = tid >> 5;
    const int wm = wid & 3, wn = wid >> 2;
    const int n0 = blockIdx.x * 128, m0 = blockIdx.y * 128;
    const int z = blockIdx.z;

    const CUtensorMap* pB = (z == 0) ? &mB0 : (z == 1) ? &mB1 : &mB2;
    const float* bias = (z == 0) ? b0 : (z == 1) ? b1 : b2;
    __half* C = (z == 0) ? C0 : (z == 1) ? C1 : C2;

    const int a_row  = wm * 32 + (lane & 15);
    const int a_c16h = lane >> 4;
    const int b_row  = wn * 64 + ((lane >> 4) << 3) + (lane & 7);
    const int b_c16h = (lane >> 3) & 1;

    float acc[2][8][4];
#pragma unroll
    for (int mi = 0; mi < 2; mi++)
#pragma unroll
        for (int ni = 0; ni < 8; ni++)
#pragma unroll
            for (int u = 0; u < 4; u++) acc[mi][ni][u] = 0.f;

    if (tid == 0) {
#pragma unroll
        for (int s = 0; s < QSTAGES; s++) MBAR_INIT(mbb + s * 8, 1);
    }
    __syncthreads();

    if (tid == 0) {
#pragma unroll
        for (int s = 0; s < QSTAGES; s++) {
            const uint32_t db = sbase + s * QSTAGE_B;
            MBAR_EXPECT(mbb + s * 8, QSTAGE_B);
            TMA2D(db,        &mAf, s * 32, m0, mbb + s * 8);
            TMA2D(db + 8192, pB,   s * 32, n0, mbb + s * 8);
        }
    }

    int s = 0, ph = 0;
    for (int it = 0; it < NCHUNK; it++) {
        mbar_wait(mbb + s * 8, ph);

        const uint32_t base = sbase + s * QSTAGE_B;
#pragma unroll
        for (int ks = 0; ks < 2; ks++) {
            uint32_t aF[2][4];
            ldsm4(aF[0], base + swoff(a_row,      ks * 2 + a_c16h));
            ldsm4(aF[1], base + swoff(a_row + 16, ks * 2 + a_c16h));
#pragma unroll
            for (int np = 0; np < 2; np++) {
                const int j0 = np * 4;
                uint32_t b0r[4], b1r[4];
                ldsm4(b0r, base + 8192 + swoff(b_row + (2*np)   * 16, ks * 2 + b_c16h));
                ldsm4(b1r, base + 8192 + swoff(b_row + (2*np+1) * 16, ks * 2 + b_c16h));
                mma16816h(acc[0][j0+0], aF[0], b0r + 0);
                mma16816h(acc[0][j0+1], aF[0], b0r + 2);
                mma16816h(acc[0][j0+2], aF[0], b1r + 0);
                mma16816h(acc[0][j0+3], aF[0], b1r + 2);
                mma16816h(acc[1][j0+0], aF[1], b0r + 0);
                mma16816h(acc[1][j0+1], aF[1], b0r + 2);
                mma16816h(acc[1][j0+2], aF[1], b1r + 0);
                mma16816h(acc[1][j0+3], aF[1], b1r + 2);
            }
        }

        if (it & 1) {
            __syncthreads();   // stages for chunks it-1, it fully consumed
            if (tid == 0) {
#pragma unroll
                for (int d = 0; d < 2; d++) {
                    const int nc = it - 1 + d + QSTAGES;
                    if (nc < NCHUNK) {
                        const int ts = nc % QSTAGES;
                        const uint32_t db = sbase + ts * QSTAGE_B;
                        MBAR_EXPECT(mbb + ts * 8, QSTAGE_B);
                        TMA2D(db,        &mAf, nc * 32, m0, mbb + ts * 8);
                        TMA2D(db + 8192, pB,   nc * 32, n0, mbb + ts * 8);
                    }
                }
            }
        }
        if (++s == QSTAGES) { s = 0; ph ^= 1; }
    }

    // fused QKV epilogue (validated layout), fp16 stores
    const int r0 = m0 + wm * 32 + (lane >> 2);
    const int nb0 = n0 + wn * 64 + 2 * (lane & 3);
#pragma unroll
    for (int mi = 0; mi < 2; mi++) {
#pragma unroll
        for (int uu = 0; uu < 4; uu += 2) {
            const int r = r0 + mi * 16 + (uu ? 8 : 0);
            const int srow = r & (Ssz - 1);
            const float msk = maskp[r];
            if (z == 2) {
#pragma unroll
                for (int ni = 0; ni < 8; ni++) {
                    const int c = nb0 + ni * 8;
                    float v0 = (acc[mi][ni][uu+0] + bias[c])     * msk;
                    float v1 = (acc[mi][ni][uu+1] + bias[c + 1]) * msk;
                    *(__half2*)(C + (long)r * 1024 + c) = pack_h2(v0, v1);
                }
            } else {
                const float scale = (z == 0) ? 0.125f : msk;
#pragma unroll
                for (int ni = 0; ni < 4; ni++) {
                    float o1[2], o2[2];
#pragma unroll
                    for (int e = 0; e < 2; e++) {
                        const int i = 2 * (lane & 3) + ni * 8 + e;
                        const int c = nb0 + ni * 8 + e;
                        float x1 = acc[mi][ni][uu + e]     + bias[c];
                        float x2 = acc[mi][ni + 4][uu + e] + bias[c + 32];
                        float2 cs = tab[srow * 32 + i];
                        float r1 = x1 * cs.x - x2 * cs.y;
                        float r2 = x2 * cs.x + x1 * cs.y;
                        o1[e] = phi_fn(r1) * scale;
                        o2[e] = phi_fn(r2) * scale;
                    }
                    const int c = nb0 + ni * 8;
                    *(__half2*)(C + (long)r * 1024 + c)      = pack_h2(o1[0], o1[1]);
                    *(__half2*)(C + (long)r * 1024 + c + 32) = pack_h2(o2[0], o2[1]);
                }
            }
        }
    }
}

// ===== OUT GEMM: single-product fp16, 6-stage, sync every 2, fp32 store ====
__global__ __launch_bounds__(256, 2)
void gemm_out(const __grid_constant__ CUtensorMap mAf,
              const __grid_constant__ CUtensorMap mB,
              const float* __restrict__ bias, float* __restrict__ C)
{
    extern __shared__ __align__(1024) char smem[];
    const uint32_t sbase = s2u(smem);
    const uint32_t mbb  = sbase + QSTAGES * QSTAGE_B;
    const int tid = threadIdx.x;
    const int lane = tid & 31, wid = tid >> 5;
    const int wm = wid & 3, wn = wid >> 2;
    const int n0 = blockIdx.x * 128, m0 = blockIdx.y * 128;

    const int a_row  = wm * 32 + (lane & 15);
    const int a_c16h = lane >> 4;
    const int b_row  = wn * 64 + ((lane >> 4) << 3) + (lane & 7);
    const int b_c16h = (lane >> 3) & 1;

    float acc[2][8][4];
#pragma unroll
    for (int mi = 0; mi < 2; mi++)
#pragma unroll
        for (int ni = 0; ni < 8; ni++)
#pragma unroll
            for (int u = 0; u < 4; u++) acc[mi][ni][u] = 0.f;

    if (tid == 0) {
#pragma unroll
        for (int s = 0; s < QSTAGES; s++) MBAR_INIT(mbb + s * 8, 1);
    }
    __syncthreads();

    if (tid == 0) {
#pragma unroll
        for (int s = 0; s < QSTAGES; s++) {
            const uint32_t db = sbase + s * QSTAGE_B;
            MBAR_EXPECT(mbb + s * 8, QSTAGE_B);
            TMA2D(db,        &mAf, s * 32, m0, mbb + s * 8);
            TMA2D(db + 8192, &mB,  s * 32, n0, mbb + s * 8);
        }
    }

    int s = 0, ph = 0;
    for (int it = 0; it < NCHUNK; it++) {
        mbar_wait(mbb + s * 8, ph);

        const uint32_t base = sbase + s * QSTAGE_B;
#pragma unroll
        for (int ks = 0; ks < 2; ks++) {
            uint32_t aF[2][4];
            ldsm4(aF[0], base + swoff(a_row,      ks * 2 + a_c16h));
            ldsm4(aF[1], base + swoff(a_row + 16, ks * 2 + a_c16h));
#pragma unroll
            for (int np = 0; np < 2; np++) {
                const int j0 = np * 4;
                uint32_t b0r[4], b1r[4];
                ldsm4(b0r, base + 8192 + swoff(b_row + (2*np)   * 16, ks * 2 + b_c16h));
                ldsm4(b1r, base + 8192 + swoff(b_row + (2*np+1) * 16, ks * 2 + b_c16h));
                mma16816h(acc[0][j0+0], aF[0], b0r + 0);
                mma16816h(acc[0][j0+1], aF[0], b0r + 2);
                mma16816h(acc[0][j0+2], aF[0], b1r + 0);
                mma16816h(acc[0][j0+3], aF[0], b1r + 2);
                mma16816h(acc[1][j0+0], aF[1], b0r + 0);
                mma16816h(acc[1][j0+1], aF[1], b0r + 2);
                mma16816h(acc[1][j0+2], aF[1], b1r + 0);
                mma16816h(acc[1][j0+3], aF[1], b1r + 2);
            }
        }

        if (it & 1) {
            __syncthreads();
            if (tid == 0) {
#pragma unroll
                for (int d = 0; d < 2; d++) {
                    const int nc = it - 1 + d + QSTAGES;
                    if (nc < NCHUNK) {
                        const int ts = nc % QSTAGES;
                        const uint32_t db = sbase + ts * QSTAGE_B;
                        MBAR_EXPECT(mbb + ts * 8, QSTAGE_B);
                        TMA2D(db,        &mAf, nc * 32, m0, mbb + ts * 8);
                        TMA2D(db + 8192, &mB,  nc * 32, n0, mbb + ts * 8);
                    }
                }
            }
        }
        if (++s == QSTAGES) { s = 0; ph ^= 1; }
    }

    const int r0 = m0 + wm * 32 + (lane >> 2);
    const int nb0 = n0 + wn * 64 + 2 * (lane & 3);
#pragma unroll
    for (int mi = 0; mi < 2; mi++) {
#pragma unroll
        for (int ni = 0; ni < 8; ni++) {
            const int r = r0 + mi * 16;
            const int c = nb0 + ni * 8;
            float2 bb = *(const float2*)(bias + c);
            *(float2*)(C + (long)r * 1024 + c) =
                make_float2(acc[mi][ni][0] + bb.x, acc[mi][ni][1] + bb.y);
            *(float2*)(C + (long)(r + 8) * 1024 + c) =
                make_float2(acc[mi][ni][2] + bb.x, acc[mi][ni][3] + bb.y);
        }
    }
}

// ================= rope table ==============================================
__global__ void rope_table_kernel(float2* __restrict__ tab)
{
    const int idx = blockIdx.x * 256 + threadIdx.x;   // 65536
    const int i = idx & 31, s = idx >> 5;
    double p = pow(10000.0, (double)(2 * i) / 64.0);
    float f = (float)s * (1.0f / (float)p);
    tab[idx] = make_float2(cosf(f), sinf(f));
}

// ============ cvt x -> single fp16 + gate (one block per row) ==============
__global__ void cvt_x_gate(const float4* __restrict__ x,
                           const float4* __restrict__ Wg,
                           const float* __restrict__ bg,
                           uint2* __restrict__ xf,
                           float* __restrict__ gout)
{
    const int row = blockIdx.x;
    const int tid = threadIdx.x;
    const long i = (long)row * 256 + tid;
    float4 v = x[i];
    float4 w = Wg[tid];
    float dot = v.x * w.x + v.y * w.y + v.z * w.z + v.w * w.w;

    float f[4] = {v.x, v.y, v.z, v.w};
    unsigned short hs[4];
#pragma unroll
    for (int j = 0; j < 4; j++) {
        __half h = __float2half(f[j]);
        hs[j] = *(unsigned short*)&h;
    }
    uint2 H;
    H.x = (uint32_t)hs[0] | ((uint32_t)hs[1] << 16);
    H.y = (uint32_t)hs[2] | ((uint32_t)hs[3] << 16);
    xf[i] = H;

#pragma unroll
    for (int o = 16; o; o >>= 1) dot += __shfl_down_sync(0xffffffffu, dot, o);
    __shared__ float ws[8];
    if ((tid & 31) == 0) ws[tid >> 5] = dot;
    __syncthreads();
    if (tid == 0) {
        float t = 0.f;
#pragma unroll
        for (int j = 0; j < 8; j++) t += ws[j];
        t += bg[0];
        gout[row] = 1.f / (1.f + expf(-t));
    }
}

// W[K][N] fp32 -> transposed single fp16 [N][K]; z selects which W
__global__ void cvt_w4(const float* __restrict__ W0, const float* __restrict__ W1,
                       const float* __restrict__ W2, const float* __restrict__ W3,
                       __half* __restrict__ h0, __half* __restrict__ h1,
                       __half* __restrict__ h2, __half* __restrict__ h3)
{
    const int z = blockIdx.z;
    const float* W = (z == 0) ? W0 : (z == 1) ? W1 : (z == 2) ? W2 : W3;
    __half* bh = (z == 0) ? h0 : (z == 1) ? h1 : (z == 2) ? h2 : h3;

    __shared__ float t[32][33];
    const int nx = blockIdx.x * 32, kx = blockIdx.y * 32;
    const int tx = threadIdx.x, ty = threadIdx.y;   // 32 x 8
#pragma unroll
    for (int r = 0; r < 32; r += 8)
        t[ty + r][tx] = W[(long)(kx + ty + r) * 1024 + nx + tx];
    __syncthreads();
#pragma unroll
    for (int r = 0; r < 32; r += 8) {
        float v = t[tx][ty + r];
        long o = (long)(nx + ty + r) * 1024 + kx + tx;
        bh[o] = __float2half(v);
    }
}

// ---------------- kv partial: per (b,n,chunk) 64x64 outer-product sum ------
__global__ void kv_partial_kernel(const __half* __restrict__ k,
                                  const __half* __restrict__ v,
                                  float* __restrict__ kv_part,
                                  float* __restrict__ ksum_part)
{
    const int bn = blockIdx.x;
    const int c  = blockIdx.y;
    const int b = bn >> 4, n = bn & 15;
    __shared__ float ks[32][64];
    __shared__ float vs[32][64];
    const int tid = threadIdx.x;
    const int ti = tid >> 4, tj = tid & 15;

    float acc[4][4];
#pragma unroll
    for (int a = 0; a < 4; a++)
#pragma unroll
        for (int d = 0; d < 4; d++) acc[a][d] = 0.f;
    float ksum = 0.f;

    const int s0 = c * 256;
    for (int so = 0; so < 256; so += 32) {
#pragma unroll
        for (int e = tid; e < 512; e += 256) {
            int sl = e >> 4, dd = (e & 15) * 4;
            long gb = (((long)(b * Ssz + s0 + so + sl) * Nh) + n) * Dh + dd;
            uint2 kr = *(const uint2*)&k[gb];
            uint2 vr = *(const uint2*)&v[gb];
            float2 k01 = __half22float2(*(__half2*)&kr.x);
            float2 k23 = __half22float2(*(__half2*)&kr.y);
            float2 v01 = __half22float2(*(__half2*)&vr.x);
            float2 v23 = __half22float2(*(__half2*)&vr.y);
            *(float4*)&ks[sl][dd] = make_float4(k01.x, k01.y, k23.x, k23.y);
            *(float4*)&vs[sl][dd] = make_float4(v01.x, v01.y, v23.x, v23.y);
        }
        __syncthreads();
#pragma unroll 4
        for (int sl = 0; sl < 32; ++sl) {
            float4 kk4 = *(const float4*)&ks[sl][ti * 4];
            float4 vv4 = *(const float4*)&vs[sl][tj * 4];
            float ka[4] = {kk4.x, kk4.y, kk4.z, kk4.w};
            float va[4] = {vv4.x, vv4.y, vv4.z, vv4.w};
#pragma unroll
            for (int a = 0; a < 4; a++)
#pragma unroll
                for (int d = 0; d < 4; d++) acc[a][d] += ka[a] * va[d];
        }
        if (tid < 64) {
#pragma unroll 4
            for (int sl = 0; sl < 32; ++sl) ksum += ks[sl][tid];
        }
        __syncthreads();
    }

    const long pbase = ((long)c * 64 + bn) * 4096;
#pragma unroll
    for (int a = 0; a < 4; a++) {
        float4 o = make_float4(acc[a][0], acc[a][1], acc[a][2], acc[a][3]);
        *(float4*)&kv_part[pbase + (ti * 4 + a) * 64 + tj * 4] = o;
    }
    if (tid < 64) ksum_part[(c * 64 + bn) * 64 + tid] = ksum;
}

__global__ void kv_reduce_kernel(const float* __restrict__ kv_part,
                                 const float* __restrict__ ksum_part,
                                 float* __restrict__ kv,
                                 float* __restrict__ ksum)
{
    const int bn = blockIdx.x;
    const int tid = threadIdx.x;
    for (int e = tid; e < 4096; e += 256) {
        float s = 0.f;
#pragma unroll
        for (int c = 0; c < 8; ++c) s += kv_part[((long)c * 64 + bn) * 4096 + e];
        kv[(long)bn * 4096 + e] = s;
    }
    if (tid < 64) {
        float s = 0.f;
#pragma unroll
        for (int c = 0; c < 8; ++c) s += ksum_part[(c * 64 + bn) * 64 + tid];
        ksum[bn * 64 + tid] = s;
    }
}

// ---- combine: num=q@kv; den=q.ksum+eps; gate mix; write single fp16 -------
__global__ void combine_kernel(const __half* __restrict__ q,
                               const float* __restrict__ kv,
                               const float* __restrict__ ksum,
                               const float* __restrict__ gate,
                               const float* __restrict__ df,
                               const float* __restrict__ gw,
                               __half* __restrict__ cf)
{
    const int bn = blockIdx.x;
    const int st = blockIdx.y;
    const int b = bn >> 4, n = bn & 15;

    __shared__ float qs[64][68];
    __shared__ float kvs[64][64];
    __shared__ float ksums[64];

    const int tid = threadIdx.x;

    float w0 = gw[0], w1 = gw[1], w2 = gw[2];
    float d0 = df[0], d1 = df[1], d2 = df[2];
    float mx = fmaxf(w0, fmaxf(w1, w2));
    float e0 = expf(w0 - mx), e1 = expf(w1 - mx), e2 = expf(w2 - mx);
    float s0f = 1.f / (1.f + expf(-d0));
    float s1f = 1.f / (1.f + expf(-d1));
    float s2f = 1.f / (1.f + expf(-d2));
    float coef = (e0 * (1.f - s0f) + e1 * (1.f - s1f) + e2 * (1.f - s2f)) / (e0 + e1 + e2);

    const long kvbase = (long)bn * 4096;
    for (int e = tid; e < 1024; e += 256)
        ((float4*)kvs)[e] = ((const float4*)(kv + kvbase))[e];
    if (tid < 64) ksums[tid] = ksum[bn * 64 + tid];

    const int srow0 = st * 64;
    for (int e = tid; e < 1024; e += 256) {
        int r = e >> 4, dd = (e & 15) * 4;
        long gq = (((long)(b * Ssz + srow0 + r) * Nh) + n) * Dh + dd;
        uint2 qr = *(const uint2*)&q[gq];
        float2 q01 = __half22float2(*(__half2*)&qr.x);
        float2 q23 = __half22float2(*(__half2*)&qr.y);
        *(float4*)&qs[r][dd] = make_float4(q01.x, q01.y, q23.x, q23.y);
    }
    __syncthreads();

    const int sl = tid >> 2;
    const int jg = tid & 3;
    float acc[16];
#pragma unroll
    for (int j = 0; j < 16; j++) acc[j] = 0.f;
    float den = 0.f;

#pragma unroll 4
    for (int kk = 0; kk < 64; ++kk) {
        float qv = qs[sl][kk];
        den += qv * ksums[kk];
        const float4* kr = (const float4*)&kvs[kk][jg * 16];
        float4 c0 = kr[0], c1 = kr[1], c2 = kr[2], c3 = kr[3];
        acc[0]  += qv * c0.x; acc[1]  += qv * c0.y; acc[2]  += qv * c0.z; acc[3]  += qv * c0.w;
        acc[4]  += qv * c1.x; acc[5]  += qv * c1.y; acc[6]  += qv * c1.z; acc[7]  += qv * c1.w;
        acc[8]  += qv * c2.x; acc[9]  += qv * c2.y; acc[10] += qv * c2.z; acc[11] += qv * c2.w;
        acc[12] += qv * c3.x; acc[13] += qv * c3.y; acc[14] += qv * c3.z; acc[15] += qv * c3.w;
    }
    den += EPSF;

    const int srow = srow0 + sl;
    const float g = gate[b * Ssz + srow];
    const float fac = g / den + (1.f - g) * coef;

    const long obase = (((long)(b * Ssz + srow) * Nh) + n) * Dh + jg * 16;
#pragma unroll
    for (int u = 0; u < 4; u++) {
        unsigned short hs[4];
#pragma unroll
        for (int e = 0; e < 4; e++) {
            __half h = __float2half(acc[u * 4 + e] * fac);
            hs[e] = *(unsigned short*)&h;
        }
        uint2 H;
        H.x = (uint32_t)hs[0] | ((uint32_t)hs[1] << 16);
        H.y = (uint32_t)hs[2] | ((uint32_t)hs[3] << 16);
        *(uint2*)(cf + obase + u * 4) = H;
    }
}

// ================= host: tensormap construction ============================
typedef CUresult (*PFN_encodeTiled)(
    CUtensorMap*, CUtensorMapDataType, cuuint32_t, void*,
    const cuuint64_t*, const cuuint64_t*, const cuuint32_t*, const cuuint32_t*,
    CUtensorMapInterleave, CUtensorMapSwizzle, CUtensorMapL2promotion,
    CUtensorMapFloatOOBfill);

static PFN_encodeTiled get_encoder() {
    static PFN_encodeTiled fn = nullptr;
    if (!fn) {
        void* p = nullptr;
        cudaDriverEntryPointQueryResult st;
        cudaGetDriverEntryPointByVersion("cuTensorMapEncodeTiled", &p, 12000,
                                         cudaEnableDefault, &st);
        fn = (PFN_encodeTiled)p;
    }
    return fn;
}

static void make_map(CUtensorMap* m, void* base, uint64_t rows) {
    cuuint64_t dims[2]    = {1024, rows};
    cuuint64_t strides[1] = {2048};
    cuuint32_t box[2]     = {32, 128};
    cuuint32_t es[2]      = {1, 1};
    get_encoder()(m, CU_TENSOR_MAP_DATA_TYPE_FLOAT16, 2, base, dims, strides,
                  box, es, CU_TENSOR_MAP_INTERLEAVE_NONE,
                  CU_TENSOR_MAP_SWIZZLE_64B, CU_TENSOR_MAP_L2_PROMOTION_L2_128B,
                  CU_TENSOR_MAP_FLOAT_OOB_FILL_NONE);
}

// ---------------------------------------------------------------------------
extern "C" void kernel_launch(void* const* d_in, const int* in_sizes, int n_in,
                              void* d_out, int out_size)
{
    const float* x    = (const float*)d_in[0];
    const float* mask = (const float*)d_in[1];
    const float* Wq   = (const float*)d_in[2];
    const float* bq   = (const float*)d_in[3];
    const float* Wk   = (const float*)d_in[4];
    const float* bk   = (const float*)d_in[5];
    const float* Wv   = (const float*)d_in[6];
    const float* bv   = (const float*)d_in[7];
    const float* Wo   = (const float*)d_in[8];
    const float* bo   = (const float*)d_in[9];
    const float* Wg   = (const float*)d_in[10];
    const float* bg   = (const float*)d_in[11];
    const float* df   = (const float*)d_in[12];
    const float* gw   = (const float*)d_in[13];
    float* out = (float*)d_out;

    float *kvp, *kv, *ksp, *ks, *gate;
    float2* tab;
    __half *q16, *k16, *v16, *af, *bq16, *bk16, *bv16, *bo16;
    cudaGetSymbolAddress((void**)&q16,  g_q16);
    cudaGetSymbolAddress((void**)&k16,  g_k16);
    cudaGetSymbolAddress((void**)&v16,  g_v16);
    cudaGetSymbolAddress((void**)&kvp,  g_kv_part);
    cudaGetSymbolAddress((void**)&kv,   g_kv);
    cudaGetSymbolAddress((void**)&ksp,  g_ksum_part);
    cudaGetSymbolAddress((void**)&ks,   g_ksum);
    cudaGetSymbolAddress((void**)&gate, g_gate);
    cudaGetSymbolAddress((void**)&tab,  g_rope);
    cudaGetSymbolAddress((void**)&af,   g_af);
    cudaGetSymbolAddress((void**)&bq16, g_bq16);
    cudaGetSymbolAddress((void**)&bk16, g_bk16);
    cudaGetSymbolAddress((void**)&bv16, g_bv16);
    cudaGetSymbolAddress((void**)&bo16, g_bo16);

    CUtensorMap mAf, mQ, mK, mV, mO;
    make_map(&mAf, af, Msz);
    make_map(&mQ,  bq16, Hsz);
    make_map(&mK,  bk16, Hsz);
    make_map(&mV,  bv16, Hsz);
    make_map(&mO,  bo16, Hsz);

    cudaFuncSetAttribute(gemm_qkv,
                         cudaFuncAttributeMaxDynamicSharedMemorySize, SMEM_QKV);
    cudaFuncSetAttribute(gemm_out,
                         cudaFuncAttributeMaxDynamicSharedMemorySize, SMEM_QKV);

    // 1. rope table
    rope_table_kernel<<<Ssz * 32 / 256, 256>>>(tab);
    // 2. activation -> single fp16 + gate
    cvt_x_gate<<<Msz, 256>>>((const float4*)x, (const float4*)Wg, bg,
                             (uint2*)af, gate);
    // 3. weight conversions: all single fp16
    cvt_w4<<<dim3(32, 32, 4), dim3(32, 8)>>>(Wq, Wk, Wv, Wo,
                                             bq16, bk16, bv16, bo16);
    // 4. fused QKV projection (single-product) + rope/phi/mask epilogue
    gemm_qkv<<<dim3(8, 64, 3), 256, SMEM_QKV>>>(
        mAf, mQ, mK, mV, bq, bk, bv, q16, k16, v16, mask, tab);
    // 5-6. kv aggregation (fp16 inputs)
    kv_partial_kernel<<<dim3(64, 8), 256>>>(k16, v16, kvp, ksp);
    kv_reduce_kernel<<<64, 256>>>(kvp, ksp, kv, ks);
    // 7. combine (fp16 q) writes single fp16 into af
    combine_kernel<<<dim3(64, Ssz / 64), 256>>>(q16, kv, ks, gate, df, gw, af);
    // 8. output projection (single-product fp16)
    gemm_out<<<dim3(8, 64), 256, SMEM_QKV>>>(mAf, mO, bo, out);
}

// round 12
// speedup vs baseline: 6.3745x; 1.4494x over previous
#include <cuda_runtime.h>
#include <cuda.h>
#include <cuda_bf16.h>
#include <cuda_fp16.h>
#include <math.h>
#include <stdint.h>

// Problem constants
#define Bsz 4
#define Ssz 2048
#define Hsz 1024
#define Nh  16
#define Dh  64
#define Msz (Bsz*Ssz)      // 8192
#define EPSF 1e-6f

// ---------------- scratch (static device globals; no allocs allowed) -------
__device__ __half g_q16[Msz*Hsz];         // q (phi'd, scaled) fp16 [s][1024]
__device__ __half g_kt[64*64*Ssz];        // k transposed [bn][kd][s] fp16
__device__ __half g_vt[64*64*Ssz];        // v transposed [bn][vd][s] fp16
__device__ float g_kv_part[4*64*64*64];   // [kc][bn][vd][kd]
__device__ __half g_kvt_h[64*72*64];      // [bn][72][64]: rows0-63 kv, 64 ksum
__device__ __half g_kvt_l[64*72*64];
__device__ float g_gate[Msz];
__device__ float2 g_rope[Ssz*32];         // (cos, sin) per (s, i)
__device__ __half g_af[Msz*Hsz];          // x fp16 (QKV phase), comb fp16 after
__device__ __half g_bq16[Hsz*Hsz];        // Wq single fp16 [N][K]
__device__ __half g_bk16[Hsz*Hsz];
__device__ __half g_bv16[Hsz*Hsz];
__device__ __half g_bo16[Hsz*Hsz];

// ================= low-level helpers =======================================
static __device__ __forceinline__ uint32_t s2u(const void* p) {
    uint32_t a;
    asm("{ .reg .u64 t; cvta.to.shared.u64 t, %1; cvt.u32.u64 %0, t; }"
        : "=r"(a) : "l"(p));
    return a;
}

static __device__ __forceinline__ void ldsm4(uint32_t* r, uint32_t addr) {
    asm volatile("ldmatrix.sync.aligned.m8n8.x4.shared.b16 {%0,%1,%2,%3}, [%4];"
                 : "=r"(r[0]), "=r"(r[1]), "=r"(r[2]), "=r"(r[3]) : "r"(addr));
}

static __device__ __forceinline__ void mma16816h(float* d, const uint32_t* a,
                                                 const uint32_t* b) {
    asm volatile(
        "mma.sync.aligned.m16n8k16.row.col.f32.f16.f16.f32 "
        "{%0,%1,%2,%3}, {%4,%5,%6,%7}, {%8,%9}, {%0,%1,%2,%3};"
        : "+f"(d[0]), "+f"(d[1]), "+f"(d[2]), "+f"(d[3])
        : "r"(a[0]), "r"(a[1]), "r"(a[2]), "r"(a[3]), "r"(b[0]), "r"(b[1]));
}

// 64B-row tile swizzle (TMA SW64 tiles: rows of 32 halves)
static __device__ __forceinline__ uint32_t swoff(int row, int c16) {
    return (uint32_t)(row * 64 + ((c16 ^ ((row >> 1) & 3)) << 4));
}
// 128B-row tile swizzle (plain-load tiles: rows of 64 halves, 8 c16 chunks)
static __device__ __forceinline__ uint32_t swoff128(int row, int c16) {
    return (uint32_t)(row * 128 + ((c16 ^ (row & 7)) << 4));
}

#define MBAR_INIT(m, c) \
    asm volatile("mbarrier.init.shared.b64 [%0], %1;" \
                 :: "r"((uint32_t)(m)), "r"((uint32_t)(c)) : "memory")
#define MBAR_EXPECT(m, b) \
    asm volatile("mbarrier.arrive.expect_tx.shared.b64 _, [%0], %1;" \
                 :: "r"((uint32_t)(m)), "r"((uint32_t)(b)) : "memory")

static __device__ __forceinline__ void mbar_wait(uint32_t mbar, uint32_t parity) {
    asm volatile(
        "{\n\t.reg .pred P;\n\t"
        "WL_%=:\n\t"
        "mbarrier.try_wait.parity.acquire.cta.shared::cta.b64 P, [%0], %1, 0x989680;\n\t"
        "@P bra.uni WD_%=;\n\t"
        "bra.uni WL_%=;\n\t"
        "WD_%=:\n\t}"
        :: "r"(mbar), "r"(parity) : "memory");
}

#define TMA2D(sa, mp, cx, cy, mb) \
    asm volatile("cp.async.bulk.tensor.2d.shared::cta.global.tile.mbarrier::complete_tx::bytes " \
                 "[%0], [%1, {%2, %3}], [%4];" \
                 :: "r"((uint32_t)(sa)), "l"(mp), "r"((int)(cx)), "r"((int)(cy)), \
                    "r"((uint32_t)(mb)) : "memory")

__device__ __forceinline__ float phi_fn(float x) {
    float t = (x > 0.f) ? x : expm1f(x);
    return (t + 1.0f) + EPSF;
}

static __device__ __forceinline__ __half2 pack_h2(float a, float b) {
    return __halves2half2(__float2half(a), __float2half(b));
}

#define NCHUNK 32

// ========== QKV GEMM: single-product fp16, 6-stage, sync every 2 ==========
// z=0: q -> rope/phi*0.125, fp16 [s][1024]
// z=1: k -> rope/phi*mask, fp16 TRANSPOSED [bn][kd][s]
// z=2: v -> mask, fp16 TRANSPOSED [bn][vd][s]
#define QSTAGES 6
#define QSTAGE_B 16384
#define SMEM_QKV (QSTAGES * QSTAGE_B + 64)

__global__ __launch_bounds__(256, 2)
void gemm_qkv(const __grid_constant__ CUtensorMap mAf,
              const __grid_constant__ CUtensorMap mB0,
              const __grid_constant__ CUtensorMap mB1,
              const __grid_constant__ CUtensorMap mB2,
              const float* __restrict__ b0, const float* __restrict__ b1,
              const float* __restrict__ b2,
              __half* __restrict__ Cq, __half* __restrict__ KT,
              __half* __restrict__ VT,
              const float* __restrict__ maskp,
              const float2* __restrict__ tab)
{
    extern __shared__ __align__(1024) char smem[];
    const uint32_t sbase = s2u(smem);
    const uint32_t mbb  = sbase + QSTAGES * QSTAGE_B;
    const int tid = threadIdx.x;
    const int lane = tid & 31, wid = tid >> 5;
    const int wm = wid & 3, wn = wid >> 2;
    const int n0 = blockIdx.x * 128, m0 = blockIdx.y * 128;
    const int z = blockIdx.z;

    const CUtensorMap* pB = (z == 0) ? &mB0 : (z == 1) ? &mB1 : &mB2;
    const float* bias = (z == 0) ? b0 : (z == 1) ? b1 : b2;

    const int a_row  = wm * 32 + (lane & 15);
    const int a_c16h = lane >> 4;
    const int b_row  = wn * 64 + ((lane >> 4) << 3) + (lane & 7);
    const int b_c16h = (lane >> 3) & 1;

    float acc[2][8][4];
#pragma unroll
    for (int mi = 0; mi < 2; mi++)
#pragma unroll
        for (int ni = 0; ni < 8; ni++)
#pragma unroll
            for (int u = 0; u < 4; u++) acc[mi][ni][u] = 0.f;

    if (tid == 0) {
#pragma unroll
        for (int s = 0; s < QSTAGES; s++) MBAR_INIT(mbb + s * 8, 1);
    }
    __syncthreads();

    if (tid == 0) {
#pragma unroll
        for (int s = 0; s < QSTAGES; s++) {
            const uint32_t db = sbase + s * QSTAGE_B;
            MBAR_EXPECT(mbb + s * 8, QSTAGE_B);
            TMA2D(db,        &mAf, s * 32, m0, mbb + s * 8);
            TMA2D(db + 8192, pB,   s * 32, n0, mbb + s * 8);
        }
    }

    int s = 0, ph = 0;
    for (int it = 0; it < NCHUNK; it++) {
        mbar_wait(mbb + s * 8, ph);

        const uint32_t base = sbase + s * QSTAGE_B;
#pragma unroll
        for (int ks = 0; ks < 2; ks++) {
            uint32_t aF[2][4];
            ldsm4(aF[0], base + swoff(a_row,      ks * 2 + a_c16h));
            ldsm4(aF[1], base + swoff(a_row + 16, ks * 2 + a_c16h));
#pragma unroll
            for (int np = 0; np < 2; np++) {
                const int j0 = np * 4;
                uint32_t b0r[4], b1r[4];
                ldsm4(b0r, base + 8192 + swoff(b_row + (2*np)   * 16, ks * 2 + b_c16h));
                ldsm4(b1r, base + 8192 + swoff(b_row + (2*np+1) * 16, ks * 2 + b_c16h));
                mma16816h(acc[0][j0+0], aF[0], b0r + 0);
                mma16816h(acc[0][j0+1], aF[0], b0r + 2);
                mma16816h(acc[0][j0+2], aF[0], b1r + 0);
                mma16816h(acc[0][j0+3], aF[0], b1r + 2);
                mma16816h(acc[1][j0+0], aF[1], b0r + 0);
                mma16816h(acc[1][j0+1], aF[1], b0r + 2);
                mma16816h(acc[1][j0+2], aF[1], b1r + 0);
                mma16816h(acc[1][j0+3], aF[1], b1r + 2);
            }
        }

        if (it & 1) {
            __syncthreads();
            if (tid == 0) {
#pragma unroll
                for (int d = 0; d < 2; d++) {
                    const int nc = it - 1 + d + QSTAGES;
                    if (nc < NCHUNK) {
                        const int ts = nc % QSTAGES;
                        const uint32_t db = sbase + ts * QSTAGE_B;
                        MBAR_EXPECT(mbb + ts * 8, QSTAGE_B);
                        TMA2D(db,        &mAf, nc * 32, m0, mbb + ts * 8);
                        TMA2D(db + 8192, pB,   nc * 32, n0, mbb + ts * 8);
                    }
                }
            }
        }
        if (++s == QSTAGES) { s = 0; ph ^= 1; }
    }

    // ---------------- epilogue ----------------
    const int r0 = m0 + wm * 32 + (lane >> 2);
    const int nb0 = n0 + wn * 64 + 2 * (lane & 3);

    if (z == 0) {
        // q: rope + phi*0.125, store [s][1024] fp16
#pragma unroll
        for (int mi = 0; mi < 2; mi++) {
#pragma unroll
            for (int uu = 0; uu < 4; uu += 2) {
                const int r = r0 + mi * 16 + (uu ? 8 : 0);
                const int srow = r & (Ssz - 1);
#pragma unroll
                for (int ni = 0; ni < 4; ni++) {
                    float o1[2], o2[2];
#pragma unroll
                    for (int e = 0; e < 2; e++) {
                        const int i = 2 * (lane & 3) + ni * 8 + e;
                        const int c = nb0 + ni * 8 + e;
                        float x1 = acc[mi][ni][uu + e]     + bias[c];
                        float x2 = acc[mi][ni + 4][uu + e] + bias[c + 32];
                        float2 cs = tab[srow * 32 + i];
                        float r1 = x1 * cs.x - x2 * cs.y;
                        float r2 = x2 * cs.x + x1 * cs.y;
                        o1[e] = phi_fn(r1) * 0.125f;
                        o2[e] = phi_fn(r2) * 0.125f;
                    }
                    const int c = nb0 + ni * 8;
                    *(__half2*)(Cq + (long)r * 1024 + c)      = pack_h2(o1[0], o1[1]);
                    *(__half2*)(Cq + (long)r * 1024 + c + 32) = pack_h2(o2[0], o2[1]);
                }
            }
        }
        return;
    }

    // k/v: transposed store via smem staging. ts[c_local][rloc], pitch 136.
    __syncthreads();                 // mainloop smem fully consumed
    __half* ts = (__half*)smem;
    const int rb = wm * 32 + (lane >> 2);       // rloc base
    const int cb = wn * 64 + 2 * (lane & 3);    // c_local base

#pragma unroll
    for (int mi = 0; mi < 2; mi++) {
#pragma unroll
        for (int uu = 0; uu < 4; uu += 2) {
            const int rloc = rb + mi * 16 + (uu ? 8 : 0);
            const int r = m0 + rloc;
            const int srow = r & (Ssz - 1);
            const float msk = maskp[r];
            if (z == 2) {
#pragma unroll
                for (int ni = 0; ni < 8; ni++) {
#pragma unroll
                    for (int e = 0; e < 2; e++) {
                        const int cl = cb + ni * 8 + e;
                        float val = (acc[mi][ni][uu + e] + bias[n0 + cl]) * msk;
                        ts[cl * 136 + rloc] = __float2half(val);
                    }
                }
            } else {
#pragma unroll
                for (int ni = 0; ni < 4; ni++) {
#pragma unroll
                    for (int e = 0; e < 2; e++) {
                        const int i = 2 * (lane & 3) + ni * 8 + e;
                        const int cl = cb + ni * 8 + e;
                        float x1 = acc[mi][ni][uu + e]     + bias[n0 + cl];
                        float x2 = acc[mi][ni + 4][uu + e] + bias[n0 + cl + 32];
                        float2 cs = tab[srow * 32 + i];
                        float r1 = x1 * cs.x - x2 * cs.y;
                        float r2 = x2 * cs.x + x1 * cs.y;
                        ts[cl * 136 + rloc]        = __float2half(phi_fn(r1) * msk);
                        ts[(cl + 32) * 136 + rloc] = __float2half(phi_fn(r2) * msk);
                    }
                }
            }
        }
    }
    __syncthreads();

    // coalesced write-out: [c][rloc] -> T[bn*64 + d][s]
    __half* T = (z == 1) ? KT : VT;
    const int b = m0 >> 11;
    const int sb = m0 & (Ssz - 1);
#pragma unroll
    for (int i = 0; i < 8; i++) {
        const int e = tid + i * 256;       // 0..2047
        const int c = e >> 4, ch = e & 15, rl = ch * 8;
        uint4 val = *(uint4*)&ts[c * 136 + rl];
        const int bn = b * 16 + (n0 >> 6) + (c >> 6);
        const int d = c & 63;
        *(uint4*)(T + ((long)(bn * 64 + d)) * Ssz + sb + rl) = val;
    }
}

// ===== OUT GEMM: single-product fp16, 6-stage, sync every 2, fp32 store ====
__global__ __launch_bounds__(256, 2)
void gemm_out(const __grid_constant__ CUtensorMap mAf,
              const __grid_constant__ CUtensorMap mB,
              const float* __restrict__ bias, float* __restrict__ C)
{
    extern __shared__ __align__(1024) char smem[];
    const uint32_t sbase = s2u(smem);
    const uint32_t mbb  = sbase + QSTAGES * QSTAGE_B;
    const int tid = threadIdx.x;
    const int lane = tid & 31, wid = tid >> 5;
    const int wm = wid & 3, wn = wid >> 2;
    const int n0 = blockIdx.x * 128, m0 = blockIdx.y * 128;

    const int a_row  = wm * 32 + (lane & 15);
    const int a_c16h = lane >> 4;
    const int b_row  = wn * 64 + ((lane >> 4) << 3) + (lane & 7);
    const int b_c16h = (lane >> 3) & 1;

    float acc[2][8][4];
#pragma unroll
    for (int mi = 0; mi < 2; mi++)
#pragma unroll
        for (int ni = 0; ni < 8; ni++)
#pragma unroll
            for (int u = 0; u < 4; u++) acc[mi][ni][u] = 0.f;

    if (tid == 0) {
#pragma unroll
        for (int s = 0; s < QSTAGES; s++) MBAR_INIT(mbb + s * 8, 1);
    }
    __syncthreads();

    if (tid == 0) {
#pragma unroll
        for (int s = 0; s < QSTAGES; s++) {
            const uint32_t db = sbase + s * QSTAGE_B;
            MBAR_EXPECT(mbb + s * 8, QSTAGE_B);
            TMA2D(db,        &mAf, s * 32, m0, mbb + s * 8);
            TMA2D(db + 8192, &mB,  s * 32, n0, mbb + s * 8);
        }
    }

    int s = 0, ph = 0;
    for (int it = 0; it < NCHUNK; it++) {
        mbar_wait(mbb + s * 8, ph);

        const uint32_t base = sbase + s * QSTAGE_B;
#pragma unroll
        for (int ks = 0; ks < 2; ks++) {
            uint32_t aF[2][4];
            ldsm4(aF[0], base + swoff(a_row,      ks * 2 + a_c16h));
            ldsm4(aF[1], base + swoff(a_row + 16, ks * 2 + a_c16h));
#pragma unroll
            for (int np = 0; np < 2; np++) {
                const int j0 = np * 4;
                uint32_t b0r[4], b1r[4];
                ldsm4(b0r, base + 8192 + swoff(b_row + (2*np)   * 16, ks * 2 + b_c16h));
                ldsm4(b1r, base + 8192 + swoff(b_row + (2*np+1) * 16, ks * 2 + b_c16h));
                mma16816h(acc[0][j0+0], aF[0], b0r + 0);
                mma16816h(acc[0][j0+1], aF[0], b0r + 2);
                mma16816h(acc[0][j0+2], aF[0], b1r + 0);
                mma16816h(acc[0][j0+3], aF[0], b1r + 2);
                mma16816h(acc[1][j0+0], aF[1], b0r + 0);
                mma16816h(acc[1][j0+1], aF[1], b0r + 2);
                mma16816h(acc[1][j0+2], aF[1], b1r + 0);
                mma16816h(acc[1][j0+3], aF[1], b1r + 2);
            }
        }

        if (it & 1) {
            __syncthreads();
            if (tid == 0) {
#pragma unroll
                for (int d = 0; d < 2; d++) {
                    const int nc = it - 1 + d + QSTAGES;
                    if (nc < NCHUNK) {
                        const int ts = nc % QSTAGES;
                        const uint32_t db = sbase + ts * QSTAGE_B;
                        MBAR_EXPECT(mbb + ts * 8, QSTAGE_B);
                        TMA2D(db,        &mAf, nc * 32, m0, mbb + ts * 8);
                        TMA2D(db + 8192, &mB,  nc * 32, n0, mbb + ts * 8);
                    }
                }
            }
        }
        if (++s == QSTAGES) { s = 0; ph ^= 1; }
    }

    const int r0 = m0 + wm * 32 + (lane >> 2);
    const int nb0 = n0 + wn * 64 + 2 * (lane & 3);
#pragma unroll
    for (int mi = 0; mi < 2; mi++) {
#pragma unroll
        for (int ni = 0; ni < 8; ni++) {
            const int r = r0 + mi * 16;
            const int c = nb0 + ni * 8;
            float2 bb = *(const float2*)(bias + c);
            *(float2*)(C + (long)r * 1024 + c) =
                make_float2(acc[mi][ni][0] + bb.x, acc[mi][ni][1] + bb.y);
            *(float2*)(C + (long)(r + 8) * 1024 + c) =
                make_float2(acc[mi][ni][2] + bb.x, acc[mi][ni][3] + bb.y);
        }
    }
}

// ============ gemm_kv: D[vd][kd] = sum_s v_t[vd][s] * k_t[kd][s] ===========
// grid (4 kchunks, 64 heads), 256 threads. Split-K partials (fp32).
__global__ __launch_bounds__(256, 4)
void gemm_kv(const __half* __restrict__ vt, const __half* __restrict__ kt,
             float* __restrict__ part)
{
    __shared__ __align__(16) char sm[16384];   // A(v_t) 8KB | B(k_t) 8KB
    const uint32_t sA = s2u(sm), sB = sA + 8192;
    const int tid = threadIdx.x;
    const int lane = tid & 31, wid = tid >> 5;
    const int wm = wid & 3, wn = wid >> 2;
    const int kc = blockIdx.x, head = blockIdx.y;

    float acc[4][4];
#pragma unroll
    for (int i = 0; i < 4; i++)
#pragma unroll
        for (int u = 0; u < 4; u++) acc[i][u] = 0.f;

    for (int sc = 0; sc < 8; sc++) {
        const int sg = kc * 512 + sc * 64;
#pragma unroll
        for (int j = 0; j < 4; j++) {
            const int e = tid + j * 256;       // 0..1023
            const int t = e >> 9, row = (e >> 3) & 63, c16 = e & 7;
            const __half* src = (t ? kt : vt) +
                ((long)(head * 64 + row)) * Ssz + sg + c16 * 8;
            *(uint4*)((char*)sm + t * 8192 + swoff128(row, c16)) =
                *(const uint4*)src;
        }
        __syncthreads();

#pragma unroll
        for (int ks = 0; ks < 4; ks++) {
            uint32_t aF[4];
            ldsm4(aF, sA + swoff128(wm * 16 + (lane & 15), ks * 2 + (lane >> 4)));
#pragma unroll
            for (int nb = 0; nb < 2; nb++) {
                uint32_t bF[4];
                ldsm4(bF, sB + swoff128(wn * 32 + nb * 16 +
                                        ((lane >> 4) << 3) + (lane & 7),
                                        ks * 2 + ((lane >> 3) & 1)));
                mma16816h(acc[nb * 2 + 0], aF, bF + 0);
                mma16816h(acc[nb * 2 + 1], aF, bF + 2);
            }
        }
        __syncthreads();
    }

    float* pb = part + ((long)(kc * 64 + head)) * 4096;
    const int rb = wm * 16 + (lane >> 2);
    const int cb = wn * 32 + 2 * (lane & 3);
#pragma unroll
    for (int nf = 0; nf < 4; nf++) {
        const int c = cb + nf * 8;
        *(float2*)(pb + rb * 64 + c)       = make_float2(acc[nf][0], acc[nf][1]);
        *(float2*)(pb + (rb + 8) * 64 + c) = make_float2(acc[nf][2], acc[nf][3]);
    }
}

// ==== kvt_finalize: reduce partials -> kvt hi/lo; row64 = ksum; 65-71 = 0 ==
__global__ void kvt_finalize(const float* __restrict__ part,
                             const __half* __restrict__ kt,
                             __half* __restrict__ kvh, __half* __restrict__ kvl)
{
    const int head = blockIdx.x;
    const int tid = threadIdx.x;
    const long ob = (long)head * 72 * 64;

    // rows 0-63: reduce 4 split-K partials, hi/lo split
    for (int e = tid; e < 4096; e += 256) {
        float s = 0.f;
#pragma unroll
        for (int c = 0; c < 4; c++)
            s += part[((long)(c * 64 + head)) * 4096 + e];
        __half h = __float2half(s);
        kvh[ob + e] = h;
        kvl[ob + e] = __float2half(s - __half2float(h));
    }

    // row 64: ksum[kd] = sum_s k_t[kd][s]
    const int kd = tid >> 2, qtr = tid & 3;
    const __half* kr = kt + ((long)(head * 64 + kd)) * Ssz + qtr * 512;
    float s = 0.f;
#pragma unroll 8
    for (int i = 0; i < 64; i++) {
        uint4 u = *(const uint4*)(kr + i * 8);
        float2 a = __half22float2(*(__half2*)&u.x);
        float2 b = __half22float2(*(__half2*)&u.y);
        float2 c = __half22float2(*(__half2*)&u.z);
        float2 d = __half22float2(*(__half2*)&u.w);
        s += a.x + a.y + b.x + b.y + c.x + c.y + d.x + d.y;
    }
    s += __shfl_down_sync(0xffffffffu, s, 2);
    s += __shfl_down_sync(0xffffffffu, s, 1);
    if (qtr == 0) {
        __half h = __float2half(s);
        kvh[ob + 64 * 64 + kd] = h;
        kvl[ob + 64 * 64 + kd] = __float2half(s - __half2float(h));
    }

    // rows 65-71: zero
    for (int e = tid; e < 7 * 64; e += 256) {
        kvh[ob + 65 * 64 + e] = __float2half(0.f);
        kvl[ob + 65 * 64 + e] = __float2half(0.f);
    }
}

// ==== gemm_cmb: num/den = q @ kvt^T (hi+lo); gate epilogue -> comb fp16 ====
// grid (16 mtiles, 64 heads), 256 threads. B rows: 0-63 kv, 64 ksum(den).
__global__ __launch_bounds__(256, 2)
void gemm_cmb(const __half* __restrict__ q,
              const __half* __restrict__ kvh, const __half* __restrict__ kvl,
              const float* __restrict__ gate,
              const float* __restrict__ df, const float* __restrict__ gw,
              __half* __restrict__ cf)
{
    __shared__ __align__(16) char sm[16384 + 2 * 10240];  // A 16K | Bh 10K | Bl 10K
    const uint32_t sA = s2u(sm);
    const uint32_t sBh = sA + 16384, sBl = sBh + 10240;
    const int tid = threadIdx.x;
    const int lane = tid & 31, wid = tid >> 5;
    const int mt = blockIdx.x, bn = blockIdx.y;
    const int b = bn >> 4, n = bn & 15;
    const long row0 = (long)b * Ssz + mt * 128;

    // coef
    float w0 = gw[0], w1 = gw[1], w2 = gw[2];
    float d0 = df[0], d1 = df[1], d2 = df[2];
    float mx = fmaxf(w0, fmaxf(w1, w2));
    float e0 = expf(w0 - mx), e1 = expf(w1 - mx), e2 = expf(w2 - mx);
    float s0f = 1.f / (1.f + expf(-d0));
    float s1f = 1.f / (1.f + expf(-d1));
    float s2f = 1.f / (1.f + expf(-d2));
    float coef = (e0 * (1.f - s0f) + e1 * (1.f - s1f) + e2 * (1.f - s2f)) / (e0 + e1 + e2);

    // load A tile [128 rows][64 halves] from q
#pragma unroll
    for (int j = 0; j < 4; j++) {
        const int e = tid + j * 256;          // 0..1023
        const int row = e >> 3, c16 = e & 7;
        *(uint4*)((char*)sm + swoff128(row, c16)) =
            *(const uint4*)(q + (row0 + row) * 1024 + n * 64 + c16 * 8);
    }
    // load B hi/lo [72 rows][64 halves]
    for (int e = tid; e < 1152; e += 256) {
        const int t = e >= 576, ee = t ? e - 576 : e;
        const int row = ee >> 3, c16 = ee & 7;
        const __half* src = (t ? kvl : kvh) + (long)bn * 4608 + row * 64 + c16 * 8;
        *(uint4*)((char*)sm + 16384 + t * 10240 + swoff128(row, c16)) =
            *(const uint4*)src;
    }
    __syncthreads();

    float acc[9][4];
#pragma unroll
    for (int i = 0; i < 9; i++)
#pragma unroll
        for (int u = 0; u < 4; u++) acc[i][u] = 0.f;

#pragma unroll
    for (int ks = 0; ks < 4; ks++) {
        uint32_t aF[4];
        ldsm4(aF, sA + swoff128(wid * 16 + (lane & 15), ks * 2 + (lane >> 4)));
        const int brow = ((lane >> 4) << 3) + (lane & 7);
        const int bc16 = ks * 2 + ((lane >> 3) & 1);
#pragma unroll
        for (int nf = 0; nf < 4; nf++) {
            uint32_t bH[4], bL[4];
            ldsm4(bH, sBh + swoff128(nf * 16 + brow, bc16));
            ldsm4(bL, sBl + swoff128(nf * 16 + brow, bc16));
            mma16816h(acc[nf * 2 + 0], aF, bH + 0);
            mma16816h(acc[nf * 2 + 1], aF, bH + 2);
            mma16816h(acc[nf * 2 + 0], aF, bL + 0);
            mma16816h(acc[nf * 2 + 1], aF, bL + 2);
        }
        uint32_t bH[4], bL[4];
        ldsm4(bH, sBh + swoff128(64 + brow, bc16));
        ldsm4(bL, sBl + swoff128(64 + brow, bc16));
        mma16816h(acc[8], aF, bH + 0);
        mma16816h(acc[8], aF, bL + 0);
    }

    // epilogue: den broadcast via shfl within quad, gate mix, store fp16
#pragma unroll
    for (int u = 0; u < 4; u += 2) {
        const int rloc = wid * 16 + (lane >> 2) + (u ? 8 : 0);
        const long gr = row0 + rloc;
        float den = __shfl_sync(0xffffffffu, acc[8][u], lane & ~3) + EPSF;
        const float g = gate[gr];
        const float fac = g / den + (1.f - g) * coef;
#pragma unroll
        for (int ni = 0; ni < 8; ni++) {
            const int c = 2 * (lane & 3) + ni * 8;
            *(__half2*)(cf + gr * 1024 + n * 64 + c) =
                pack_h2(acc[ni][u] * fac, acc[ni][u + 1] * fac);
        }
    }
}

// ================= rope table ==============================================
__global__ void rope_table_kernel(float2* __restrict__ tab)
{
    const int idx = blockIdx.x * 256 + threadIdx.x;
    const int i = idx & 31, s = idx >> 5;
    double p = pow(10000.0, (double)(2 * i) / 64.0);
    float f = (float)s * (1.0f / (float)p);
    tab[idx] = make_float2(cosf(f), sinf(f));
}

// ============ cvt x -> single fp16 + gate (one block per row) ==============
__global__ void cvt_x_gate(const float4* __restrict__ x,
                           const float4* __restrict__ Wg,
                           const float* __restrict__ bg,
                           uint2* __restrict__ xf,
                           float* __restrict__ gout)
{
    const int row = blockIdx.x;
    const int tid = threadIdx.x;
    const long i = (long)row * 256 + tid;
    float4 v = x[i];
    float4 w = Wg[tid];
    float dot = v.x * w.x + v.y * w.y + v.z * w.z + v.w * w.w;

    float f[4] = {v.x, v.y, v.z, v.w};
    unsigned short hs[4];
#pragma unroll
    for (int j = 0; j < 4; j++) {
        __half h = __float2half(f[j]);
        hs[j] = *(unsigned short*)&h;
    }
    uint2 H;
    H.x = (uint32_t)hs[0] | ((uint32_t)hs[1] << 16);
    H.y = (uint32_t)hs[2] | ((uint32_t)hs[3] << 16);
    xf[i] = H;

#pragma unroll
    for (int o = 16; o; o >>= 1) dot += __shfl_down_sync(0xffffffffu, dot, o);
    __shared__ float ws[8];
    if ((tid & 31) == 0) ws[tid >> 5] = dot;
    __syncthreads();
    if (tid == 0) {
        float t = 0.f;
#pragma unroll
        for (int j = 0; j < 8; j++) t += ws[j];
        t += bg[0];
        gout[row] = 1.f / (1.f + expf(-t));
    }
}

// W[K][N] fp32 -> transposed single fp16 [N][K]; z selects which W
__global__ void cvt_w4(const float* __restrict__ W0, const float* __restrict__ W1,
                       const float* __restrict__ W2, const float* __restrict__ W3,
                       __half* __restrict__ h0, __half* __restrict__ h1,
                       __half* __restrict__ h2, __half* __restrict__ h3)
{
    const int z = blockIdx.z;
    const float* W = (z == 0) ? W0 : (z == 1) ? W1 : (z == 2) ? W2 : W3;
    __half* bh = (z == 0) ? h0 : (z == 1) ? h1 : (z == 2) ? h2 : h3;

    __shared__ float t[32][33];
    const int nx = blockIdx.x * 32, kx = blockIdx.y * 32;
    const int tx = threadIdx.x, ty = threadIdx.y;
#pragma unroll
    for (int r = 0; r < 32; r += 8)
        t[ty + r][tx] = W[(long)(kx + ty + r) * 1024 + nx + tx];
    __syncthreads();
#pragma unroll
    for (int r = 0; r < 32; r += 8) {
        float v = t[tx][ty + r];
        long o = (long)(nx + ty + r) * 1024 + kx + tx;
        bh[o] = __float2half(v);
    }
}

// ================= host: tensormap construction ============================
typedef CUresult (*PFN_encodeTiled)(
    CUtensorMap*, CUtensorMapDataType, cuuint32_t, void*,
    const cuuint64_t*, const cuuint64_t*, const cuuint32_t*, const cuuint32_t*,
    CUtensorMapInterleave, CUtensorMapSwizzle, CUtensorMapL2promotion,
    CUtensorMapFloatOOBfill);

static PFN_encodeTiled get_encoder() {
    static PFN_encodeTiled fn = nullptr;
    if (!fn) {
        void* p = nullptr;
        cudaDriverEntryPointQueryResult st;
        cudaGetDriverEntryPointByVersion("cuTensorMapEncodeTiled", &p, 12000,
                                         cudaEnableDefault, &st);
        fn = (PFN_encodeTiled)p;
    }
    return fn;
}

static void make_map(CUtensorMap* m, void* base, uint64_t rows) {
    cuuint64_t dims[2]    = {1024, rows};
    cuuint64_t strides[1] = {2048};
    cuuint32_t box[2]     = {32, 128};
    cuuint32_t es[2]      = {1, 1};
    get_encoder()(m, CU_TENSOR_MAP_DATA_TYPE_FLOAT16, 2, base, dims, strides,
                  box, es, CU_TENSOR_MAP_INTERLEAVE_NONE,
                  CU_TENSOR_MAP_SWIZZLE_64B, CU_TENSOR_MAP_L2_PROMOTION_L2_128B,
                  CU_TENSOR_MAP_FLOAT_OOB_FILL_NONE);
}

// ---------------------------------------------------------------------------
extern "C" void kernel_launch(void* const* d_in, const int* in_sizes, int n_in,
                              void* d_out, int out_size)
{
    const float* x    = (const float*)d_in[0];
    const float* mask = (const float*)d_in[1];
    const float* Wq   = (const float*)d_in[2];
    const float* bq   = (const float*)d_in[3];
    const float* Wk   = (const float*)d_in[4];
    const float* bk   = (const float*)d_in[5];
    const float* Wv   = (const float*)d_in[6];
    const float* bv   = (const float*)d_in[7];
    const float* Wo   = (const float*)d_in[8];
    const float* bo   = (const float*)d_in[9];
    const float* Wg   = (const float*)d_in[10];
    const float* bg   = (const float*)d_in[11];
    const float* df   = (const float*)d_in[12];
    const float* gw   = (const float*)d_in[13];
    float* out = (float*)d_out;

    float *kvp, *gate;
    float2* tab;
    __half *q16, *kt, *vt, *kvh, *kvl, *af, *bq16, *bk16, *bv16, *bo16;
    cudaGetSymbolAddress((void**)&q16,  g_q16);
    cudaGetSymbolAddress((void**)&kt,   g_kt);
    cudaGetSymbolAddress((void**)&vt,   g_vt);
    cudaGetSymbolAddress((void**)&kvp,  g_kv_part);
    cudaGetSymbolAddress((void**)&kvh,  g_kvt_h);
    cudaGetSymbolAddress((void**)&kvl,  g_kvt_l);
    cudaGetSymbolAddress((void**)&gate, g_gate);
    cudaGetSymbolAddress((void**)&tab,  g_rope);
    cudaGetSymbolAddress((void**)&af,   g_af);
    cudaGetSymbolAddress((void**)&bq16, g_bq16);
    cudaGetSymbolAddress((void**)&bk16, g_bk16);
    cudaGetSymbolAddress((void**)&bv16, g_bv16);
    cudaGetSymbolAddress((void**)&bo16, g_bo16);

    CUtensorMap mAf, mQ, mK, mV, mO;
    make_map(&mAf, af, Msz);
    make_map(&mQ,  bq16, Hsz);
    make_map(&mK,  bk16, Hsz);
    make_map(&mV,  bv16, Hsz);
    make_map(&mO,  bo16, Hsz);

    cudaFuncSetAttribute(gemm_qkv,
                         cudaFuncAttributeMaxDynamicSharedMemorySize, SMEM_QKV);
    cudaFuncSetAttribute(gemm_out,
                         cudaFuncAttributeMaxDynamicSharedMemorySize, SMEM_QKV);

    // 1. rope table
    rope_table_kernel<<<Ssz * 32 / 256, 256>>>(tab);
    // 2. activation -> single fp16 + gate
    cvt_x_gate<<<Msz, 256>>>((const float4*)x, (const float4*)Wg, bg,
                             (uint2*)af, gate);
    // 3. weight conversions
    cvt_w4<<<dim3(32, 32, 4), dim3(32, 8)>>>(Wq, Wk, Wv, Wo,
                                             bq16, bk16, bv16, bo16);
    // 4. fused QKV projection; q -> [s][1024], k/v -> transposed fp16
    gemm_qkv<<<dim3(8, 64, 3), 256, SMEM_QKV>>>(
        mAf, mQ, mK, mV, bq, bk, bv, q16, kt, vt, mask, tab);
    // 5. kv outer-product GEMM (split-K partials)
    gemm_kv<<<dim3(4, 64), 256>>>(vt, kt, kvp);
    // 6. reduce partials + ksum -> kvt hi/lo
    kvt_finalize<<<64, 256>>>(kvp, kt, kvh, kvl);
    // 7. combine GEMM (num + den in one MMA) + gate epilogue -> af fp16
    gemm_cmb<<<dim3(16, 64), 256>>>(q16, kvh, kvl, gate, df, gw, af);
    // 8. output projection
    gemm_out<<<dim3(8, 64), 256, SMEM_QKV>>>(mAf, mO, bo, out);
}

// round 13
// speedup vs baseline: 6.4132x; 1.0061x over previous
#include <cuda_runtime.h>
#include <cuda.h>
#include <cuda_bf16.h>
#include <cuda_fp16.h>
#include <math.h>
#include <stdint.h>

// Problem constants
#define Bsz 4
#define Ssz 2048
#define Hsz 1024
#define Nh  16
#define Dh  64
#define Msz (Bsz*Ssz)      // 8192
#define EPSF 1e-6f

// ---------------- scratch (static device globals; no allocs allowed) -------
__device__ __half g_q16[Msz*Hsz];         // q (phi'd, scaled) fp16 [s][1024]
__device__ __half g_kt[64*64*Ssz];        // k transposed [bn][kd][s] fp16
__device__ __half g_vt[64*64*Ssz];        // v transposed [bn][vd][s] fp16
__device__ float g_kv_part[4*64*64*64];   // [kc][bn][vd][kd]
__device__ __half g_kvt_h[64*72*64];      // [bn][72][64]: rows0-63 kv, 64 ksum
__device__ __half g_kvt_l[64*72*64];
__device__ float g_gate[Msz];
__device__ float2 g_rope[Ssz*32];         // (cos, sin) per (s, i)
__device__ __half g_af[Msz*Hsz];          // x fp16 (QKV phase), comb fp16 after
__device__ __half g_bq16[Hsz*Hsz];        // Wq single fp16 [N][K]
__device__ __half g_bk16[Hsz*Hsz];
__device__ __half g_bv16[Hsz*Hsz];
__device__ __half g_bo16[Hsz*Hsz];

// ================= low-level helpers =======================================
static __device__ __forceinline__ uint32_t s2u(const void* p) {
    uint32_t a;
    asm("{ .reg .u64 t; cvta.to.shared.u64 t, %1; cvt.u32.u64 %0, t; }"
        : "=r"(a) : "l"(p));
    return a;
}

static __device__ __forceinline__ void ldsm4(uint32_t* r, uint32_t addr) {
    asm volatile("ldmatrix.sync.aligned.m8n8.x4.shared.b16 {%0,%1,%2,%3}, [%4];"
                 : "=r"(r[0]), "=r"(r[1]), "=r"(r[2]), "=r"(r[3]) : "r"(addr));
}

static __device__ __forceinline__ void mma16816h(float* d, const uint32_t* a,
                                                 const uint32_t* b) {
    asm volatile(
        "mma.sync.aligned.m16n8k16.row.col.f32.f16.f16.f32 "
        "{%0,%1,%2,%3}, {%4,%5,%6,%7}, {%8,%9}, {%0,%1,%2,%3};"
        : "+f"(d[0]), "+f"(d[1]), "+f"(d[2]), "+f"(d[3])
        : "r"(a[0]), "r"(a[1]), "r"(a[2]), "r"(a[3]), "r"(b[0]), "r"(b[1]));
}

// 64B-row tile swizzle (TMA SW64 tiles: rows of 32 halves)
static __device__ __forceinline__ uint32_t swoff(int row, int c16) {
    return (uint32_t)(row * 64 + ((c16 ^ ((row >> 1) & 3)) << 4));
}
// 128B-row tile swizzle (plain-load tiles: rows of 64 halves, 8 c16 chunks)
static __device__ __forceinline__ uint32_t swoff128(int row, int c16) {
    return (uint32_t)(row * 128 + ((c16 ^ (row & 7)) << 4));
}

#define MBAR_INIT(m, c) \
    asm volatile("mbarrier.init.shared.b64 [%0], %1;" \
                 :: "r"((uint32_t)(m)), "r"((uint32_t)(c)) : "memory")
#define MBAR_EXPECT(m, b) \
    asm volatile("mbarrier.arrive.expect_tx.shared.b64 _, [%0], %1;" \
                 :: "r"((uint32_t)(m)), "r"((uint32_t)(b)) : "memory")

static __device__ __forceinline__ void mbar_wait(uint32_t mbar, uint32_t parity) {
    asm volatile(
        "{\n\t.reg .pred P;\n\t"
        "WL_%=:\n\t"
        "mbarrier.try_wait.parity.acquire.cta.shared::cta.b64 P, [%0], %1, 0x989680;\n\t"
        "@P bra.uni WD_%=;\n\t"
        "bra.uni WL_%=;\n\t"
        "WD_%=:\n\t}"
        :: "r"(mbar), "r"(parity) : "memory");
}

#define TMA2D(sa, mp, cx, cy, mb) \
    asm volatile("cp.async.bulk.tensor.2d.shared::cta.global.tile.mbarrier::complete_tx::bytes " \
                 "[%0], [%1, {%2, %3}], [%4];" \
                 :: "r"((uint32_t)(sa)), "l"(mp), "r"((int)(cx)), "r"((int)(cy)), \
                    "r"((uint32_t)(mb)) : "memory")

__device__ __forceinline__ float phi_fn(float x) {
    float t = (x > 0.f) ? x : expm1f(x);
    return (t + 1.0f) + EPSF;
}

static __device__ __forceinline__ __half2 pack_h2(float a, float b) {
    return __halves2half2(__float2half(a), __float2half(b));
}

// ===== GEMM mainloop config: BK=64 stages (two 8KB halves per operand) =====
// stage 32KB: [A0 8K][A1 8K][B0 8K][B1 8K]; 3 stages; 16 pairs of K-chunks.
#define PSTAGES 3
#define PSTAGE_B 32768
#define NPAIR 16
#define SMEM_GEMM (PSTAGES * PSTAGE_B + 64)

// Shared mainloop macro body implemented as a device function via lambda-ish
// pattern is awkward; duplicate the small loop in both kernels instead.

// ========== QKV GEMM: single-product fp16 =================================
// z=0: q -> rope/phi*0.125, fp16 [s][1024]
// z=1: k -> rope/phi*mask, fp16 TRANSPOSED [bn][kd][s]
// z=2: v -> mask, fp16 TRANSPOSED [bn][vd][s]
__global__ __launch_bounds__(256, 2)
void gemm_qkv(const __grid_constant__ CUtensorMap mAf,
              const __grid_constant__ CUtensorMap mB0,
              const __grid_constant__ CUtensorMap mB1,
              const __grid_constant__ CUtensorMap mB2,
              const float* __restrict__ b0, const float* __restrict__ b1,
              const float* __restrict__ b2,
              __half* __restrict__ Cq, __half* __restrict__ KT,
              __half* __restrict__ VT,
              const float* __restrict__ maskp,
              const float2* __restrict__ tab)
{
    extern __shared__ __align__(1024) char smem[];
    const uint32_t sbase = s2u(smem);
    const uint32_t mbb  = sbase + PSTAGES * PSTAGE_B;
    const int tid = threadIdx.x;
    const int lane = tid & 31, wid = tid >> 5;
    const int wm = wid & 3, wn = wid >> 2;
    const int n0 = blockIdx.x * 128, m0 = blockIdx.y * 128;
    const int z = blockIdx.z;

    const CUtensorMap* pB = (z == 0) ? &mB0 : (z == 1) ? &mB1 : &mB2;
    const float* bias = (z == 0) ? b0 : (z == 1) ? b1 : b2;

    const int a_row  = wm * 32 + (lane & 15);
    const int a_c16h = lane >> 4;
    const int b_row  = wn * 64 + ((lane >> 4) << 3) + (lane & 7);
    const int b_c16h = (lane >> 3) & 1;

    float acc[2][8][4];
#pragma unroll
    for (int mi = 0; mi < 2; mi++)
#pragma unroll
        for (int ni = 0; ni < 8; ni++)
#pragma unroll
            for (int u = 0; u < 4; u++) acc[mi][ni][u] = 0.f;

    if (tid == 0) {
#pragma unroll
        for (int s = 0; s < PSTAGES; s++) MBAR_INIT(mbb + s * 8, 1);
    }
    __syncthreads();

    if (tid == 0) {
#pragma unroll
        for (int s = 0; s < PSTAGES; s++) {
            const uint32_t db = sbase + s * PSTAGE_B;
            MBAR_EXPECT(mbb + s * 8, PSTAGE_B);
            TMA2D(db,         &mAf, s * 64,      m0, mbb + s * 8);
            TMA2D(db + 8192,  &mAf, s * 64 + 32, m0, mbb + s * 8);
            TMA2D(db + 16384, pB,   s * 64,      n0, mbb + s * 8);
            TMA2D(db + 24576, pB,   s * 64 + 32, n0, mbb + s * 8);
        }
    }

    int sp = 0, ph = 0;
    for (int p = 0; p < NPAIR; p++) {
        mbar_wait(mbb + sp * 8, ph);

        const uint32_t bA = sbase + sp * PSTAGE_B;
        const uint32_t bB = bA + 16384;

        uint32_t aF[2][2][4];
        ldsm4(aF[0][0], bA + swoff(a_row,      a_c16h));
        ldsm4(aF[0][1], bA + swoff(a_row + 16, a_c16h));
#pragma unroll
        for (int ks = 0; ks < 4; ks++) {
            const int cur = ks & 1, nxt = cur ^ 1;
            const uint32_t hB = bB + (ks >> 1) * 8192;
            const int kk = ks & 1;
            uint32_t br[4][4];
#pragma unroll
            for (int nf = 0; nf < 4; nf++)
                ldsm4(br[nf], hB + swoff(b_row + nf * 16, kk * 2 + b_c16h));
            if (ks < 3) {
                const uint32_t hA2 = bA + ((ks + 1) >> 1) * 8192;
                const int kk2 = (ks + 1) & 1;
                ldsm4(aF[nxt][0], hA2 + swoff(a_row,      kk2 * 2 + a_c16h));
                ldsm4(aF[nxt][1], hA2 + swoff(a_row + 16, kk2 * 2 + a_c16h));
            }
#pragma unroll
            for (int nf = 0; nf < 4; nf++) {
                mma16816h(acc[0][nf * 2 + 0], aF[cur][0], br[nf] + 0);
                mma16816h(acc[0][nf * 2 + 1], aF[cur][0], br[nf] + 2);
                mma16816h(acc[1][nf * 2 + 0], aF[cur][1], br[nf] + 0);
                mma16816h(acc[1][nf * 2 + 1], aF[cur][1], br[nf] + 2);
            }
        }

        __syncthreads();   // all threads done reading stage sp
        const int np_ = p + PSTAGES;
        if (np_ < NPAIR && tid == 0) {
            const uint32_t db = sbase + sp * PSTAGE_B;
            MBAR_EXPECT(mbb + sp * 8, PSTAGE_B);
            TMA2D(db,         &mAf, np_ * 64,      m0, mbb + sp * 8);
            TMA2D(db + 8192,  &mAf, np_ * 64 + 32, m0, mbb + sp * 8);
            TMA2D(db + 16384, pB,   np_ * 64,      n0, mbb + sp * 8);
            TMA2D(db + 24576, pB,   np_ * 64 + 32, n0, mbb + sp * 8);
        }
        if (++sp == PSTAGES) { sp = 0; ph ^= 1; }
    }

    // ---------------- epilogue ----------------
    const int r0 = m0 + wm * 32 + (lane >> 2);
    const int nb0 = n0 + wn * 64 + 2 * (lane & 3);

    if (z == 0) {
#pragma unroll
        for (int mi = 0; mi < 2; mi++) {
#pragma unroll
            for (int uu = 0; uu < 4; uu += 2) {
                const int r = r0 + mi * 16 + (uu ? 8 : 0);
                const int srow = r & (Ssz - 1);
#pragma unroll
                for (int ni = 0; ni < 4; ni++) {
                    float o1[2], o2[2];
#pragma unroll
                    for (int e = 0; e < 2; e++) {
                        const int i = 2 * (lane & 3) + ni * 8 + e;
                        const int c = nb0 + ni * 8 + e;
                        float x1 = acc[mi][ni][uu + e]     + bias[c];
                        float x2 = acc[mi][ni + 4][uu + e] + bias[c + 32];
                        float2 cs = tab[srow * 32 + i];
                        float r1 = x1 * cs.x - x2 * cs.y;
                        float r2 = x2 * cs.x + x1 * cs.y;
                        o1[e] = phi_fn(r1) * 0.125f;
                        o2[e] = phi_fn(r2) * 0.125f;
                    }
                    const int c = nb0 + ni * 8;
                    *(__half2*)(Cq + (long)r * 1024 + c)      = pack_h2(o1[0], o1[1]);
                    *(__half2*)(Cq + (long)r * 1024 + c + 32) = pack_h2(o2[0], o2[1]);
                }
            }
        }
        return;
    }

    // k/v: transposed store via smem staging. ts[c_local][rloc], pitch 136.
    __syncthreads();
    __half* ts = (__half*)smem;
    const int rb = wm * 32 + (lane >> 2);
    const int cb = wn * 64 + 2 * (lane & 3);

#pragma unroll
    for (int mi = 0; mi < 2; mi++) {
#pragma unroll
        for (int uu = 0; uu < 4; uu += 2) {
            const int rloc = rb + mi * 16 + (uu ? 8 : 0);
            const int r = m0 + rloc;
            const int srow = r & (Ssz - 1);
            const float msk = maskp[r];
            if (z == 2) {
#pragma unroll
                for (int ni = 0; ni < 8; ni++) {
#pragma unroll
                    for (int e = 0; e < 2; e++) {
                        const int cl = cb + ni * 8 + e;
                        float val = (acc[mi][ni][uu + e] + bias[n0 + cl]) * msk;
                        ts[cl * 136 + rloc] = __float2half(val);
                    }
                }
            } else {
#pragma unroll
                for (int ni = 0; ni < 4; ni++) {
#pragma unroll
                    for (int e = 0; e < 2; e++) {
                        const int i = 2 * (lane & 3) + ni * 8 + e;
                        const int cl = cb + ni * 8 + e;
                        float x1 = acc[mi][ni][uu + e]     + bias[n0 + cl];
                        float x2 = acc[mi][ni + 4][uu + e] + bias[n0 + cl + 32];
                        float2 cs = tab[srow * 32 + i];
                        float r1 = x1 * cs.x - x2 * cs.y;
                        float r2 = x2 * cs.x + x1 * cs.y;
                        ts[cl * 136 + rloc]        = __float2half(phi_fn(r1) * msk);
                        ts[(cl + 32) * 136 + rloc] = __float2half(phi_fn(r2) * msk);
                    }
                }
            }
        }
    }
    __syncthreads();

    __half* T = (z == 1) ? KT : VT;
    const int b = m0 >> 11;
    const int sb = m0 & (Ssz - 1);
#pragma unroll
    for (int i = 0; i < 8; i++) {
        const int e = tid + i * 256;
        const int c = e >> 4, ch = e & 15, rl = ch * 8;
        uint4 val = *(uint4*)&ts[c * 136 + rl];
        const int bn = b * 16 + (n0 >> 6) + (c >> 6);
        const int d = c & 63;
        *(uint4*)(T + ((long)(bn * 64 + d)) * Ssz + sb + rl) = val;
    }
}

// ===== OUT GEMM: single-product fp16, BK=64 stages, fp32 store =============
__global__ __launch_bounds__(256, 2)
void gemm_out(const __grid_constant__ CUtensorMap mAf,
              const __grid_constant__ CUtensorMap mB,
              const float* __restrict__ bias, float* __restrict__ C)
{
    extern __shared__ __align__(1024) char smem[];
    const uint32_t sbase = s2u(smem);
    const uint32_t mbb  = sbase + PSTAGES * PSTAGE_B;
    const int tid = threadIdx.x;
    const int lane = tid & 31, wid = tid >> 5;
    const int wm = wid & 3, wn = wid >> 2;
    const int n0 = blockIdx.x * 128, m0 = blockIdx.y * 128;

    const int a_row  = wm * 32 + (lane & 15);
    const int a_c16h = lane >> 4;
    const int b_row  = wn * 64 + ((lane >> 4) << 3) + (lane & 7);
    const int b_c16h = (lane >> 3) & 1;

    float acc[2][8][4];
#pragma unroll
    for (int mi = 0; mi < 2; mi++)
#pragma unroll
        for (int ni = 0; ni < 8; ni++)
#pragma unroll
            for (int u = 0; u < 4; u++) acc[mi][ni][u] = 0.f;

    if (tid == 0) {
#pragma unroll
        for (int s = 0; s < PSTAGES; s++) MBAR_INIT(mbb + s * 8, 1);
    }
    __syncthreads();

    if (tid == 0) {
#pragma unroll
        for (int s = 0; s < PSTAGES; s++) {
            const uint32_t db = sbase + s * PSTAGE_B;
            MBAR_EXPECT(mbb + s * 8, PSTAGE_B);
            TMA2D(db,         &mAf, s * 64,      m0, mbb + s * 8);
            TMA2D(db + 8192,  &mAf, s * 64 + 32, m0, mbb + s * 8);
            TMA2D(db + 16384, &mB,  s * 64,      n0, mbb + s * 8);
            TMA2D(db + 24576, &mB,  s * 64 + 32, n0, mbb + s * 8);
        }
    }

    int sp = 0, ph = 0;
    for (int p = 0; p < NPAIR; p++) {
        mbar_wait(mbb + sp * 8, ph);

        const uint32_t bA = sbase + sp * PSTAGE_B;
        const uint32_t bB = bA + 16384;

        uint32_t aF[2][2][4];
        ldsm4(aF[0][0], bA + swoff(a_row,      a_c16h));
        ldsm4(aF[0][1], bA + swoff(a_row + 16, a_c16h));
#pragma unroll
        for (int ks = 0; ks < 4; ks++) {
            const int cur = ks & 1, nxt = cur ^ 1;
            const uint32_t hB = bB + (ks >> 1) * 8192;
            const int kk = ks & 1;
            uint32_t br[4][4];
#pragma unroll
            for (int nf = 0; nf < 4; nf++)
                ldsm4(br[nf], hB + swoff(b_row + nf * 16, kk * 2 + b_c16h));
            if (ks < 3) {
                const uint32_t hA2 = bA + ((ks + 1) >> 1) * 8192;
                const int kk2 = (ks + 1) & 1;
                ldsm4(aF[nxt][0], hA2 + swoff(a_row,      kk2 * 2 + a_c16h));
                ldsm4(aF[nxt][1], hA2 + swoff(a_row + 16, kk2 * 2 + a_c16h));
            }
#pragma unroll
            for (int nf = 0; nf < 4; nf++) {
                mma16816h(acc[0][nf * 2 + 0], aF[cur][0], br[nf] + 0);
                mma16816h(acc[0][nf * 2 + 1], aF[cur][0], br[nf] + 2);
                mma16816h(acc[1][nf * 2 + 0], aF[cur][1], br[nf] + 0);
                mma16816h(acc[1][nf * 2 + 1], aF[cur][1], br[nf] + 2);
            }
        }

        __syncthreads();
        const int np_ = p + PSTAGES;
        if (np_ < NPAIR && tid == 0) {
            const uint32_t db = sbase + sp * PSTAGE_B;
            MBAR_EXPECT(mbb + sp * 8, PSTAGE_B);
            TMA2D(db,         &mAf, np_ * 64,      m0, mbb + sp * 8);
            TMA2D(db + 8192,  &mAf, np_ * 64 + 32, m0, mbb + sp * 8);
            TMA2D(db + 16384, &mB,  np_ * 64,      n0, mbb + sp * 8);
            TMA2D(db + 24576, &mB,  np_ * 64 + 32, n0, mbb + sp * 8);
        }
        if (++sp == PSTAGES) { sp = 0; ph ^= 1; }
    }

    const int r0 = m0 + wm * 32 + (lane >> 2);
    const int nb0 = n0 + wn * 64 + 2 * (lane & 3);
#pragma unroll
    for (int mi = 0; mi < 2; mi++) {
#pragma unroll
        for (int ni = 0; ni < 8; ni++) {
            const int r = r0 + mi * 16;
            const int c = nb0 + ni * 8;
            float2 bb = *(const float2*)(bias + c);
            *(float2*)(C + (long)r * 1024 + c) =
                make_float2(acc[mi][ni][0] + bb.x, acc[mi][ni][1] + bb.y);
            *(float2*)(C + (long)(r + 8) * 1024 + c) =
                make_float2(acc[mi][ni][2] + bb.x, acc[mi][ni][3] + bb.y);
        }
    }
}

// ============ gemm_kv: D[vd][kd] = sum_s v_t[vd][s] * k_t[kd][s] ===========
__global__ __launch_bounds__(256, 4)
void gemm_kv(const __half* __restrict__ vt, const __half* __restrict__ kt,
             float* __restrict__ part)
{
    __shared__ __align__(16) char sm[16384];
    const uint32_t sA = s2u(sm), sB = sA + 8192;
    const int tid = threadIdx.x;
    const int lane = tid & 31, wid = tid >> 5;
    const int wm = wid & 3, wn = wid >> 2;
    const int kc = blockIdx.x, head = blockIdx.y;

    float acc[4][4];
#pragma unroll
    for (int i = 0; i < 4; i++)
#pragma unroll
        for (int u = 0; u < 4; u++) acc[i][u] = 0.f;

    for (int sc = 0; sc < 8; sc++) {
        const int sg = kc * 512 + sc * 64;
#pragma unroll
        for (int j = 0; j < 4; j++) {
            const int e = tid + j * 256;
            const int t = e >> 9, row = (e >> 3) & 63, c16 = e & 7;
            const __half* src = (t ? kt : vt) +
                ((long)(head * 64 + row)) * Ssz + sg + c16 * 8;
            *(uint4*)((char*)sm + t * 8192 + swoff128(row, c16)) =
                *(const uint4*)src;
        }
        __syncthreads();

#pragma unroll
        for (int ks = 0; ks < 4; ks++) {
            uint32_t aF[4];
            ldsm4(aF, sA + swoff128(wm * 16 + (lane & 15), ks * 2 + (lane >> 4)));
#pragma unroll
            for (int nb = 0; nb < 2; nb++) {
                uint32_t bF[4];
                ldsm4(bF, sB + swoff128(wn * 32 + nb * 16 +
                                        ((lane >> 4) << 3) + (lane & 7),
                                        ks * 2 + ((lane >> 3) & 1)));
                mma16816h(acc[nb * 2 + 0], aF, bF + 0);
                mma16816h(acc[nb * 2 + 1], aF, bF + 2);
            }
        }
        __syncthreads();
    }

    float* pb = part + ((long)(kc * 64 + head)) * 4096;
    const int rb = wm * 16 + (lane >> 2);
    const int cb = wn * 32 + 2 * (lane & 3);
#pragma unroll
    for (int nf = 0; nf < 4; nf++) {
        const int c = cb + nf * 8;
        *(float2*)(pb + rb * 64 + c)       = make_float2(acc[nf][0], acc[nf][1]);
        *(float2*)(pb + (rb + 8) * 64 + c) = make_float2(acc[nf][2], acc[nf][3]);
    }
}

// ==== kvt_finalize: reduce partials -> kvt hi/lo; row64 = ksum; 65-71 = 0 ==
__global__ void kvt_finalize(const float* __restrict__ part,
                             const __half* __restrict__ kt,
                             __half* __restrict__ kvh, __half* __restrict__ kvl)
{
    const int head = blockIdx.x;
    const int tid = threadIdx.x;
    const long ob = (long)head * 72 * 64;

    for (int e = tid; e < 4096; e += 256) {
        float s = 0.f;
#pragma unroll
        for (int c = 0; c < 4; c++)
            s += part[((long)(c * 64 + head)) * 4096 + e];
        __half h = __float2half(s);
        kvh[ob + e] = h;
        kvl[ob + e] = __float2half(s - __half2float(h));
    }

    const int kd = tid >> 2, qtr = tid & 3;
    const __half* kr = kt + ((long)(head * 64 + kd)) * Ssz + qtr * 512;
    float s = 0.f;
#pragma unroll 8
    for (int i = 0; i < 64; i++) {
        uint4 u = *(const uint4*)(kr + i * 8);
        float2 a = __half22float2(*(__half2*)&u.x);
        float2 b = __half22float2(*(__half2*)&u.y);
        float2 c = __half22float2(*(__half2*)&u.z);
        float2 d = __half22float2(*(__half2*)&u.w);
        s += a.x + a.y + b.x + b.y + c.x + c.y + d.x + d.y;
    }
    s += __shfl_down_sync(0xffffffffu, s, 2);
    s += __shfl_down_sync(0xffffffffu, s, 1);
    if (qtr == 0) {
        __half h = __float2half(s);
        kvh[ob + 64 * 64 + kd] = h;
        kvl[ob + 64 * 64 + kd] = __float2half(s - __half2float(h));
    }

    for (int e = tid; e < 7 * 64; e += 256) {
        kvh[ob + 65 * 64 + e] = __float2half(0.f);
        kvl[ob + 65 * 64 + e] = __float2half(0.f);
    }
}

// ==== gemm_cmb: num/den = q @ kvt^T (hi+lo); gate epilogue -> comb fp16 ====
__global__ __launch_bounds__(256, 2)
void gemm_cmb(const __half* __restrict__ q,
              const __half* __restrict__ kvh, const __half* __restrict__ kvl,
              const float* __restrict__ gate,
              const float* __restrict__ df, const float* __restrict__ gw,
              __half* __restrict__ cf)
{
    __shared__ __align__(16) char sm[16384 + 2 * 10240];
    const uint32_t sA = s2u(sm);
    const uint32_t sBh = sA + 16384, sBl = sBh + 10240;
    const int tid = threadIdx.x;
    const int lane = tid & 31, wid = tid >> 5;
    const int mt = blockIdx.x, bn = blockIdx.y;
    const int b = bn >> 4, n = bn & 15;
    const long row0 = (long)b * Ssz + mt * 128;

    float w0 = gw[0], w1 = gw[1], w2 = gw[2];
    float d0 = df[0], d1 = df[1], d2 = df[2];
    float mx = fmaxf(w0, fmaxf(w1, w2));
    float e0 = expf(w0 - mx), e1 = expf(w1 - mx), e2 = expf(w2 - mx);
    float s0f = 1.f / (1.f + expf(-d0));
    float s1f = 1.f / (1.f + expf(-d1));
    float s2f = 1.f / (1.f + expf(-d2));
    float coef = (e0 * (1.f - s0f) + e1 * (1.f - s1f) + e2 * (1.f - s2f)) / (e0 + e1 + e2);

#pragma unroll
    for (int j = 0; j < 4; j++) {
        const int e = tid + j * 256;
        const int row = e >> 3, c16 = e & 7;
        *(uint4*)((char*)sm + swoff128(row, c16)) =
            *(const uint4*)(q + (row0 + row) * 1024 + n * 64 + c16 * 8);
    }
    for (int e = tid; e < 1152; e += 256) {
        const int t = e >= 576, ee = t ? e - 576 : e;
        const int row = ee >> 3, c16 = ee & 7;
        const __half* src = (t ? kvl : kvh) + (long)bn * 4608 + row * 64 + c16 * 8;
        *(uint4*)((char*)sm + 16384 + t * 10240 + swoff128(row, c16)) =
            *(const uint4*)src;
    }
    __syncthreads();

    float acc[9][4];
#pragma unroll
    for (int i = 0; i < 9; i++)
#pragma unroll
        for (int u = 0; u < 4; u++) acc[i][u] = 0.f;

#pragma unroll
    for (int ks = 0; ks < 4; ks++) {
        uint32_t aF[4];
        ldsm4(aF, sA + swoff128(wid * 16 + (lane & 15), ks * 2 + (lane >> 4)));
        const int brow = ((lane >> 4) << 3) + (lane & 7);
        const int bc16 = ks * 2 + ((lane >> 3) & 1);
#pragma unroll
        for (int nf = 0; nf < 4; nf++) {
            uint32_t bH[4], bL[4];
            ldsm4(bH, sBh + swoff128(nf * 16 + brow, bc16));
            ldsm4(bL, sBl + swoff128(nf * 16 + brow, bc16));
            mma16816h(acc[nf * 2 + 0], aF, bH + 0);
            mma16816h(acc[nf * 2 + 1], aF, bH + 2);
            mma16816h(acc[nf * 2 + 0], aF, bL + 0);
            mma16816h(acc[nf * 2 + 1], aF, bL + 2);
        }
        uint32_t bH[4], bL[4];
        ldsm4(bH, sBh + swoff128(64 + brow, bc16));
        ldsm4(bL, sBl + swoff128(64 + brow, bc16));
        mma16816h(acc[8], aF, bH + 0);
        mma16816h(acc[8], aF, bL + 0);
    }

#pragma unroll
    for (int u = 0; u < 4; u += 2) {
        const int rloc = wid * 16 + (lane >> 2) + (u ? 8 : 0);
        const long gr = row0 + rloc;
        float den = __shfl_sync(0xffffffffu, acc[8][u], lane & ~3) + EPSF;
        const float g = gate[gr];
        const float fac = g / den + (1.f - g) * coef;
#pragma unroll
        for (int ni = 0; ni < 8; ni++) {
            const int c = 2 * (lane & 3) + ni * 8;
            *(__half2*)(cf + gr * 1024 + n * 64 + c) =
                pack_h2(acc[ni][u] * fac, acc[ni][u + 1] * fac);
        }
    }
}

// ================= rope table ==============================================
__global__ void rope_table_kernel(float2* __restrict__ tab)
{
    const int idx = blockIdx.x * 256 + threadIdx.x;
    const int i = idx & 31, s = idx >> 5;
    double p = pow(10000.0, (double)(2 * i) / 64.0);
    float f = (float)s * (1.0f / (float)p);
    tab[idx] = make_float2(cosf(f), sinf(f));
}

// ============ cvt x -> single fp16 + gate (one block per row) ==============
__global__ void cvt_x_gate(const float4* __restrict__ x,
                           const float4* __restrict__ Wg,
                           const float* __restrict__ bg,
                           uint2* __restrict__ xf,
                           float* __restrict__ gout)
{
    const int row = blockIdx.x;
    const int tid = threadIdx.x;
    const long i = (long)row * 256 + tid;
    float4 v = x[i];
    float4 w = Wg[tid];
    float dot = v.x * w.x + v.y * w.y + v.z * w.z + v.w * w.w;

    float f[4] = {v.x, v.y, v.z, v.w};
    unsigned short hs[4];
#pragma unroll
    for (int j = 0; j < 4; j++) {
        __half h = __float2half(f[j]);
        hs[j] = *(unsigned short*)&h;
    }
    uint2 H;
    H.x = (uint32_t)hs[0] | ((uint32_t)hs[1] << 16);
    H.y = (uint32_t)hs[2] | ((uint32_t)hs[3] << 16);
    xf[i] = H;

#pragma unroll
    for (int o = 16; o; o >>= 1) dot += __shfl_down_sync(0xffffffffu, dot, o);
    __shared__ float ws[8];
    if ((tid & 31) == 0) ws[tid >> 5] = dot;
    __syncthreads();
    if (tid == 0) {
        float t = 0.f;
#pragma unroll
        for (int j = 0; j < 8; j++) t += ws[j];
        t += bg[0];
        gout[row] = 1.f / (1.f + expf(-t));
    }
}

// W[K][N] fp32 -> transposed single fp16 [N][K]; z selects which W
__global__ void cvt_w4(const float* __restrict__ W0, const float* __restrict__ W1,
                       const float* __restrict__ W2, const float* __restrict__ W3,
                       __half* __restrict__ h0, __half* __restrict__ h1,
                       __half* __restrict__ h2, __half* __restrict__ h3)
{
    const int z = blockIdx.z;
    const float* W = (z == 0) ? W0 : (z == 1) ? W1 : (z == 2) ? W2 : W3;
    __half* bh = (z == 0) ? h0 : (z == 1) ? h1 : (z == 2) ? h2 : h3;

    __shared__ float t[32][33];
    const int nx = blockIdx.x * 32, kx = blockIdx.y * 32;
    const int tx = threadIdx.x, ty = threadIdx.y;
#pragma unroll
    for (int r = 0; r < 32; r += 8)
        t[ty + r][tx] = W[(long)(kx + ty + r) * 1024 + nx + tx];
    __syncthreads();
#pragma unroll
    for (int r = 0; r < 32; r += 8) {
        float v = t[tx][ty + r];
        long o = (long)(nx + ty + r) * 1024 + kx + tx;
        bh[o] = __float2half(v);
    }
}

// ================= host: tensormap construction ============================
typedef CUresult (*PFN_encodeTiled)(
    CUtensorMap*, CUtensorMapDataType, cuuint32_t, void*,
    const cuuint64_t*, const cuuint64_t*, const cuuint32_t*, const cuuint32_t*,
    CUtensorMapInterleave, CUtensorMapSwizzle, CUtensorMapL2promotion,
    CUtensorMapFloatOOBfill);

static PFN_encodeTiled get_encoder() {
    static PFN_encodeTiled fn = nullptr;
    if (!fn) {
        void* p = nullptr;
        cudaDriverEntryPointQueryResult st;
        cudaGetDriverEntryPointByVersion("cuTensorMapEncodeTiled", &p, 12000,
                                         cudaEnableDefault, &st);
        fn = (PFN_encodeTiled)p;
    }
    return fn;
}

static void make_map(CUtensorMap* m, void* base, uint64_t rows) {
    cuuint64_t dims[2]    = {1024, rows};
    cuuint64_t strides[1] = {2048};
    cuuint32_t box[2]     = {32, 128};
    cuuint32_t es[2]      = {1, 1};
    get_encoder()(m, CU_TENSOR_MAP_DATA_TYPE_FLOAT16, 2, base, dims, strides,
                  box, es, CU_TENSOR_MAP_INTERLEAVE_NONE,
                  CU_TENSOR_MAP_SWIZZLE_64B, CU_TENSOR_MAP_L2_PROMOTION_L2_128B,
                  CU_TENSOR_MAP_FLOAT_OOB_FILL_NONE);
}

// ---------------------------------------------------------------------------
extern "C" void kernel_launch(void* const* d_in, const int* in_sizes, int n_in,
                              void* d_out, int out_size)
{
    const float* x    = (const float*)d_in[0];
    const float* mask = (const float*)d_in[1];
    const float* Wq   = (const float*)d_in[2];
    const float* bq   = (const float*)d_in[3];
    const float* Wk   = (const float*)d_in[4];
    const float* bk   = (const float*)d_in[5];
    const float* Wv   = (const float*)d_in[6];
    const float* bv   = (const float*)d_in[7];
    const float* Wo   = (const float*)d_in[8];
    const float* bo   = (const float*)d_in[9];
    const float* Wg   = (const float*)d_in[10];
    const float* bg   = (const float*)d_in[11];
    const float* df   = (const float*)d_in[12];
    const float* gw   = (const float*)d_in[13];
    float* out = (float*)d_out;

    float *kvp, *gate;
    float2* tab;
    __half *q16, *kt, *vt, *kvh, *kvl, *af, *bq16, *bk16, *bv16, *bo16;
    cudaGetSymbolAddress((void**)&q16,  g_q16);
    cudaGetSymbolAddress((void**)&kt,   g_kt);
    cudaGetSymbolAddress((void**)&vt,   g_vt);
    cudaGetSymbolAddress((void**)&kvp,  g_kv_part);
    cudaGetSymbolAddress((void**)&kvh,  g_kvt_h);
    cudaGetSymbolAddress((void**)&kvl,  g_kvt_l);
    cudaGetSymbolAddress((void**)&gate, g_gate);
    cudaGetSymbolAddress((void**)&tab,  g_rope);
    cudaGetSymbolAddress((void**)&af,   g_af);
    cudaGetSymbolAddress((void**)&bq16, g_bq16);
    cudaGetSymbolAddress((void**)&bk16, g_bk16);
    cudaGetSymbolAddress((void**)&bv16, g_bv16);
    cudaGetSymbolAddress((void**)&bo16, g_bo16);

    CUtensorMap mAf, mQ, mK, mV, mO;
    make_map(&mAf, af, Msz);
    make_map(&mQ,  bq16, Hsz);
    make_map(&mK,  bk16, Hsz);
    make_map(&mV,  bv16, Hsz);
    make_map(&mO,  bo16, Hsz);

    cudaFuncSetAttribute(gemm_qkv,
                         cudaFuncAttributeMaxDynamicSharedMemorySize, SMEM_GEMM);
    cudaFuncSetAttribute(gemm_out,
                         cudaFuncAttributeMaxDynamicSharedMemorySize, SMEM_GEMM);

    // 1. rope table
    rope_table_kernel<<<Ssz * 32 / 256, 256>>>(tab);
    // 2. activation -> single fp16 + gate
    cvt_x_gate<<<Msz, 256>>>((const float4*)x, (const float4*)Wg, bg,
                             (uint2*)af, gate);
    // 3. weight conversions
    cvt_w4<<<dim3(32, 32, 4), dim3(32, 8)>>>(Wq, Wk, Wv, Wo,
                                             bq16, bk16, bv16, bo16);
    // 4. fused QKV projection; q -> [s][1024], k/v -> transposed fp16
    gemm_qkv<<<dim3(8, 64, 3), 256, SMEM_GEMM>>>(
        mAf, mQ, mK, mV, bq, bk, bv, q16, kt, vt, mask, tab);
    // 5. kv outer-product GEMM (split-K partials)
    gemm_kv<<<dim3(4, 64), 256>>>(vt, kt, kvp);
    // 6. reduce partials + ksum -> kvt hi/lo
    kvt_finalize<<<64, 256>>>(kvp, kt, kvh, kvl);
    // 7. combine GEMM (num + den in one MMA) + gate epilogue -> af fp16
    gemm_cmb<<<dim3(16, 64), 256>>>(q16, kvh, kvl, gate, df, gw, af);
    // 8. output projection
    gemm_out<<<dim3(8, 64), 256, SMEM_GEMM>>>(mAf, mO, bo, out);
}

// round 14
// speedup vs baseline: 6.4702x; 1.0089x over previous
#include <cuda_runtime.h>
#include <cuda.h>
#include <cuda_bf16.h>
#include <cuda_fp16.h>
#include <math.h>
#include <stdint.h>

// Problem constants
#define Bsz 4
#define Ssz 2048
#define Hsz 1024
#define Nh  16
#define Dh  64
#define Msz (Bsz*Ssz)      // 8192
#define EPSF 1e-6f

// ---------------- scratch (static device globals; no allocs allowed) -------
__device__ __half g_q16[Msz*Hsz];         // q (phi'd, scaled) fp16 [s][1024]
__device__ __half g_kt[64*64*Ssz];        // k transposed [bn][kd][s] fp16
__device__ __half g_vt[64*64*Ssz];        // v transposed [bn][vd][s] fp16
__device__ float g_kv_part[4*64*64*64];   // [kc][bn][vd][kd]
__device__ __half g_kvt_h[64*72*64];      // [bn][72][64]: rows0-63 kv, 64 ksum
__device__ __half g_kvt_l[64*72*64];
__device__ float g_gate[Msz];
__device__ float2 g_rope[Ssz*32];         // (cos, sin) per (s, i)
__device__ __half g_af[Msz*Hsz];          // x fp16 (QKV phase), comb fp16 after
__device__ __half g_bq16[Hsz*Hsz];        // Wq single fp16 [N][K]
__device__ __half g_bk16[Hsz*Hsz];
__device__ __half g_bv16[Hsz*Hsz];
__device__ __half g_bo16[Hsz*Hsz];

// ================= low-level helpers =======================================
static __device__ __forceinline__ uint32_t s2u(const void* p) {
    uint32_t a;
    asm("{ .reg .u64 t; cvta.to.shared.u64 t, %1; cvt.u32.u64 %0, t; }"
        : "=r"(a) : "l"(p));
    return a;
}

static __device__ __forceinline__ void ldsm4(uint32_t* r, uint32_t addr) {
    asm volatile("ldmatrix.sync.aligned.m8n8.x4.shared.b16 {%0,%1,%2,%3}, [%4];"
                 : "=r"(r[0]), "=r"(r[1]), "=r"(r[2]), "=r"(r[3]) : "r"(addr));
}

static __device__ __forceinline__ void mma16816h(float* d, const uint32_t* a,
                                                 const uint32_t* b) {
    asm volatile(
        "mma.sync.aligned.m16n8k16.row.col.f32.f16.f16.f32 "
        "{%0,%1,%2,%3}, {%4,%5,%6,%7}, {%8,%9}, {%0,%1,%2,%3};"
        : "+f"(d[0]), "+f"(d[1]), "+f"(d[2]), "+f"(d[3])
        : "r"(a[0]), "r"(a[1]), "r"(a[2]), "r"(a[3]), "r"(b[0]), "r"(b[1]));
}

// 64B-row tile swizzle (TMA SW64 tiles: rows of 32 halves)
static __device__ __forceinline__ uint32_t swoff(int row, int c16) {
    return (uint32_t)(row * 64 + ((c16 ^ ((row >> 1) & 3)) << 4));
}
// 128B-row tile swizzle (plain-load tiles: rows of 64 halves, 8 c16 chunks)
static __device__ __forceinline__ uint32_t swoff128(int row, int c16) {
    return (uint32_t)(row * 128 + ((c16 ^ (row & 7)) << 4));
}

#define MBAR_INIT(m, c) \
    asm volatile("mbarrier.init.shared.b64 [%0], %1;" \
                 :: "r"((uint32_t)(m)), "r"((uint32_t)(c)) : "memory")
#define MBAR_EXPECT(m, b) \
    asm volatile("mbarrier.arrive.expect_tx.shared.b64 _, [%0], %1;" \
                 :: "r"((uint32_t)(m)), "r"((uint32_t)(b)) : "memory")

static __device__ __forceinline__ void mbar_wait(uint32_t mbar, uint32_t parity) {
    asm volatile(
        "{\n\t.reg .pred P;\n\t"
        "WL_%=:\n\t"
        "mbarrier.try_wait.parity.acquire.cta.shared::cta.b64 P, [%0], %1, 0x989680;\n\t"
        "@P bra.uni WD_%=;\n\t"
        "bra.uni WL_%=;\n\t"
        "WD_%=:\n\t}"
        :: "r"(mbar), "r"(parity) : "memory");
}

#define TMA2D(sa, mp, cx, cy, mb) \
    asm volatile("cp.async.bulk.tensor.2d.shared::cta.global.tile.mbarrier::complete_tx::bytes " \
                 "[%0], [%1, {%2, %3}], [%4];" \
                 :: "r"((uint32_t)(sa)), "l"(mp), "r"((int)(cx)), "r"((int)(cy)), \
                    "r"((uint32_t)(mb)) : "memory")

__device__ __forceinline__ float phi_fn(float x) {
    float t = (x > 0.f) ? x : expm1f(x);
    return (t + 1.0f) + EPSF;
}

static __device__ __forceinline__ __half2 pack_h2(float a, float b) {
    return __halves2half2(__float2half(a), __float2half(b));
}

// ===== GEMM mainloop config: BK=64 stages (two 8KB halves per operand) =====
#define PSTAGES 3
#define PSTAGE_B 32768
#define NPAIR 16
#define SMEM_GEMM (PSTAGES * PSTAGE_B + 64)

// Interleaved ldsm/MMA slice body, warp-staggered k-slice order.
// aF/br are double-buffered; per-warp accumulation order is fixed -> deterministic.
#define PAIR_BODY(bA, bB)                                                     \
    {                                                                         \
        uint32_t aF[2][2][4], br[2][2][4];                                    \
        {                                                                     \
            const int ks0 = wm & 3;                                           \
            const uint32_t hA = (bA) + (ks0 >> 1) * 8192;                     \
            const int kk = (ks0 & 1) * 2 + a_c16h;                            \
            ldsm4(aF[0][0], hA + swoff(a_row,      kk));                      \
            ldsm4(aF[0][1], hA + swoff(a_row + 16, kk));                      \
        }                                                                     \
        _Pragma("unroll")                                                     \
        for (int ksi = 0; ksi < 4; ksi++) {                                   \
            const int cur = ksi & 1, nxt = cur ^ 1;                           \
            const int ks = (ksi + wm) & 3;                                    \
            const uint32_t hB = (bB) + (ks >> 1) * 8192;                      \
            const int bc = (ks & 1) * 2 + b_c16h;                             \
            ldsm4(br[0][0], hB + swoff(b_row,      bc));                      \
            ldsm4(br[0][1], hB + swoff(b_row + 16, bc));                      \
            if (ksi < 3) {                                                    \
                const int ks2 = (ksi + 1 + wm) & 3;                           \
                const uint32_t hA2 = (bA) + (ks2 >> 1) * 8192;                \
                const int kk2 = (ks2 & 1) * 2 + a_c16h;                       \
                ldsm4(aF[nxt][0], hA2 + swoff(a_row,      kk2));              \
                ldsm4(aF[nxt][1], hA2 + swoff(a_row + 16, kk2));              \
            }                                                                 \
            mma16816h(acc[0][0], aF[cur][0], br[0][0] + 0);                   \
            mma16816h(acc[0][1], aF[cur][0], br[0][0] + 2);                   \
            mma16816h(acc[1][0], aF[cur][1], br[0][0] + 0);                   \
            mma16816h(acc[1][1], aF[cur][1], br[0][0] + 2);                   \
            ldsm4(br[1][0], hB + swoff(b_row + 32, bc));                      \
            mma16816h(acc[0][2], aF[cur][0], br[0][1] + 0);                   \
            mma16816h(acc[0][3], aF[cur][0], br[0][1] + 2);                   \
            mma16816h(acc[1][2], aF[cur][1], br[0][1] + 0);                   \
            mma16816h(acc[1][3], aF[cur][1], br[0][1] + 2);                   \
            ldsm4(br[1][1], hB + swoff(b_row + 48, bc));                      \
            mma16816h(acc[0][4], aF[cur][0], br[1][0] + 0);                   \
            mma16816h(acc[0][5], aF[cur][0], br[1][0] + 2);                   \
            mma16816h(acc[1][4], aF[cur][1], br[1][0] + 0);                   \
            mma16816h(acc[1][5], aF[cur][1], br[1][0] + 2);                   \
            mma16816h(acc[0][6], aF[cur][0], br[1][1] + 0);                   \
            mma16816h(acc[0][7], aF[cur][0], br[1][1] + 2);                   \
            mma16816h(acc[1][6], aF[cur][1], br[1][1] + 0);                   \
            mma16816h(acc[1][7], aF[cur][1], br[1][1] + 2);                   \
        }                                                                     \
    }

// ========== QKV GEMM: single-product fp16 =================================
// z=0: q -> rope/phi*0.125, fp16 [s][1024]
// z=1: k -> rope/phi*mask, fp16 TRANSPOSED [bn][kd][s]
// z=2: v -> mask, fp16 TRANSPOSED [bn][vd][s]
__global__ __launch_bounds__(256, 2)
void gemm_qkv(const __grid_constant__ CUtensorMap mAf,
              const __grid_constant__ CUtensorMap mB0,
              const __grid_constant__ CUtensorMap mB1,
              const __grid_constant__ CUtensorMap mB2,
              const float* __restrict__ b0, const float* __restrict__ b1,
              const float* __restrict__ b2,
              __half* __restrict__ Cq, __half* __restrict__ KT,
              __half* __restrict__ VT,
              const float* __restrict__ maskp,
              const float2* __restrict__ tab)
{
    extern __shared__ __align__(1024) char smem[];
    const uint32_t sbase = s2u(smem);
    const uint32_t mbb  = sbase + PSTAGES * PSTAGE_B;
    const int tid = threadIdx.x;
    const int lane = tid & 31, wid = tid >> 5;
    const int wm = wid & 3, wn = wid >> 2;
    const int n0 = blockIdx.x * 128, m0 = blockIdx.y * 128;
    const int z = blockIdx.z;

    const CUtensorMap* pB = (z == 0) ? &mB0 : (z == 1) ? &mB1 : &mB2;
    const float* bias = (z == 0) ? b0 : (z == 1) ? b1 : b2;

    const int a_row  = wm * 32 + (lane & 15);
    const int a_c16h = lane >> 4;
    const int b_row  = wn * 64 + ((lane >> 4) << 3) + (lane & 7);
    const int b_c16h = (lane >> 3) & 1;

    float acc[2][8][4];
#pragma unroll
    for (int mi = 0; mi < 2; mi++)
#pragma unroll
        for (int ni = 0; ni < 8; ni++)
#pragma unroll
            for (int u = 0; u < 4; u++) acc[mi][ni][u] = 0.f;

    if (tid == 0) {
#pragma unroll
        for (int s = 0; s < PSTAGES; s++) MBAR_INIT(mbb + s * 8, 1);
    }
    __syncthreads();

    if (tid == 0) {
#pragma unroll
        for (int s = 0; s < PSTAGES; s++) {
            const uint32_t db = sbase + s * PSTAGE_B;
            MBAR_EXPECT(mbb + s * 8, PSTAGE_B);
            TMA2D(db,         &mAf, s * 64,      m0, mbb + s * 8);
            TMA2D(db + 8192,  &mAf, s * 64 + 32, m0, mbb + s * 8);
            TMA2D(db + 16384, pB,   s * 64,      n0, mbb + s * 8);
            TMA2D(db + 24576, pB,   s * 64 + 32, n0, mbb + s * 8);
        }
    }

    int sp = 0, ph = 0;
    for (int p = 0; p < NPAIR; p++) {
        mbar_wait(mbb + sp * 8, ph);

        const uint32_t bA = sbase + sp * PSTAGE_B;
        const uint32_t bB = bA + 16384;
        PAIR_BODY(bA, bB)

        __syncthreads();   // all threads done reading stage sp
        const int np_ = p + PSTAGES;
        if (np_ < NPAIR && tid == 0) {
            const uint32_t db = sbase + sp * PSTAGE_B;
            MBAR_EXPECT(mbb + sp * 8, PSTAGE_B);
            TMA2D(db,         &mAf, np_ * 64,      m0, mbb + sp * 8);
            TMA2D(db + 8192,  &mAf, np_ * 64 + 32, m0, mbb + sp * 8);
            TMA2D(db + 16384, pB,   np_ * 64,      n0, mbb + sp * 8);
            TMA2D(db + 24576, pB,   np_ * 64 + 32, n0, mbb + sp * 8);
        }
        if (++sp == PSTAGES) { sp = 0; ph ^= 1; }
    }

    // ---------------- epilogue ----------------
    const int r0 = m0 + wm * 32 + (lane >> 2);
    const int nb0 = n0 + wn * 64 + 2 * (lane & 3);

    if (z == 0) {
#pragma unroll
        for (int mi = 0; mi < 2; mi++) {
#pragma unroll
            for (int uu = 0; uu < 4; uu += 2) {
                const int r = r0 + mi * 16 + (uu ? 8 : 0);
                const int srow = r & (Ssz - 1);
#pragma unroll
                for (int ni = 0; ni < 4; ni++) {
                    float o1[2], o2[2];
#pragma unroll
                    for (int e = 0; e < 2; e++) {
                        const int i = 2 * (lane & 3) + ni * 8 + e;
                        const int c = nb0 + ni * 8 + e;
                        float x1 = acc[mi][ni][uu + e]     + bias[c];
                        float x2 = acc[mi][ni + 4][uu + e] + bias[c + 32];
                        float2 cs = tab[srow * 32 + i];
                        float r1 = x1 * cs.x - x2 * cs.y;
                        float r2 = x2 * cs.x + x1 * cs.y;
                        o1[e] = phi_fn(r1) * 0.125f;
                        o2[e] = phi_fn(r2) * 0.125f;
                    }
                    const int c = nb0 + ni * 8;
                    *(__half2*)(Cq + (long)r * 1024 + c)      = pack_h2(o1[0], o1[1]);
                    *(__half2*)(Cq + (long)r * 1024 + c + 32) = pack_h2(o2[0], o2[1]);
                }
            }
        }
        return;
    }

    // k/v: transposed store via smem staging. ts[c_local][rloc], pitch 136.
    __syncthreads();
    __half* ts = (__half*)smem;
    const int rb = wm * 32 + (lane >> 2);
    const int cb = wn * 64 + 2 * (lane & 3);

#pragma unroll
    for (int mi = 0; mi < 2; mi++) {
#pragma unroll
        for (int uu = 0; uu < 4; uu += 2) {
            const int rloc = rb + mi * 16 + (uu ? 8 : 0);
            const int r = m0 + rloc;
            const int srow = r & (Ssz - 1);
            const float msk = maskp[r];
            if (z == 2) {
#pragma unroll
                for (int ni = 0; ni < 8; ni++) {
#pragma unroll
                    for (int e = 0; e < 2; e++) {
                        const int cl = cb + ni * 8 + e;
                        float val = (acc[mi][ni][uu + e] + bias[n0 + cl]) * msk;
                        ts[cl * 136 + rloc] = __float2half(val);
                    }
                }
            } else {
#pragma unroll
                for (int ni = 0; ni < 4; ni++) {
#pragma unroll
                    for (int e = 0; e < 2; e++) {
                        const int i = 2 * (lane & 3) + ni * 8 + e;
                        const int cl = cb + ni * 8 + e;
                        float x1 = acc[mi][ni][uu + e]     + bias[n0 + cl];
                        float x2 = acc[mi][ni + 4][uu + e] + bias[n0 + cl + 32];
                        float2 cs = tab[srow * 32 + i];
                        float r1 = x1 * cs.x - x2 * cs.y;
                        float r2 = x2 * cs.x + x1 * cs.y;
                        ts[cl * 136 + rloc]        = __float2half(phi_fn(r1) * msk);
                        ts[(cl + 32) * 136 + rloc] = __float2half(phi_fn(r2) * msk);
                    }
                }
            }
        }
    }
    __syncthreads();

    __half* T = (z == 1) ? KT : VT;
    const int b = m0 >> 11;
    const int sb = m0 & (Ssz - 1);
#pragma unroll
    for (int i = 0; i < 8; i++) {
        const int e = tid + i * 256;
        const int c = e >> 4, ch = e & 15, rl = ch * 8;
        uint4 val = *(uint4*)&ts[c * 136 + rl];
        const int bn = b * 16 + (n0 >> 6) + (c >> 6);
        const int d = c & 63;
        *(uint4*)(T + ((long)(bn * 64 + d)) * Ssz + sb + rl) = val;
    }
}

// ===== OUT GEMM: single-product fp16, BK=64 stages, fp32 store =============
__global__ __launch_bounds__(256, 2)
void gemm_out(const __grid_constant__ CUtensorMap mAf,
              const __grid_constant__ CUtensorMap mB,
              const float* __restrict__ bias, float* __restrict__ C)
{
    extern __shared__ __align__(1024) char smem[];
    const uint32_t sbase = s2u(smem);
    const uint32_t mbb  = sbase + PSTAGES * PSTAGE_B;
    const int tid = threadIdx.x;
    const int lane = tid & 31, wid = tid >> 5;
    const int wm = wid & 3, wn = wid >> 2;
    const int n0 = blockIdx.x * 128, m0 = blockIdx.y * 128;

    const int a_row  = wm * 32 + (lane & 15);
    const int a_c16h = lane >> 4;
    const int b_row  = wn * 64 + ((lane >> 4) << 3) + (lane & 7);
    const int b_c16h = (lane >> 3) & 1;

    float acc[2][8][4];
#pragma unroll
    for (int mi = 0; mi < 2; mi++)
#pragma unroll
        for (int ni = 0; ni < 8; ni++)
#pragma unroll
            for (int u = 0; u < 4; u++) acc[mi][ni][u] = 0.f;

    if (tid == 0) {
#pragma unroll
        for (int s = 0; s < PSTAGES; s++) MBAR_INIT(mbb + s * 8, 1);
    }
    __syncthreads();

    if (tid == 0) {
#pragma unroll
        for (int s = 0; s < PSTAGES; s++) {
            const uint32_t db = sbase + s * PSTAGE_B;
            MBAR_EXPECT(mbb + s * 8, PSTAGE_B);
            TMA2D(db,         &mAf, s * 64,      m0, mbb + s * 8);
            TMA2D(db + 8192,  &mAf, s * 64 + 32, m0, mbb + s * 8);
            TMA2D(db + 16384, &mB,  s * 64,      n0, mbb + s * 8);
            TMA2D(db + 24576, &mB,  s * 64 + 32, n0, mbb + s * 8);
        }
    }

    int sp = 0, ph = 0;
    for (int p = 0; p < NPAIR; p++) {
        mbar_wait(mbb + sp * 8, ph);

        const uint32_t bA = sbase + sp * PSTAGE_B;
        const uint32_t bB = bA + 16384;
        PAIR_BODY(bA, bB)

        __syncthreads();
        const int np_ = p + PSTAGES;
        if (np_ < NPAIR && tid == 0) {
            const uint32_t db = sbase + sp * PSTAGE_B;
            MBAR_EXPECT(mbb + sp * 8, PSTAGE_B);
            TMA2D(db,         &mAf, np_ * 64,      m0, mbb + sp * 8);
            TMA2D(db + 8192,  &mAf, np_ * 64 + 32, m0, mbb + sp * 8);
            TMA2D(db + 16384, &mB,  np_ * 64,      n0, mbb + sp * 8);
            TMA2D(db + 24576, &mB,  np_ * 64 + 32, n0, mbb + sp * 8);
        }
        if (++sp == PSTAGES) { sp = 0; ph ^= 1; }
    }

    const int r0 = m0 + wm * 32 + (lane >> 2);
    const int nb0 = n0 + wn * 64 + 2 * (lane & 3);
#pragma unroll
    for (int mi = 0; mi < 2; mi++) {
#pragma unroll
        for (int ni = 0; ni < 8; ni++) {
            const int r = r0 + mi * 16;
            const int c = nb0 + ni * 8;
            float2 bb = *(const float2*)(bias + c);
            *(float2*)(C + (long)r * 1024 + c) =
                make_float2(acc[mi][ni][0] + bb.x, acc[mi][ni][1] + bb.y);
            *(float2*)(C + (long)(r + 8) * 1024 + c) =
                make_float2(acc[mi][ni][2] + bb.x, acc[mi][ni][3] + bb.y);
        }
    }
}

// ============ gemm_kv: D[vd][kd] = sum_s v_t[vd][s] * k_t[kd][s] ===========
__global__ __launch_bounds__(256, 4)
void gemm_kv(const __half* __restrict__ vt, const __half* __restrict__ kt,
             float* __restrict__ part)
{
    __shared__ __align__(16) char sm[16384];
    const uint32_t sA = s2u(sm), sB = sA + 8192;
    const int tid = threadIdx.x;
    const int lane = tid & 31, wid = tid >> 5;
    const int wm = wid & 3, wn = wid >> 2;
    const int kc = blockIdx.x, head = blockIdx.y;

    float acc[4][4];
#pragma unroll
    for (int i = 0; i < 4; i++)
#pragma unroll
        for (int u = 0; u < 4; u++) acc[i][u] = 0.f;

    for (int sc = 0; sc < 8; sc++) {
        const int sg = kc * 512 + sc * 64;
#pragma unroll
        for (int j = 0; j < 4; j++) {
            const int e = tid + j * 256;
            const int t = e >> 9, row = (e >> 3) & 63, c16 = e & 7;
            const __half* src = (t ? kt : vt) +
                ((long)(head * 64 + row)) * Ssz + sg + c16 * 8;
            *(uint4*)((char*)sm + t * 8192 + swoff128(row, c16)) =
                *(const uint4*)src;
        }
        __syncthreads();

#pragma unroll
        for (int ks = 0; ks < 4; ks++) {
            uint32_t aF[4];
            ldsm4(aF, sA + swoff128(wm * 16 + (lane & 15), ks * 2 + (lane >> 4)));
#pragma unroll
            for (int nb = 0; nb < 2; nb++) {
                uint32_t bF[4];
                ldsm4(bF, sB + swoff128(wn * 32 + nb * 16 +
                                        ((lane >> 4) << 3) + (lane & 7),
                                        ks * 2 + ((lane >> 3) & 1)));
                mma16816h(acc[nb * 2 + 0], aF, bF + 0);
                mma16816h(acc[nb * 2 + 1], aF, bF + 2);
            }
        }
        __syncthreads();
    }

    float* pb = part + ((long)(kc * 64 + head)) * 4096;
    const int rb = wm * 16 + (lane >> 2);
    const int cb = wn * 32 + 2 * (lane & 3);
#pragma unroll
    for (int nf = 0; nf < 4; nf++) {
        const int c = cb + nf * 8;
        *(float2*)(pb + rb * 64 + c)       = make_float2(acc[nf][0], acc[nf][1]);
        *(float2*)(pb + (rb + 8) * 64 + c) = make_float2(acc[nf][2], acc[nf][3]);
    }
}

// ==== kvt_finalize: reduce partials -> kvt hi/lo; row64 = ksum; 65-71 = 0 ==
__global__ void kvt_finalize(const float* __restrict__ part,
                             const __half* __restrict__ kt,
                             __half* __restrict__ kvh, __half* __restrict__ kvl)
{
    const int head = blockIdx.x;
    const int tid = threadIdx.x;
    const long ob = (long)head * 72 * 64;

    for (int e = tid; e < 4096; e += 256) {
        float s = 0.f;
#pragma unroll
        for (int c = 0; c < 4; c++)
            s += part[((long)(c * 64 + head)) * 4096 + e];
        __half h = __float2half(s);
        kvh[ob + e] = h;
        kvl[ob + e] = __float2half(s - __half2float(h));
    }

    const int kd = tid >> 2, qtr = tid & 3;
    const __half* kr = kt + ((long)(head * 64 + kd)) * Ssz + qtr * 512;
    float s = 0.f;
#pragma unroll 8
    for (int i = 0; i < 64; i++) {
        uint4 u = *(const uint4*)(kr + i * 8);
        float2 a = __half22float2(*(__half2*)&u.x);
        float2 b = __half22float2(*(__half2*)&u.y);
        float2 c = __half22float2(*(__half2*)&u.z);
        float2 d = __half22float2(*(__half2*)&u.w);
        s += a.x + a.y + b.x + b.y + c.x + c.y + d.x + d.y;
    }
    s += __shfl_down_sync(0xffffffffu, s, 2);
    s += __shfl_down_sync(0xffffffffu, s, 1);
    if (qtr == 0) {
        __half h = __float2half(s);
        kvh[ob + 64 * 64 + kd] = h;
        kvl[ob + 64 * 64 + kd] = __float2half(s - __half2float(h));
    }

    for (int e = tid; e < 7 * 64; e += 256) {
        kvh[ob + 65 * 64 + e] = __float2half(0.f);
        kvl[ob + 65 * 64 + e] = __float2half(0.f);
    }
}

// ==== gemm_cmb: num/den = q @ kvt^T (hi+lo); gate epilogue -> comb fp16 ====
__global__ __launch_bounds__(256, 2)
void gemm_cmb(const __half* __restrict__ q,
              const __half* __restrict__ kvh, const __half* __restrict__ kvl,
              const float* __restrict__ gate,
              const float* __restrict__ df, const float* __restrict__ gw,
              __half* __restrict__ cf)
{
    __shared__ __align__(16) char sm[16384 + 2 * 10240];
    const uint32_t sA = s2u(sm);
    const uint32_t sBh = sA + 16384, sBl = sBh + 10240;
    const int tid = threadIdx.x;
    const int lane = tid & 31, wid = tid >> 5;
    const int mt = blockIdx.x, bn = blockIdx.y;
    const int b = bn >> 4, n = bn & 15;
    const long row0 = (long)b * Ssz + mt * 128;

    float w0 = gw[0], w1 = gw[1], w2 = gw[2];
    float d0 = df[0], d1 = df[1], d2 = df[2];
    float mx = fmaxf(w0, fmaxf(w1, w2));
    float e0 = expf(w0 - mx), e1 = expf(w1 - mx), e2 = expf(w2 - mx);
    float s0f = 1.f / (1.f + expf(-d0));
    float s1f = 1.f / (1.f + expf(-d1));
    float s2f = 1.f / (1.f + expf(-d2));
    float coef = (e0 * (1.f - s0f) + e1 * (1.f - s1f) + e2 * (1.f - s2f)) / (e0 + e1 + e2);

#pragma unroll
    for (int j = 0; j < 4; j++) {
        const int e = tid + j * 256;
        const int row = e >> 3, c16 = e & 7;
        *(uint4*)((char*)sm + swoff128(row, c16)) =
            *(const uint4*)(q + (row0 + row) * 1024 + n * 64 + c16 * 8);
    }
    for (int e = tid; e < 1152; e += 256) {
        const int t = e >= 576, ee = t ? e - 576 : e;
        const int row = ee >> 3, c16 = ee & 7;
        const __half* src = (t ? kvl : kvh) + (long)bn * 4608 + row * 64 + c16 * 8;
        *(uint4*)((char*)sm + 16384 + t * 10240 + swoff128(row, c16)) =
            *(const uint4*)src;
    }
    __syncthreads();

    float acc[9][4];
#pragma unroll
    for (int i = 0; i < 9; i++)
#pragma unroll
        for (int u = 0; u < 4; u++) acc[i][u] = 0.f;

#pragma unroll
    for (int ks = 0; ks < 4; ks++) {
        uint32_t aF[4];
        ldsm4(aF, sA + swoff128(wid * 16 + (lane & 15), ks * 2 + (lane >> 4)));
        const int brow = ((lane >> 4) << 3) + (lane & 7);
        const int bc16 = ks * 2 + ((lane >> 3) & 1);
#pragma unroll
        for (int nf = 0; nf < 4; nf++) {
            uint32_t bH[4], bL[4];
            ldsm4(bH, sBh + swoff128(nf * 16 + brow, bc16));
            ldsm4(bL, sBl + swoff128(nf * 16 + brow, bc16));
            mma16816h(acc[nf * 2 + 0], aF, bH + 0);
            mma16816h(acc[nf * 2 + 1], aF, bH + 2);
            mma16816h(acc[nf * 2 + 0], aF, bL + 0);
            mma16816h(acc[nf * 2 + 1], aF, bL + 2);
        }
        uint32_t bH[4], bL[4];
        ldsm4(bH, sBh + swoff128(64 + brow, bc16));
        ldsm4(bL, sBl + swoff128(64 + brow, bc16));
        mma16816h(acc[8], aF, bH + 0);
        mma16816h(acc[8], aF, bL + 0);
    }

#pragma unroll
    for (int u = 0; u < 4; u += 2) {
        const int rloc = wid * 16 + (lane >> 2) + (u ? 8 : 0);
        const long gr = row0 + rloc;
        float den = __shfl_sync(0xffffffffu, acc[8][u], lane & ~3) + EPSF;
        const float g = gate[gr];
        const float fac = g / den + (1.f - g) * coef;
#pragma unroll
        for (int ni = 0; ni < 8; ni++) {
            const int c = 2 * (lane & 3) + ni * 8;
            *(__half2*)(cf + gr * 1024 + n * 64 + c) =
                pack_h2(acc[ni][u] * fac, acc[ni][u + 1] * fac);
        }
    }
}

// ================= rope table ==============================================
__global__ void rope_table_kernel(float2* __restrict__ tab)
{
    const int idx = blockIdx.x * 256 + threadIdx.x;
    const int i = idx & 31, s = idx >> 5;
    double p = pow(10000.0, (double)(2 * i) / 64.0);
    float f = (float)s * (1.0f / (float)p);
    tab[idx] = make_float2(cosf(f), sinf(f));
}

// ============ cvt x -> single fp16 + gate (one block per row) ==============
__global__ void cvt_x_gate(const float4* __restrict__ x,
                           const float4* __restrict__ Wg,
                           const float* __restrict__ bg,
                           uint2* __restrict__ xf,
                           float* __restrict__ gout)
{
    const int row = blockIdx.x;
    const int tid = threadIdx.x;
    const long i = (long)row * 256 + tid;
    float4 v = x[i];
    float4 w = Wg[tid];
    float dot = v.x * w.x + v.y * w.y + v.z * w.z + v.w * w.w;

    float f[4] = {v.x, v.y, v.z, v.w};
    unsigned short hs[4];
#pragma unroll
    for (int j = 0; j < 4; j++) {
        __half h = __float2half(f[j]);
        hs[j] = *(unsigned short*)&h;
    }
    uint2 H;
    H.x = (uint32_t)hs[0] | ((uint32_t)hs[1] << 16);
    H.y = (uint32_t)hs[2] | ((uint32_t)hs[3] << 16);
    xf[i] = H;

#pragma unroll
    for (int o = 16; o; o >>= 1) dot += __shfl_down_sync(0xffffffffu, dot, o);
    __shared__ float ws[8];
    if ((tid & 31) == 0) ws[tid >> 5] = dot;
    __syncthreads();
    if (tid == 0) {
        float t = 0.f;
#pragma unroll
        for (int j = 0; j < 8; j++) t += ws[j];
        t += bg[0];
        gout[row] = 1.f / (1.f + expf(-t));
    }
}

// W[K][N] fp32 -> transposed single fp16 [N][K]; z selects which W
__global__ void cvt_w4(const float* __restrict__ W0, const float* __restrict__ W1,
                       const float* __restrict__ W2, const float* __restrict__ W3,
                       __half* __restrict__ h0, __half* __restrict__ h1,
                       __half* __restrict__ h2, __half* __restrict__ h3)
{
    const int z = blockIdx.z;
    const float* W = (z == 0) ? W0 : (z == 1) ? W1 : (z == 2) ? W2 : W3;
    __half* bh = (z == 0) ? h0 : (z == 1) ? h1 : (z == 2) ? h2 : h3;

    __shared__ float t[32][33];
    const int nx = blockIdx.x * 32, kx = blockIdx.y * 32;
    const int tx = threadIdx.x, ty = threadIdx.y;
#pragma unroll
    for (int r = 0; r < 32; r += 8)
        t[ty + r][tx] = W[(long)(kx + ty + r) * 1024 + nx + tx];
    __syncthreads();
#pragma unroll
    for (int r = 0; r < 32; r += 8) {
        float v = t[tx][ty + r];
        long o = (long)(nx + ty + r) * 1024 + kx + tx;
        bh[o] = __float2half(v);
    }
}

// ================= host: tensormap construction ============================
typedef CUresult (*PFN_encodeTiled)(
    CUtensorMap*, CUtensorMapDataType, cuuint32_t, void*,
    const cuuint64_t*, const cuuint64_t*, const cuuint32_t*, const cuuint32_t*,
    CUtensorMapInterleave, CUtensorMapSwizzle, CUtensorMapL2promotion,
    CUtensorMapFloatOOBfill);

static PFN_encodeTiled get_encoder() {
    static PFN_encodeTiled fn = nullptr;
    if (!fn) {
        void* p = nullptr;
        cudaDriverEntryPointQueryResult st;
        cudaGetDriverEntryPointByVersion("cuTensorMapEncodeTiled", &p, 12000,
                                         cudaEnableDefault, &st);
        fn = (PFN_encodeTiled)p;
    }
    return fn;
}

static void make_map(CUtensorMap* m, void* base, uint64_t rows) {
    cuuint64_t dims[2]    = {1024, rows};
    cuuint64_t strides[1] = {2048};
    cuuint32_t box[2]     = {32, 128};
    cuuint32_t es[2]      = {1, 1};
    get_encoder()(m, CU_TENSOR_MAP_DATA_TYPE_FLOAT16, 2, base, dims, strides,
                  box, es, CU_TENSOR_MAP_INTERLEAVE_NONE,
                  CU_TENSOR_MAP_SWIZZLE_64B, CU_TENSOR_MAP_L2_PROMOTION_L2_128B,
                  CU_TENSOR_MAP_FLOAT_OOB_FILL_NONE);
}

// ---------------------------------------------------------------------------
extern "C" void kernel_launch(void* const* d_in, const int* in_sizes, int n_in,
                              void* d_out, int out_size)
{
    const float* x    = (const float*)d_in[0];
    const float* mask = (const float*)d_in[1];
    const float* Wq   = (const float*)d_in[2];
    const float* bq   = (const float*)d_in[3];
    const float* Wk   = (const float*)d_in[4];
    const float* bk   = (const float*)d_in[5];
    const float* Wv   = (const float*)d_in[6];
    const float* bv   = (const float*)d_in[7];
    const float* Wo   = (const float*)d_in[8];
    const float* bo   = (const float*)d_in[9];
    const float* Wg   = (const float*)d_in[10];
    const float* bg   = (const float*)d_in[11];
    const float* df   = (const float*)d_in[12];
    const float* gw   = (const float*)d_in[13];
    float* out = (float*)d_out;

    float *kvp, *gate;
    float2* tab;
    __half *q16, *kt, *vt, *kvh, *kvl, *af, *bq16, *bk16, *bv16, *bo16;
    cudaGetSymbolAddress((void**)&q16,  g_q16);
    cudaGetSymbolAddress((void**)&kt,   g_kt);
    cudaGetSymbolAddress((void**)&vt,   g_vt);
    cudaGetSymbolAddress((void**)&kvp,  g_kv_part);
    cudaGetSymbolAddress((void**)&kvh,  g_kvt_h);
    cudaGetSymbolAddress((void**)&kvl,  g_kvt_l);
    cudaGetSymbolAddress((void**)&gate, g_gate);
    cudaGetSymbolAddress((void**)&tab,  g_rope);
    cudaGetSymbolAddress((void**)&af,   g_af);
    cudaGetSymbolAddress((void**)&bq16, g_bq16);
    cudaGetSymbolAddress((void**)&bk16, g_bk16);
    cudaGetSymbolAddress((void**)&bv16, g_bv16);
    cudaGetSymbolAddress((void**)&bo16, g_bo16);

    CUtensorMap mAf, mQ, mK, mV, mO;
    make_map(&mAf, af, Msz);
    make_map(&mQ,  bq16, Hsz);
    make_map(&mK,  bk16, Hsz);
    make_map(&mV,  bv16, Hsz);
    make_map(&mO,  bo16, Hsz);

    cudaFuncSetAttribute(gemm_qkv,
                         cudaFuncAttributeMaxDynamicSharedMemorySize, SMEM_GEMM);
    cudaFuncSetAttribute(gemm_out,
                         cudaFuncAttributeMaxDynamicSharedMemorySize, SMEM_GEMM);

    // 1. rope table
    rope_table_kernel<<<Ssz * 32 / 256, 256>>>(tab);
    // 2. activation -> single fp16 + gate
    cvt_x_gate<<<Msz, 256>>>((const float4*)x, (const float4*)Wg, bg,
                             (uint2*)af, gate);
    // 3. weight conversions
    cvt_w4<<<dim3(32, 32, 4), dim3(32, 8)>>>(Wq, Wk, Wv, Wo,
                                             bq16, bk16, bv16, bo16);
    // 4. fused QKV projection; q -> [s][1024], k/v -> transposed fp16
    gemm_qkv<<<dim3(8, 64, 3), 256, SMEM_GEMM>>>(
        mAf, mQ, mK, mV, bq, bk, bv, q16, kt, vt, mask, tab);
    // 5. kv outer-product GEMM (split-K partials)
    gemm_kv<<<dim3(4, 64), 256>>>(vt, kt, kvp);
    // 6. reduce partials + ksum -> kvt hi/lo
    kvt_finalize<<<64, 256>>>(kvp, kt, kvh, kvl);
    // 7. combine GEMM (num + den in one MMA) + gate epilogue -> af fp16
    gemm_cmb<<<dim3(16, 64), 256>>>(q16, kvh, kvl, gate, df, gw, af);
    // 8. output projection
    gemm_out<<<dim3(8, 64), 256, SMEM_GEMM>>>(mAf, mO, bo, out);
}